// round 1
// baseline (speedup 1.0000x reference)
#include <cuda_runtime.h>
#include <math.h>
#include <float.h>

// ---------------- problem constants ----------------
#define Dm   1024
#define Bb   4
#define Ss   2048
#define Rr   3
#define Kk   256
#define MAXR 256
#define Hh   8
#define HDm  128
#define BS   (Bb*Ss)     // 8192
#define RBn  (Rr*Bb)     // 12
#define NHID 512         // DIM/2

// ---------------- scratch (device globals; no allocation) ----------------
__device__ float g_qf1[Rr*Bb*Ss*Dm];            // 25165824
__device__ float g_qf2[Rr*Bb*Ss*Dm];
__device__ float g_scores[RBn*Ss*Ss];           // 50331648
__device__ float g_w[RBn*Ss];
__device__ float g_pooled[RBn*Dm];
__device__ float g_pooledln[RBn*Dm];
__device__ float g_queries[RBn*Dm];
__device__ float g_qpart[RBn*NHID];
__device__ float g_hidden[RBn*Kk*NHID];
__device__ float g_rel[RBn*Kk];
__device__ int   g_selidx[Bb*MAXR];
__device__ float g_keyvalid[Bb*MAXR];
__device__ int   g_anyvalid[Bb];
__device__ float g_seltok[Bb*MAXR*Dm];
__device__ float g_q[BS*Dm];
__device__ float g_k[Bb*MAXR*Dm];
__device__ float g_v[Bb*MAXR*Dm];
__device__ float g_fsc[Bb*Hh*Ss*MAXR];          // 16777216
__device__ float g_attnout[BS*Dm];
__device__ float g_fused[BS*Dm];

__device__ __forceinline__ float gelu_f(float x) {
    return 0.5f * x * (1.0f + erff(x * 0.70710678118654752440f));
}

// ---------------- generic tiled SGEMM ----------------
// C[m,n] = alpha * sum_k A[m,k] * B(k,n)  (+ bias)(+gelu)
// transB=0: B row-major [K,N] (ldb = row stride)
// transB=1: B row-major [N,K]; computes A * B^T
// 2-level batching: z -> (z1 = z/Z2, z2 = z%Z2); offsets = z1*s?1 + z2*s?2
__global__ void __launch_bounds__(256)
sgemm_kernel(const float* __restrict__ A, const float* __restrict__ B,
             float* __restrict__ C,
             int M, int N, int Kd, int lda, int ldb, int ldc,
             long sA1, long sB1, long sC1, int Z2, long sA2, long sB2, long sC2,
             float alpha, const float* __restrict__ bias, long sbias1,
             int bias_mdiv, int act, int transB)
{
    __shared__ float As[8][128];
    __shared__ float Bs[8][128];
    int z  = blockIdx.z;
    int z1 = z / Z2, z2 = z % Z2;
    A += z1 * sA1 + z2 * sA2;
    B += z1 * sB1 + z2 * sB2;
    C += z1 * sC1 + z2 * sC2;
    const float* bptr = bias ? bias + z1 * sbias1 : (const float*)0;

    int m0 = blockIdx.y * 128;
    int n0 = blockIdx.x * 128;
    int t  = threadIdx.x;
    int tx = t & 15, ty = t >> 4;

    int arow = t >> 1;          // 0..127
    int acol = (t & 1) * 4;     // 0 or 4
    int brow = t >> 5;          // 0..7
    int bcol = (t & 31) * 4;    // 0..124

    float acc[8][8];
#pragma unroll
    for (int i = 0; i < 8; i++)
#pragma unroll
        for (int j = 0; j < 8; j++) acc[i][j] = 0.0f;

    for (int k0 = 0; k0 < Kd; k0 += 8) {
        float4 av = *(const float4*)(A + (long)(m0 + arow) * lda + k0 + acol);
        As[acol + 0][arow] = av.x; As[acol + 1][arow] = av.y;
        As[acol + 2][arow] = av.z; As[acol + 3][arow] = av.w;
        if (!transB) {
            float4 bv = *(const float4*)(B + (long)(k0 + brow) * ldb + n0 + bcol);
            *(float4*)(&Bs[brow][bcol]) = bv;
        } else {
            float4 bv = *(const float4*)(B + (long)(n0 + arow) * ldb + k0 + acol);
            Bs[acol + 0][arow] = bv.x; Bs[acol + 1][arow] = bv.y;
            Bs[acol + 2][arow] = bv.z; Bs[acol + 3][arow] = bv.w;
        }
        __syncthreads();
#pragma unroll
        for (int kk = 0; kk < 8; kk++) {
            float4 a0 = *(const float4*)(&As[kk][ty * 8]);
            float4 a1 = *(const float4*)(&As[kk][ty * 8 + 4]);
            float4 b0 = *(const float4*)(&Bs[kk][tx * 8]);
            float4 b1 = *(const float4*)(&Bs[kk][tx * 8 + 4]);
            float af[8] = {a0.x, a0.y, a0.z, a0.w, a1.x, a1.y, a1.z, a1.w};
            float bf[8] = {b0.x, b0.y, b0.z, b0.w, b1.x, b1.y, b1.z, b1.w};
#pragma unroll
            for (int i = 0; i < 8; i++)
#pragma unroll
                for (int j = 0; j < 8; j++)
                    acc[i][j] = fmaf(af[i], bf[j], acc[i][j]);
        }
        __syncthreads();
    }

#pragma unroll
    for (int i = 0; i < 8; i++) {
        int m = m0 + ty * 8 + i;
#pragma unroll
        for (int j = 0; j < 8; j++) {
            int n = n0 + tx * 8 + j;
            float v = acc[i][j] * alpha;
            if (bptr) {
                long bi = (bias_mdiv ? (long)(m / bias_mdiv) * N : 0L) + n;
                v += bptr[bi];
            }
            if (act == 1) v = gelu_f(v);
            C[(long)m * ldc + n] = v;
        }
    }
}

static void launch_gemm(const float* A, const float* B, float* C,
                        int M, int N, int Kd, int lda, int ldb, int ldc,
                        long sA1, long sB1, long sC1, int Z, int Z2,
                        long sA2, long sB2, long sC2,
                        float alpha, const float* bias, long sbias1,
                        int bias_mdiv, int act, int transB)
{
    dim3 grid(N / 128, M / 128, Z);
    sgemm_kernel<<<grid, 256>>>(A, B, C, M, N, Kd, lda, ldb, ldc,
                                sA1, sB1, sC1, Z2, sA2, sB2, sC2,
                                alpha, bias, sbias1, bias_mdiv, act, transB);
}

// ---------------- reductions / elementwise kernels ----------------
__device__ __forceinline__ float blockReduceSum256(float v, float* red) {
    int t = threadIdx.x;
    red[t] = v; __syncthreads();
    for (int s = 128; s > 0; s >>= 1) { if (t < s) red[t] += red[t + s]; __syncthreads(); }
    float r = red[0]; __syncthreads();
    return r;
}
__device__ __forceinline__ float blockReduceMax256(float v, float* red) {
    int t = threadIdx.x;
    red[t] = v; __syncthreads();
    for (int s = 128; s > 0; s >>= 1) { if (t < s) red[t] = fmaxf(red[t], red[t + s]); __syncthreads(); }
    float r = red[0]; __syncthreads();
    return r;
}

// in-place softmax over rows of length 2048 (pooling attention)
__global__ void softmax2048_kernel(float* __restrict__ S)
{
    long row = blockIdx.x;
    float* p = S + row * 2048;
    __shared__ float red[256];
    int t = threadIdx.x;
    float lmax = -FLT_MAX;
    for (int i = t; i < 2048; i += 256) lmax = fmaxf(lmax, p[i]);
    float mx = blockReduceMax256(lmax, red);
    float lsum = 0.f;
    float e[8];
#pragma unroll
    for (int q = 0; q < 8; q++) { e[q] = expf(p[t + 256 * q] - mx); lsum += e[q]; }
    float sum = blockReduceSum256(lsum, red);
    float inv = 1.0f / sum;
#pragma unroll
    for (int q = 0; q < 8; q++) p[t + 256 * q] = e[q] * inv;
}

// w[rb,t] = (1/S) * sum_s p[rb,s,t]
__global__ void colmean_kernel(const float* __restrict__ S, float* __restrict__ w)
{
    int rb = blockIdx.y;
    int tcol = blockIdx.x * 256 + threadIdx.x;
    const float* base = S + (long)rb * Ss * Ss + tcol;
    float acc = 0.f;
    for (int s = 0; s < Ss; s++) acc += base[(long)s * Ss];
    w[rb * Ss + tcol] = acc * (1.0f / (float)Ss);
}

// pooled[rb,d] = sum_t w[rb,t] * qf2[rb,t,d]
__global__ void pooled_gemv_kernel(const float* __restrict__ qf2,
                                   const float* __restrict__ w,
                                   float* __restrict__ pooled)
{
    int rb = blockIdx.y;
    int d = blockIdx.x * 128 + threadIdx.x;
    const float* Q = qf2 + (long)rb * Ss * Dm + d;
    const float* wv = w + rb * Ss;
    float acc = 0.f;
    for (int tt = 0; tt < Ss; tt++) acc += wv[tt] * Q[(long)tt * Dm];
    pooled[rb * Dm + d] = acc;
}

// LayerNorm per rb row of pooled -> pooledln (with per-r gamma/beta)
__global__ void ln12_kernel(const float* __restrict__ pooled,
                            const float* __restrict__ gw, const float* __restrict__ bw,
                            float* __restrict__ out)
{
    int rb = blockIdx.x;
    int r = rb >> 2;
    int t = threadIdx.x;
    __shared__ float red[256];
    const float* p = pooled + rb * Dm;
    float v0 = p[t], v1 = p[t + 256], v2 = p[t + 512], v3 = p[t + 768];
    float mean = blockReduceSum256(v0 + v1 + v2 + v3, red) * (1.0f / (float)Dm);
    float d0 = v0 - mean, d1 = v1 - mean, d2 = v2 - mean, d3 = v3 - mean;
    float var = blockReduceSum256(d0 * d0 + d1 * d1 + d2 * d2 + d3 * d3, red) * (1.0f / (float)Dm);
    float rs = rsqrtf(var + 1e-5f);
    out[rb * Dm + t]       = d0 * rs * gw[r * Dm + t]       + bw[r * Dm + t];
    out[rb * Dm + t + 256] = d1 * rs * gw[r * Dm + t + 256] + bw[r * Dm + t + 256];
    out[rb * Dm + t + 512] = d2 * rs * gw[r * Dm + t + 512] + bw[r * Dm + t + 512];
    out[rb * Dm + t + 768] = d3 * rs * gw[r * Dm + t + 768] + bw[r * Dm + t + 768];
}

// queries[rb,e] = pooledln[rb,:] @ pool_w[r] + pool_b[r]
__global__ void queries_kernel(const float* __restrict__ pooledln,
                               const float* __restrict__ pool_w,
                               const float* __restrict__ pool_b,
                               float* __restrict__ queries)
{
    int rb = blockIdx.y;
    int r = rb >> 2;
    int e = blockIdx.x * 128 + threadIdx.x;
    __shared__ float sm[Dm];
    for (int i = threadIdx.x; i < Dm; i += 128) sm[i] = pooledln[rb * Dm + i];
    __syncthreads();
    const float* W = pool_w + (long)r * Dm * Dm;
    float acc = pool_b[r * Dm + e];
    for (int d = 0; d < Dm; d++) acc += sm[d] * W[(long)d * Dm + e];
    queries[rb * Dm + e] = acc;
}

// qpart[rb,j] = queries[rb,:] @ rel_w1[D: , j] + rel_b1[j]
__global__ void qpart_kernel(const float* __restrict__ queries,
                             const float* __restrict__ rel_w1,
                             const float* __restrict__ rel_b1,
                             float* __restrict__ qpart)
{
    int rb = blockIdx.y;
    int j = blockIdx.x * 128 + threadIdx.x;
    __shared__ float sm[Dm];
    for (int i = threadIdx.x; i < Dm; i += 128) sm[i] = queries[rb * Dm + i];
    __syncthreads();
    float acc = rel_b1[j];
    for (int d = 0; d < Dm; d++) acc += sm[d] * rel_w1[(long)(Dm + d) * NHID + j];
    qpart[rb * NHID + j] = acc;
}

// rel[i] = sigmoid(hidden[i,:] @ rel_w2 + rel_b2)
__global__ void relscore_kernel(const float* __restrict__ hidden,
                                const float* __restrict__ w2,
                                const float* __restrict__ b2,
                                float* __restrict__ rel)
{
    int row = blockIdx.x * 8 + threadIdx.y;
    const float* h = hidden + (long)row * NHID;
    float a = 0.f;
    for (int i = threadIdx.x; i < NHID; i += 32) a += h[i] * w2[i];
#pragma unroll
    for (int off = 16; off > 0; off >>= 1) a += __shfl_down_sync(0xffffffffu, a, off);
    if (threadIdx.x == 0) {
        float s = a + b2[0];
        rel[row] = 1.0f / (1.0f + expf(-s));
    }
}

// exact top-k: bitonic sort of 768 masked candidates (pad to 1024), desc by
// value, ties by ascending index (matches jax.lax.top_k)
__global__ void topk_kernel(const float* __restrict__ rel,
                            int* __restrict__ selidx, float* __restrict__ keyvalid,
                            int* __restrict__ anyvalid)
{
    int b = blockIdx.x;
    int t = threadIdx.x;
    __shared__ float v[1024];
    __shared__ int   id[1024];
    float val = -FLT_MAX;
    if (t < Rr * Kk) {
        int r = t >> 8, kk = t & 255;
        float rv = rel[(r * Bb + b) * Kk + kk];
        val = (rv >= 0.5f) ? rv : -FLT_MAX;
    }
    v[t] = val; id[t] = t;
    __syncthreads();
    for (int k = 2; k <= 1024; k <<= 1) {
        for (int j = k >> 1; j > 0; j >>= 1) {
            int ixj = t ^ j;
            if (ixj > t) {
                float va = v[t], vb2 = v[ixj];
                int ia = id[t], ib = id[ixj];
                bool aFirst = (va > vb2) || (va == vb2 && ia < ib);
                bool dirDesc = ((t & k) == 0);
                if (dirDesc ? !aFirst : aFirst) {
                    v[t] = vb2; v[ixj] = va; id[t] = ib; id[ixj] = ia;
                }
            }
            __syncthreads();
        }
    }
    if (t < MAXR) {
        bool valid = (v[t] > -FLT_MAX);
        selidx[b * MAXR + t] = id[t];
        keyvalid[b * MAXR + t] = valid ? 1.0f : 0.0f;
        if (t == 0) anyvalid[b] = valid ? 1 : 0;
    }
}

__global__ void gather_kernel(const float* __restrict__ retrieved,
                              const int* __restrict__ selidx,
                              float* __restrict__ seltok)
{
    int b = blockIdx.y;
    int j = blockIdx.x;
    int t = threadIdx.x;
    int c = selidx[b * MAXR + j];
    int r = c >> 8, kk = c & 255;
    const float4* src = (const float4*)(retrieved + (((long)r * Bb + b) * Kk + kk) * Dm);
    float4* dst = (float4*)(seltok + ((long)b * MAXR + j) * Dm);
    dst[t] = src[t];
}

// masked softmax over 256 keys (fusion attention); in-place on g_fsc
__global__ void fsoftmax_kernel(float* __restrict__ sc, const float* __restrict__ keyvalid)
{
    long row = blockIdx.x;                 // [B,H,S] row
    int b = (int)(row / (Hh * Ss));
    float* p = sc + row * MAXR;
    int t = threadIdx.x;                   // 256
    __shared__ float red[256];
    float val = p[t];
    if (keyvalid[b * MAXR + t] == 0.0f) val = -1e9f;
    float mx = blockReduceMax256(val, red);
    float e = expf(val - mx);
    float sum = blockReduceSum256(e, red);
    p[t] = e / sum;
}

// out = any_valid[b] ? LN(x + fused) * g + b : x
__global__ void finalize_kernel(const float* __restrict__ x, const float* __restrict__ fused,
                                const float* __restrict__ gw, const float* __restrict__ bw,
                                const int* __restrict__ anyvalid, float* __restrict__ out)
{
    long row = blockIdx.x;                 // [B*S]
    int b = (int)(row >> 11);
    int t = threadIdx.x;
    __shared__ float red[256];
    const float* xr = x + row * Dm;
    const float* fr = fused + row * Dm;
    float v0 = xr[t] + fr[t];
    float v1 = xr[t + 256] + fr[t + 256];
    float v2 = xr[t + 512] + fr[t + 512];
    float v3 = xr[t + 768] + fr[t + 768];
    float mean = blockReduceSum256(v0 + v1 + v2 + v3, red) * (1.0f / (float)Dm);
    float d0 = v0 - mean, d1 = v1 - mean, d2 = v2 - mean, d3 = v3 - mean;
    float var = blockReduceSum256(d0 * d0 + d1 * d1 + d2 * d2 + d3 * d3, red) * (1.0f / (float)Dm);
    float rs = rsqrtf(var + 1e-5f);
    int av = anyvalid[b];
    float* o = out + row * Dm;
    o[t]       = av ? (d0 * rs * gw[t]       + bw[t])       : xr[t];
    o[t + 256] = av ? (d1 * rs * gw[t + 256] + bw[t + 256]) : xr[t + 256];
    o[t + 512] = av ? (d2 * rs * gw[t + 512] + bw[t + 512]) : xr[t + 512];
    o[t + 768] = av ? (d3 * rs * gw[t + 768] + bw[t + 768]) : xr[t + 768];
}

// ---------------- host orchestration ----------------
template <typename T>
static float* sym(T& s) { void* p = 0; cudaGetSymbolAddress(&p, s); return (float*)p; }
template <typename T>
static int* symi(T& s) { void* p = 0; cudaGetSymbolAddress(&p, s); return (int*)p; }

extern "C" void kernel_launch(void* const* d_in, const int* in_sizes, int n_in,
                              void* d_out, int out_size)
{
    const float* x       = (const float*)d_in[0];
    const float* retr    = (const float*)d_in[1];
    const float* qg_w1   = (const float*)d_in[2];
    const float* qg_b1   = (const float*)d_in[3];
    const float* qg_w2   = (const float*)d_in[4];
    const float* qg_b2   = (const float*)d_in[5];
    const float* pln_g   = (const float*)d_in[6];
    const float* pln_b   = (const float*)d_in[7];
    const float* pool_w  = (const float*)d_in[8];
    const float* pool_b  = (const float*)d_in[9];
    const float* rel_w1  = (const float*)d_in[10];
    const float* rel_b1  = (const float*)d_in[11];
    const float* rel_w2  = (const float*)d_in[12];
    const float* rel_b2  = (const float*)d_in[13];
    const float* in_w    = (const float*)d_in[14];
    const float* in_b    = (const float*)d_in[15];
    const float* out_w   = (const float*)d_in[16];
    const float* out_b   = (const float*)d_in[17];
    const float* fln_g   = (const float*)d_in[18];
    const float* fln_b   = (const float*)d_in[19];
    float* out = (float*)d_out;

    float* qf1    = sym(g_qf1);
    float* qf2    = sym(g_qf2);
    float* scores = sym(g_scores);
    float* wmean  = sym(g_w);
    float* pooled = sym(g_pooled);
    float* pooledln = sym(g_pooledln);
    float* queries = sym(g_queries);
    float* qpart  = sym(g_qpart);
    float* hidden = sym(g_hidden);
    float* rel    = sym(g_rel);
    int*   selidx = symi(g_selidx);
    float* keyvalid = sym(g_keyvalid);
    int*   anyvalid = symi(g_anyvalid);
    float* seltok = sym(g_seltok);
    float* qb     = sym(g_q);
    float* kb     = sym(g_k);
    float* vb     = sym(g_v);
    float* fsc    = sym(g_fsc);
    float* attnout = sym(g_attnout);
    float* fused  = sym(g_fused);

    const long DD = (long)Dm * Dm;

    // qf1 = gelu(x @ qg_w1[r] + qg_b1[r])   [R batches]
    launch_gemm(x, qg_w1, qf1, BS, Dm, Dm, Dm, Dm, Dm,
                0, DD, (long)BS * Dm, Rr, 1, 0, 0, 0,
                1.0f, qg_b1, Dm, 0, 1, 0);
    // qf2 = qf1 @ qg_w2[r] + qg_b2[r]
    launch_gemm(qf1, qg_w2, qf2, BS, Dm, Dm, Dm, Dm, Dm,
                (long)BS * Dm, DD, (long)BS * Dm, Rr, 1, 0, 0, 0,
                1.0f, qg_b2, Dm, 0, 0, 0);
    // scores = qf2 @ qf2^T / sqrt(D)   [12 batches]
    launch_gemm(qf2, qf2, scores, Ss, Ss, Dm, Dm, Dm, Ss,
                (long)Ss * Dm, (long)Ss * Dm, (long)Ss * Ss, RBn, 1, 0, 0, 0,
                0.03125f, 0, 0, 0, 0, 1);
    softmax2048_kernel<<<RBn * Ss, 256>>>(scores);
    { dim3 g(Ss / 256, RBn); colmean_kernel<<<g, 256>>>(scores, wmean); }
    { dim3 g(Dm / 128, RBn); pooled_gemv_kernel<<<g, 128>>>(qf2, wmean, pooled); }
    ln12_kernel<<<RBn, 256>>>(pooled, pln_g, pln_b, pooledln);
    { dim3 g(Dm / 128, RBn); queries_kernel<<<g, 128>>>(pooledln, pool_w, pool_b, queries); }
    { dim3 g(NHID / 128, RBn); qpart_kernel<<<g, 128>>>(queries, rel_w1, rel_b1, qpart); }
    // hidden = gelu(retrieved @ rel_w1[:D] + qpart[rb])  (qpart already has rel_b1)
    launch_gemm(retr, rel_w1, hidden, RBn * Kk, NHID, Dm, Dm, NHID, NHID,
                0, 0, 0, 1, 1, 0, 0, 0,
                1.0f, qpart, 0, Kk, 1, 0);
    { dim3 blk(32, 8); relscore_kernel<<<RBn * Kk / 8, blk>>>(hidden, rel_w2, rel_b2, rel); }
    topk_kernel<<<Bb, 1024>>>(rel, selidx, keyvalid, anyvalid);
    { dim3 g(MAXR, Bb); gather_kernel<<<g, 256>>>(retr, selidx, seltok); }
    // q/k/v projections
    launch_gemm(x, in_w, qb, BS, Dm, Dm, Dm, Dm, Dm,
                0, 0, 0, 1, 1, 0, 0, 0, 1.0f, in_b, 0, 0, 0, 0);
    launch_gemm(seltok, in_w + DD, kb, Bb * MAXR, Dm, Dm, Dm, Dm, Dm,
                0, 0, 0, 1, 1, 0, 0, 0, 1.0f, in_b + Dm, 0, 0, 0, 0);
    launch_gemm(seltok, in_w + 2 * DD, vb, Bb * MAXR, Dm, Dm, Dm, Dm, Dm,
                0, 0, 0, 1, 1, 0, 0, 0, 1.0f, in_b + 2 * Dm, 0, 0, 0, 0);
    // fusion scores: per (b,h)  q[b,:,h,:] @ k[b,:,h,:]^T / sqrt(HD)
    launch_gemm(qb, kb, fsc, Ss, MAXR, HDm, Dm, Dm, MAXR,
                (long)Ss * Dm, (long)MAXR * Dm, (long)Hh * Ss * MAXR,
                Bb * Hh, Hh, HDm, HDm, (long)Ss * MAXR,
                0.08838834764831845f, 0, 0, 0, 0, 1);
    fsoftmax_kernel<<<Bb * Hh * Ss, 256>>>(fsc, keyvalid);
    // attnout: per (b,h)  P @ v[b,:,h,:]
    launch_gemm(fsc, vb, attnout, Ss, HDm, MAXR, MAXR, Dm, Dm,
                (long)Hh * Ss * MAXR, (long)MAXR * Dm, (long)Ss * Dm,
                Bb * Hh, Hh, (long)Ss * MAXR, HDm, HDm,
                1.0f, 0, 0, 0, 0, 0);
    // out projection
    launch_gemm(attnout, out_w, fused, BS, Dm, Dm, Dm, Dm, Dm,
                0, 0, 0, 1, 1, 0, 0, 0, 1.0f, out_b, 0, 0, 0, 0);
    finalize_kernel<<<BS, 256>>>(x, fused, fln_g, fln_b, anyvalid, out);
}

// round 6
// speedup vs baseline: 1.4281x; 1.4281x over previous
#include <cuda_runtime.h>
#include <math.h>
#include <float.h>

// ---------------- problem constants ----------------
#define Dm   1024
#define Bb   4
#define Ss   2048
#define Rr   3
#define Kk   256
#define MAXR 256
#define Hh   8
#define HDm  128
#define BS   (Bb*Ss)     // 8192
#define RBn  (Rr*Bb)     // 12
#define NHID 512         // DIM/2

// ---------------- scratch (device globals; no allocation) ----------------
__device__ float g_qf1[Rr*Bb*Ss*Dm];
__device__ float g_qf2[Rr*Bb*Ss*Dm];
__device__ float g_scores[RBn*Ss*Ss];
__device__ float g_w[RBn*Ss];
__device__ float g_pooled[RBn*Dm];
__device__ float g_pooledln[RBn*Dm];
__device__ float g_queries[RBn*Dm];
__device__ float g_qpart[RBn*NHID];
__device__ float g_hidden[RBn*Kk*NHID];
__device__ float g_rel[RBn*Kk];
__device__ int   g_selidx[Bb*MAXR];
__device__ float g_keyvalid[Bb*MAXR];
__device__ int   g_anyvalid[Bb];
__device__ float g_seltok[Bb*MAXR*Dm];
__device__ float g_q[BS*Dm];
__device__ float g_k[Bb*MAXR*Dm];
__device__ float g_v[Bb*MAXR*Dm];
__device__ float g_fsc[Bb*Hh*Ss*MAXR];
__device__ float g_attnout[BS*Dm];
__device__ float g_fused[BS*Dm];

__device__ __forceinline__ float gelu_f(float x) {
    return 0.5f * x * (1.0f + erff(x * 0.70710678118654752440f));
}

__device__ __forceinline__ unsigned f2tf(float x) {
    unsigned r;
    asm("cvt.rna.tf32.f32 %0, %1;" : "=r"(r) : "f"(x));
    return r;
}

__device__ __forceinline__ void mma_tf32(float* c,
    unsigned a0, unsigned a1, unsigned a2, unsigned a3,
    unsigned b0, unsigned b1)
{
    asm volatile(
        "mma.sync.aligned.m16n8k8.row.col.f32.tf32.tf32.f32 "
        "{%0,%1,%2,%3},{%4,%5,%6,%7},{%8,%9},{%0,%1,%2,%3};\n"
        : "+f"(c[0]), "+f"(c[1]), "+f"(c[2]), "+f"(c[3])
        : "r"(a0), "r"(a1), "r"(a2), "r"(a3), "r"(b0), "r"(b1));
}

// ---------------- tf32x3 tensor-core GEMM ----------------
// C[m,n] = alpha * sum_k A[m,k] * B(k,n)  (+ bias)(+gelu)
// TRANSB=0: B row-major [K,N]; TRANSB=1: B row-major [N,K] -> A*B^T
// 2-level batching as before.
template<int TRANSB>
__global__ void __launch_bounds__(256, 1)
tgemm_kernel(const float* __restrict__ A, const float* __restrict__ B,
             float* __restrict__ C,
             int M, int N, int Kd, int lda, int ldb, int ldc,
             long sA1, long sB1, long sC1, int Z2, long sA2, long sB2, long sC2,
             float alpha, const float* __restrict__ bias, long sbias1,
             int bias_mdiv, int act)
{
    __shared__ float Asm[32][132];
    __shared__ float Bsm[32][132];

    int z  = blockIdx.z;
    int z1 = z / Z2, z2 = z - z1 * Z2;
    A += z1 * sA1 + z2 * sA2;
    B += z1 * sB1 + z2 * sB2;
    C += z1 * sC1 + z2 * sC2;
    const float* bptr = bias ? bias + z1 * sbias1 : (const float*)0;

    int m0 = blockIdx.y * 128;
    int n0 = blockIdx.x * 128;
    int t = threadIdx.x, lane = t & 31, warp = t >> 5;
    int wm = (warp >> 2) * 64, wn = (warp & 3) * 32;
    int r0 = lane >> 2, c4 = lane & 3;

    float acc[4][4][4];
#pragma unroll
    for (int i = 0; i < 4; i++)
#pragma unroll
        for (int j = 0; j < 4; j++)
#pragma unroll
            for (int q = 0; q < 4; q++) acc[i][j][q] = 0.0f;

    int arow = t >> 3;         // 0..31
    int acol = (t & 7) * 4;    // 0..28
    int brow = t >> 5;         // 0..7
    int bcol = (t & 31) * 4;   // 0..124

    float4 pa[4], pb[4];
    const int KT = Kd >> 5;

    // prologue: load tile 0
    {
        const float* Aptr = A + (long)m0 * lda;
#pragma unroll
        for (int p = 0; p < 4; p++)
            pa[p] = *(const float4*)(Aptr + (long)(arow + p * 32) * lda + acol);
        if (TRANSB == 0) {
            const float* Bptr = B + n0;
#pragma unroll
            for (int p = 0; p < 4; p++)
                pb[p] = *(const float4*)(Bptr + (long)(brow + p * 8) * ldb + bcol);
        } else {
            const float* Bptr = B + (long)n0 * ldb;
#pragma unroll
            for (int p = 0; p < 4; p++)
                pb[p] = *(const float4*)(Bptr + (long)(arow + p * 32) * ldb + acol);
        }
    }

    for (int kt = 0; kt < KT; kt++) {
        // stage registers -> smem
#pragma unroll
        for (int p = 0; p < 4; p++) {
            Asm[acol + 0][arow + p * 32] = pa[p].x;
            Asm[acol + 1][arow + p * 32] = pa[p].y;
            Asm[acol + 2][arow + p * 32] = pa[p].z;
            Asm[acol + 3][arow + p * 32] = pa[p].w;
        }
        if (TRANSB == 0) {
#pragma unroll
            for (int p = 0; p < 4; p++)
                *(float4*)&Bsm[brow + p * 8][bcol] = pb[p];
        } else {
#pragma unroll
            for (int p = 0; p < 4; p++) {
                Bsm[acol + 0][arow + p * 32] = pb[p].x;
                Bsm[acol + 1][arow + p * 32] = pb[p].y;
                Bsm[acol + 2][arow + p * 32] = pb[p].z;
                Bsm[acol + 3][arow + p * 32] = pb[p].w;
            }
        }
        __syncthreads();

        // prefetch next tile into registers (overlaps with MMA below)
        if (kt + 1 < KT) {
            int k0 = (kt + 1) * 32;
            const float* Aptr = A + (long)m0 * lda + k0;
#pragma unroll
            for (int p = 0; p < 4; p++)
                pa[p] = *(const float4*)(Aptr + (long)(arow + p * 32) * lda + acol);
            if (TRANSB == 0) {
                const float* Bptr = B + (long)k0 * ldb + n0;
#pragma unroll
                for (int p = 0; p < 4; p++)
                    pb[p] = *(const float4*)(Bptr + (long)(brow + p * 8) * ldb + bcol);
            } else {
                const float* Bptr = B + (long)n0 * ldb + k0;
#pragma unroll
                for (int p = 0; p < 4; p++)
                    pb[p] = *(const float4*)(Bptr + (long)(arow + p * 32) * ldb + acol);
            }
        }

        // compute: 4 k8-substeps, tf32x3 split
#pragma unroll
        for (int ks = 0; ks < 4; ks++) {
            int k8 = ks * 8;
            unsigned ah[4][4], al[4][4];
#pragma unroll
            for (int mt = 0; mt < 4; mt++) {
                int row = wm + mt * 16 + r0;
                float f0 = Asm[k8 + c4][row];
                float f1 = Asm[k8 + c4][row + 8];
                float f2 = Asm[k8 + c4 + 4][row];
                float f3 = Asm[k8 + c4 + 4][row + 8];
                ah[mt][0] = f2tf(f0); al[mt][0] = f2tf(f0 - __uint_as_float(ah[mt][0]));
                ah[mt][1] = f2tf(f1); al[mt][1] = f2tf(f1 - __uint_as_float(ah[mt][1]));
                ah[mt][2] = f2tf(f2); al[mt][2] = f2tf(f2 - __uint_as_float(ah[mt][2]));
                ah[mt][3] = f2tf(f3); al[mt][3] = f2tf(f3 - __uint_as_float(ah[mt][3]));
            }
            unsigned bh[4][2], bl[4][2];
#pragma unroll
            for (int nt = 0; nt < 4; nt++) {
                int col = wn + nt * 8 + r0;
                float g0 = Bsm[k8 + c4][col];
                float g1 = Bsm[k8 + c4 + 4][col];
                bh[nt][0] = f2tf(g0); bl[nt][0] = f2tf(g0 - __uint_as_float(bh[nt][0]));
                bh[nt][1] = f2tf(g1); bl[nt][1] = f2tf(g1 - __uint_as_float(bh[nt][1]));
            }
#pragma unroll
            for (int mt = 0; mt < 4; mt++)
#pragma unroll
                for (int nt = 0; nt < 4; nt++) {
                    float* c = acc[mt][nt];
                    mma_tf32(c, al[mt][0], al[mt][1], al[mt][2], al[mt][3], bh[nt][0], bh[nt][1]);
                    mma_tf32(c, ah[mt][0], ah[mt][1], ah[mt][2], ah[mt][3], bl[nt][0], bl[nt][1]);
                    mma_tf32(c, ah[mt][0], ah[mt][1], ah[mt][2], ah[mt][3], bh[nt][0], bh[nt][1]);
                }
        }
        __syncthreads();
    }

    // epilogue
#pragma unroll
    for (int mt = 0; mt < 4; mt++) {
#pragma unroll
        for (int nt = 0; nt < 4; nt++) {
            int row = m0 + wm + mt * 16 + r0;
            int col = n0 + wn + nt * 8 + c4 * 2;
            float v0 = acc[mt][nt][0] * alpha;
            float v1 = acc[mt][nt][1] * alpha;
            float v2 = acc[mt][nt][2] * alpha;
            float v3 = acc[mt][nt][3] * alpha;
            if (bptr) {
                long bi0 = (bias_mdiv ? (long)(row / bias_mdiv) * N : 0L);
                long bi2 = (bias_mdiv ? (long)((row + 8) / bias_mdiv) * N : 0L);
                v0 += bptr[bi0 + col];     v1 += bptr[bi0 + col + 1];
                v2 += bptr[bi2 + col];     v3 += bptr[bi2 + col + 1];
            }
            if (act == 1) { v0 = gelu_f(v0); v1 = gelu_f(v1); v2 = gelu_f(v2); v3 = gelu_f(v3); }
            float2 w01 = make_float2(v0, v1);
            float2 w23 = make_float2(v2, v3);
            *(float2*)(C + (long)row * ldc + col) = w01;
            *(float2*)(C + (long)(row + 8) * ldc + col) = w23;
        }
    }
}

static void launch_tgemm(const float* A, const float* B, float* C,
                         int M, int N, int Kd, int lda, int ldb, int ldc,
                         long sA1, long sB1, long sC1, int Z, int Z2,
                         long sA2, long sB2, long sC2,
                         float alpha, const float* bias, long sbias1,
                         int bias_mdiv, int act, int transB)
{
    dim3 grid(N / 128, M / 128, Z);
    if (transB)
        tgemm_kernel<1><<<grid, 256>>>(A, B, C, M, N, Kd, lda, ldb, ldc,
                                       sA1, sB1, sC1, Z2, sA2, sB2, sC2,
                                       alpha, bias, sbias1, bias_mdiv, act);
    else
        tgemm_kernel<0><<<grid, 256>>>(A, B, C, M, N, Kd, lda, ldb, ldc,
                                       sA1, sB1, sC1, Z2, sA2, sB2, sC2,
                                       alpha, bias, sbias1, bias_mdiv, act);
}

// ---------------- reductions / elementwise kernels ----------------
__device__ __forceinline__ float blockReduceSum256(float v, float* red) {
    int t = threadIdx.x;
    red[t] = v; __syncthreads();
    for (int s = 128; s > 0; s >>= 1) { if (t < s) red[t] += red[t + s]; __syncthreads(); }
    float r = red[0]; __syncthreads();
    return r;
}
__device__ __forceinline__ float blockReduceMax256(float v, float* red) {
    int t = threadIdx.x;
    red[t] = v; __syncthreads();
    for (int s = 128; s > 0; s >>= 1) { if (t < s) red[t] = fmaxf(red[t], red[t + s]); __syncthreads(); }
    float r = red[0]; __syncthreads();
    return r;
}

__global__ void softmax2048_kernel(float* __restrict__ S)
{
    long row = blockIdx.x;
    float* p = S + row * 2048;
    __shared__ float red[256];
    int t = threadIdx.x;
    float lmax = -FLT_MAX;
    for (int i = t; i < 2048; i += 256) lmax = fmaxf(lmax, p[i]);
    float mx = blockReduceMax256(lmax, red);
    float lsum = 0.f;
    float e[8];
#pragma unroll
    for (int q = 0; q < 8; q++) { e[q] = expf(p[t + 256 * q] - mx); lsum += e[q]; }
    float sum = blockReduceSum256(lsum, red);
    float inv = 1.0f / sum;
#pragma unroll
    for (int q = 0; q < 8; q++) p[t + 256 * q] = e[q] * inv;
}

__global__ void colmean_kernel(const float* __restrict__ S, float* __restrict__ w)
{
    int rb = blockIdx.y;
    int tcol = blockIdx.x * 256 + threadIdx.x;
    const float* base = S + (long)rb * Ss * Ss + tcol;
    float acc = 0.f;
    for (int s = 0; s < Ss; s++) acc += base[(long)s * Ss];
    w[rb * Ss + tcol] = acc * (1.0f / (float)Ss);
}

__global__ void pooled_gemv_kernel(const float* __restrict__ qf2,
                                   const float* __restrict__ w,
                                   float* __restrict__ pooled)
{
    int rb = blockIdx.y;
    int d = blockIdx.x * 128 + threadIdx.x;
    const float* Q = qf2 + (long)rb * Ss * Dm + d;
    const float* wv = w + rb * Ss;
    float acc = 0.f;
    for (int tt = 0; tt < Ss; tt++) acc += wv[tt] * Q[(long)tt * Dm];
    pooled[rb * Dm + d] = acc;
}

__global__ void ln12_kernel(const float* __restrict__ pooled,
                            const float* __restrict__ gw, const float* __restrict__ bw,
                            float* __restrict__ out)
{
    int rb = blockIdx.x;
    int r = rb >> 2;
    int t = threadIdx.x;
    __shared__ float red[256];
    const float* p = pooled + rb * Dm;
    float v0 = p[t], v1 = p[t + 256], v2 = p[t + 512], v3 = p[t + 768];
    float mean = blockReduceSum256(v0 + v1 + v2 + v3, red) * (1.0f / (float)Dm);
    float d0 = v0 - mean, d1 = v1 - mean, d2 = v2 - mean, d3 = v3 - mean;
    float var = blockReduceSum256(d0 * d0 + d1 * d1 + d2 * d2 + d3 * d3, red) * (1.0f / (float)Dm);
    float rs = rsqrtf(var + 1e-5f);
    out[rb * Dm + t]       = d0 * rs * gw[r * Dm + t]       + bw[r * Dm + t];
    out[rb * Dm + t + 256] = d1 * rs * gw[r * Dm + t + 256] + bw[r * Dm + t + 256];
    out[rb * Dm + t + 512] = d2 * rs * gw[r * Dm + t + 512] + bw[r * Dm + t + 512];
    out[rb * Dm + t + 768] = d3 * rs * gw[r * Dm + t + 768] + bw[r * Dm + t + 768];
}

__global__ void queries_kernel(const float* __restrict__ pooledln,
                               const float* __restrict__ pool_w,
                               const float* __restrict__ pool_b,
                               float* __restrict__ queries)
{
    int rb = blockIdx.y;
    int r = rb >> 2;
    int e = blockIdx.x * 128 + threadIdx.x;
    __shared__ float sm[Dm];
    for (int i = threadIdx.x; i < Dm; i += 128) sm[i] = pooledln[rb * Dm + i];
    __syncthreads();
    const float* W = pool_w + (long)r * Dm * Dm;
    float acc = pool_b[r * Dm + e];
    for (int d = 0; d < Dm; d++) acc += sm[d] * W[(long)d * Dm + e];
    queries[rb * Dm + e] = acc;
}

__global__ void qpart_kernel(const float* __restrict__ queries,
                             const float* __restrict__ rel_w1,
                             const float* __restrict__ rel_b1,
                             float* __restrict__ qpart)
{
    int rb = blockIdx.y;
    int j = blockIdx.x * 128 + threadIdx.x;
    __shared__ float sm[Dm];
    for (int i = threadIdx.x; i < Dm; i += 128) sm[i] = queries[rb * Dm + i];
    __syncthreads();
    float acc = rel_b1[j];
    for (int d = 0; d < Dm; d++) acc += sm[d] * rel_w1[(long)(Dm + d) * NHID + j];
    qpart[rb * NHID + j] = acc;
}

__global__ void relscore_kernel(const float* __restrict__ hidden,
                                const float* __restrict__ w2,
                                const float* __restrict__ b2,
                                float* __restrict__ rel)
{
    int row = blockIdx.x * 8 + threadIdx.y;
    const float* h = hidden + (long)row * NHID;
    float a = 0.f;
    for (int i = threadIdx.x; i < NHID; i += 32) a += h[i] * w2[i];
#pragma unroll
    for (int off = 16; off > 0; off >>= 1) a += __shfl_down_sync(0xffffffffu, a, off);
    if (threadIdx.x == 0) {
        float s = a + b2[0];
        rel[row] = 1.0f / (1.0f + expf(-s));
    }
}

__global__ void topk_kernel(const float* __restrict__ rel,
                            int* __restrict__ selidx, float* __restrict__ keyvalid,
                            int* __restrict__ anyvalid)
{
    int b = blockIdx.x;
    int t = threadIdx.x;
    __shared__ float v[1024];
    __shared__ int   id[1024];
    float val = -FLT_MAX;
    if (t < Rr * Kk) {
        int r = t >> 8, kk = t & 255;
        float rv = rel[(r * Bb + b) * Kk + kk];
        val = (rv >= 0.5f) ? rv : -FLT_MAX;
    }
    v[t] = val; id[t] = t;
    __syncthreads();
    for (int k = 2; k <= 1024; k <<= 1) {
        for (int j = k >> 1; j > 0; j >>= 1) {
            int ixj = t ^ j;
            if (ixj > t) {
                float va = v[t], vb2 = v[ixj];
                int ia = id[t], ib = id[ixj];
                bool aFirst = (va > vb2) || (va == vb2 && ia < ib);
                bool dirDesc = ((t & k) == 0);
                if (dirDesc ? !aFirst : aFirst) {
                    v[t] = vb2; v[ixj] = va; id[t] = ib; id[ixj] = ia;
                }
            }
            __syncthreads();
        }
    }
    if (t < MAXR) {
        bool valid = (v[t] > -FLT_MAX);
        selidx[b * MAXR + t] = id[t];
        keyvalid[b * MAXR + t] = valid ? 1.0f : 0.0f;
        if (t == 0) anyvalid[b] = valid ? 1 : 0;
    }
}

__global__ void gather_kernel(const float* __restrict__ retrieved,
                              const int* __restrict__ selidx,
                              float* __restrict__ seltok)
{
    int b = blockIdx.y;
    int j = blockIdx.x;
    int t = threadIdx.x;
    int c = selidx[b * MAXR + j];
    int r = c >> 8, kk = c & 255;
    const float4* src = (const float4*)(retrieved + (((long)r * Bb + b) * Kk + kk) * Dm);
    float4* dst = (float4*)(seltok + ((long)b * MAXR + j) * Dm);
    dst[t] = src[t];
}

__global__ void fsoftmax_kernel(float* __restrict__ sc, const float* __restrict__ keyvalid)
{
    long row = blockIdx.x;
    int b = (int)(row / (Hh * Ss));
    float* p = sc + row * MAXR;
    int t = threadIdx.x;
    __shared__ float red[256];
    float val = p[t];
    if (keyvalid[b * MAXR + t] == 0.0f) val = -1e9f;
    float mx = blockReduceMax256(val, red);
    float e = expf(val - mx);
    float sum = blockReduceSum256(e, red);
    p[t] = e / sum;
}

__global__ void finalize_kernel(const float* __restrict__ x, const float* __restrict__ fused,
                                const float* __restrict__ gw, const float* __restrict__ bw,
                                const int* __restrict__ anyvalid, float* __restrict__ out)
{
    long row = blockIdx.x;
    int b = (int)(row >> 11);
    int t = threadIdx.x;
    __shared__ float red[256];
    const float* xr = x + row * Dm;
    const float* fr = fused + row * Dm;
    float v0 = xr[t] + fr[t];
    float v1 = xr[t + 256] + fr[t + 256];
    float v2 = xr[t + 512] + fr[t + 512];
    float v3 = xr[t + 768] + fr[t + 768];
    float mean = blockReduceSum256(v0 + v1 + v2 + v3, red) * (1.0f / (float)Dm);
    float d0 = v0 - mean, d1 = v1 - mean, d2 = v2 - mean, d3 = v3 - mean;
    float var = blockReduceSum256(d0 * d0 + d1 * d1 + d2 * d2 + d3 * d3, red) * (1.0f / (float)Dm);
    float rs = rsqrtf(var + 1e-5f);
    int av = anyvalid[b];
    float* o = out + row * Dm;
    o[t]       = av ? (d0 * rs * gw[t]       + bw[t])       : xr[t];
    o[t + 256] = av ? (d1 * rs * gw[t + 256] + bw[t + 256]) : xr[t + 256];
    o[t + 512] = av ? (d2 * rs * gw[t + 512] + bw[t + 512]) : xr[t + 512];
    o[t + 768] = av ? (d3 * rs * gw[t + 768] + bw[t + 768]) : xr[t + 768];
}

// ---------------- host orchestration ----------------
template <typename T>
static float* sym(T& s) { void* p = 0; cudaGetSymbolAddress(&p, s); return (float*)p; }
template <typename T>
static int* symi(T& s) { void* p = 0; cudaGetSymbolAddress(&p, s); return (int*)p; }

extern "C" void kernel_launch(void* const* d_in, const int* in_sizes, int n_in,
                              void* d_out, int out_size)
{
    const float* x       = (const float*)d_in[0];
    const float* retr    = (const float*)d_in[1];
    const float* qg_w1   = (const float*)d_in[2];
    const float* qg_b1   = (const float*)d_in[3];
    const float* qg_w2   = (const float*)d_in[4];
    const float* qg_b2   = (const float*)d_in[5];
    const float* pln_g   = (const float*)d_in[6];
    const float* pln_b   = (const float*)d_in[7];
    const float* pool_w  = (const float*)d_in[8];
    const float* pool_b  = (const float*)d_in[9];
    const float* rel_w1  = (const float*)d_in[10];
    const float* rel_b1  = (const float*)d_in[11];
    const float* rel_w2  = (const float*)d_in[12];
    const float* rel_b2  = (const float*)d_in[13];
    const float* in_w    = (const float*)d_in[14];
    const float* in_b    = (const float*)d_in[15];
    const float* out_w   = (const float*)d_in[16];
    const float* out_b   = (const float*)d_in[17];
    const float* fln_g   = (const float*)d_in[18];
    const float* fln_b   = (const float*)d_in[19];
    float* out = (float*)d_out;

    float* qf1    = sym(g_qf1);
    float* qf2    = sym(g_qf2);
    float* scores = sym(g_scores);
    float* wmean  = sym(g_w);
    float* pooled = sym(g_pooled);
    float* pooledln = sym(g_pooledln);
    float* queries = sym(g_queries);
    float* qpart  = sym(g_qpart);
    float* hidden = sym(g_hidden);
    float* rel    = sym(g_rel);
    int*   selidx = symi(g_selidx);
    float* keyvalid = sym(g_keyvalid);
    int*   anyvalid = symi(g_anyvalid);
    float* seltok = sym(g_seltok);
    float* qb     = sym(g_q);
    float* kb     = sym(g_k);
    float* vb     = sym(g_v);
    float* fsc    = sym(g_fsc);
    float* attnout = sym(g_attnout);
    float* fused  = sym(g_fused);

    const long DD = (long)Dm * Dm;

    // qf1 = gelu(x @ qg_w1[r] + qg_b1[r])
    launch_tgemm(x, qg_w1, qf1, BS, Dm, Dm, Dm, Dm, Dm,
                 0, DD, (long)BS * Dm, Rr, 1, 0, 0, 0,
                 1.0f, qg_b1, Dm, 0, 1, 0);
    // qf2 = qf1 @ qg_w2[r] + qg_b2[r]
    launch_tgemm(qf1, qg_w2, qf2, BS, Dm, Dm, Dm, Dm, Dm,
                 (long)BS * Dm, DD, (long)BS * Dm, Rr, 1, 0, 0, 0,
                 1.0f, qg_b2, Dm, 0, 0, 0);
    // scores = qf2 @ qf2^T / 32
    launch_tgemm(qf2, qf2, scores, Ss, Ss, Dm, Dm, Dm, Ss,
                 (long)Ss * Dm, (long)Ss * Dm, (long)Ss * Ss, RBn, 1, 0, 0, 0,
                 0.03125f, 0, 0, 0, 0, 1);
    softmax2048_kernel<<<RBn * Ss, 256>>>(scores);
    { dim3 g(Ss / 256, RBn); colmean_kernel<<<g, 256>>>(scores, wmean); }
    { dim3 g(Dm / 128, RBn); pooled_gemv_kernel<<<g, 128>>>(qf2, wmean, pooled); }
    ln12_kernel<<<RBn, 256>>>(pooled, pln_g, pln_b, pooledln);
    { dim3 g(Dm / 128, RBn); queries_kernel<<<g, 128>>>(pooledln, pool_w, pool_b, queries); }
    { dim3 g(NHID / 128, RBn); qpart_kernel<<<g, 128>>>(queries, rel_w1, rel_b1, qpart); }
    // hidden = gelu(retrieved @ rel_w1[:D] + qpart[rb])
    launch_tgemm(retr, rel_w1, hidden, RBn * Kk, NHID, Dm, Dm, NHID, NHID,
                 0, 0, 0, 1, 1, 0, 0, 0,
                 1.0f, qpart, 0, Kk, 1, 0);
    { dim3 blk(32, 8); relscore_kernel<<<RBn * Kk / 8, blk>>>(hidden, rel_w2, rel_b2, rel); }
    topk_kernel<<<Bb, 1024>>>(rel, selidx, keyvalid, anyvalid);
    { dim3 g(MAXR, Bb); gather_kernel<<<g, 256>>>(retr, selidx, seltok); }
    // q/k/v projections
    launch_tgemm(x, in_w, qb, BS, Dm, Dm, Dm, Dm, Dm,
                 0, 0, 0, 1, 1, 0, 0, 0, 1.0f, in_b, 0, 0, 0, 0);
    launch_tgemm(seltok, in_w + DD, kb, Bb * MAXR, Dm, Dm, Dm, Dm, Dm,
                 0, 0, 0, 1, 1, 0, 0, 0, 1.0f, in_b + Dm, 0, 0, 0, 0);
    launch_tgemm(seltok, in_w + 2 * DD, vb, Bb * MAXR, Dm, Dm, Dm, Dm, Dm,
                 0, 0, 0, 1, 1, 0, 0, 0, 1.0f, in_b + 2 * Dm, 0, 0, 0, 0);
    // fusion scores
    launch_tgemm(qb, kb, fsc, Ss, MAXR, HDm, Dm, Dm, MAXR,
                 (long)Ss * Dm, (long)MAXR * Dm, (long)Hh * Ss * MAXR,
                 Bb * Hh, Hh, HDm, HDm, (long)Ss * MAXR,
                 0.08838834764831845f, 0, 0, 0, 0, 1);
    fsoftmax_kernel<<<Bb * Hh * Ss, 256>>>(fsc, keyvalid);
    // attnout = P @ V
    launch_tgemm(fsc, vb, attnout, Ss, HDm, MAXR, MAXR, Dm, Dm,
                 (long)Hh * Ss * MAXR, (long)MAXR * Dm, (long)Ss * Dm,
                 Bb * Hh, Hh, (long)Ss * MAXR, HDm, HDm,
                 1.0f, 0, 0, 0, 0, 0);
    // out projection
    launch_tgemm(attnout, out_w, fused, BS, Dm, Dm, Dm, Dm, Dm,
                 0, 0, 0, 1, 1, 0, 0, 0, 1.0f, out_b, 0, 0, 0, 0);
    finalize_kernel<<<BS, 256>>>(x, fused, fln_g, fln_b, anyvalid, out);
}

// round 7
// speedup vs baseline: 2.2535x; 1.5780x over previous
#include <cuda_runtime.h>
#include <math.h>
#include <float.h>

// ---------------- problem constants ----------------
#define Dm   1024
#define Bb   4
#define Ss   2048
#define Rr   3
#define Kk   256
#define MAXR 256
#define Hh   8
#define HDm  128
#define BS   (Bb*Ss)     // 8192
#define RBn  (Rr*Bb)     // 12
#define NHID 512         // DIM/2

// ---------------- scratch (device globals; no allocation) ----------------
__device__ float g_qf1[Rr*Bb*Ss*Dm];
__device__ float g_qf2[Rr*Bb*Ss*Dm];
__device__ float g_scores[RBn*Ss*Ss];
__device__ float g_w[RBn*Ss];
__device__ float g_pooled[RBn*Dm];
__device__ float g_pooledln[RBn*Dm];
__device__ float g_queries[RBn*Dm];
__device__ float g_qpart[RBn*NHID];
__device__ float g_hidden[RBn*Kk*NHID];
__device__ float g_rel[RBn*Kk];
__device__ int   g_selidx[Bb*MAXR];
__device__ float g_keyvalid[Bb*MAXR];
__device__ int   g_anyvalid[Bb];
__device__ float g_seltok[Bb*MAXR*Dm];
__device__ float g_q[BS*Dm];
__device__ float g_k[Bb*MAXR*Dm];
__device__ float g_v[Bb*MAXR*Dm];
__device__ float g_fsc[Bb*Hh*Ss*MAXR];
__device__ float g_attnout[BS*Dm];
__device__ float g_fused[BS*Dm];

__device__ __forceinline__ float gelu_f(float x) {
    return 0.5f * x * (1.0f + erff(x * 0.70710678118654752440f));
}

// pack two floats into bf16x2: 'a' -> lower half, 'b' -> upper half
__device__ __forceinline__ unsigned pk_bf16x2(float a, float b) {
    unsigned r;
    asm("cvt.rn.bf16x2.f32 %0, %1, %2;" : "=r"(r) : "f"(b), "f"(a));
    return r;
}
__device__ __forceinline__ float lo16f(unsigned u) { return __uint_as_float(u << 16); }
__device__ __forceinline__ float hi16f(unsigned u) { return __uint_as_float(u & 0xFFFF0000u); }

__device__ __forceinline__ void mma_bf16(float* c,
    unsigned a0, unsigned a1, unsigned a2, unsigned a3,
    unsigned b0, unsigned b1)
{
    asm volatile(
        "mma.sync.aligned.m16n8k16.row.col.f32.bf16.bf16.f32 "
        "{%0,%1,%2,%3},{%4,%5,%6,%7},{%8,%9},{%0,%1,%2,%3};\n"
        : "+f"(c[0]), "+f"(c[1]), "+f"(c[2]), "+f"(c[3])
        : "r"(a0), "r"(a1), "r"(a2), "r"(a3), "r"(b0), "r"(b1));
}

// ---------------- bf16x3 tensor-core GEMM ----------------
// C[m,n] = alpha * sum_k A[m,k] * B(k,n)  (+ bias)(+gelu)
// TRANSB=0: B row-major [K,N]; TRANSB=1: B row-major [N,K] -> A*B^T
// Split-at-staging: smem holds packed bf16x2 hi and lo planes (k-pairs).
template<int TRANSB>
__global__ void __launch_bounds__(256, 1)
tgemm_kernel(const float* __restrict__ A, const float* __restrict__ B,
             float* __restrict__ C,
             int M, int N, int Kd, int lda, int ldb, int ldc,
             long sA1, long sB1, long sC1, int Z2, long sA2, long sB2, long sC2,
             float alpha, const float* __restrict__ bias, long sbias1,
             int bias_mdiv, int act)
{
    // 16 k-pairs x 128 (+pad to 136) of packed bf16x2
    __shared__ unsigned Ah[16][136];
    __shared__ unsigned Al[16][136];
    __shared__ unsigned Bh[16][136];
    __shared__ unsigned Bl[16][136];

    int z  = blockIdx.z;
    int z1 = z / Z2, z2 = z - z1 * Z2;
    A += z1 * sA1 + z2 * sA2;
    B += z1 * sB1 + z2 * sB2;
    C += z1 * sC1 + z2 * sC2;
    const float* bptr = bias ? bias + z1 * sbias1 : (const float*)0;

    int m0 = blockIdx.y * 128;
    int n0 = blockIdx.x * 128;
    int t = threadIdx.x, lane = t & 31, warp = t >> 5;
    int wm = (warp >> 2) * 64, wn = (warp & 3) * 32;
    int r0 = lane >> 2, c4 = lane & 3;

    float acc[4][4][4];
#pragma unroll
    for (int i = 0; i < 4; i++)
#pragma unroll
        for (int j = 0; j < 4; j++)
#pragma unroll
            for (int q = 0; q < 4; q++) acc[i][j][q] = 0.0f;

    int arow = t >> 3;          // 0..31 (A/BT loader row)
    int acol = (t & 7) * 4;     // 0..28 (k offset)
    int kpA  = (t & 7) * 2;     // k-pair base for A loader
    int qrow = t >> 5;          // 0..7  (B k-pair group, TRANSB=0)
    int n4   = (t & 31) * 4;    // 0..124 (B col, TRANSB=0)

    float4 pa[4], pb[4];
    const int KT = Kd >> 5;

    // prologue: load tile 0
    {
        const float* Aptr = A + (long)m0 * lda;
#pragma unroll
        for (int p = 0; p < 4; p++)
            pa[p] = *(const float4*)(Aptr + (long)(arow + p * 32) * lda + acol);
        if (TRANSB == 0) {
            const float* Bptr = B + n0;
#pragma unroll
            for (int p = 0; p < 2; p++) {
                pb[2 * p]     = *(const float4*)(Bptr + (long)((qrow + p * 8) * 2)     * ldb + n4);
                pb[2 * p + 1] = *(const float4*)(Bptr + (long)((qrow + p * 8) * 2 + 1) * ldb + n4);
            }
        } else {
            const float* Bptr = B + (long)n0 * ldb;
#pragma unroll
            for (int p = 0; p < 4; p++)
                pb[p] = *(const float4*)(Bptr + (long)(arow + p * 32) * ldb + acol);
        }
    }

    for (int kt = 0; kt < KT; kt++) {
        // stage registers -> smem with bf16 hi/lo split (once per element)
#pragma unroll
        for (int p = 0; p < 4; p++) {
            int row = arow + p * 32;
            unsigned h0 = pk_bf16x2(pa[p].x, pa[p].y);
            unsigned l0 = pk_bf16x2(pa[p].x - lo16f(h0), pa[p].y - hi16f(h0));
            unsigned h1 = pk_bf16x2(pa[p].z, pa[p].w);
            unsigned l1 = pk_bf16x2(pa[p].z - lo16f(h1), pa[p].w - hi16f(h1));
            Ah[kpA][row] = h0;  Al[kpA][row] = l0;
            Ah[kpA + 1][row] = h1;  Al[kpA + 1][row] = l1;
        }
        if (TRANSB == 0) {
#pragma unroll
            for (int p = 0; p < 2; p++) {
                int kp = qrow + p * 8;
                float4 ra = pb[2 * p], rb = pb[2 * p + 1];
                uint4 H, L;
                H.x = pk_bf16x2(ra.x, rb.x); L.x = pk_bf16x2(ra.x - lo16f(H.x), rb.x - hi16f(H.x));
                H.y = pk_bf16x2(ra.y, rb.y); L.y = pk_bf16x2(ra.y - lo16f(H.y), rb.y - hi16f(H.y));
                H.z = pk_bf16x2(ra.z, rb.z); L.z = pk_bf16x2(ra.z - lo16f(H.z), rb.z - hi16f(H.z));
                H.w = pk_bf16x2(ra.w, rb.w); L.w = pk_bf16x2(ra.w - lo16f(H.w), rb.w - hi16f(H.w));
                *(uint4*)&Bh[kp][n4] = H;
                *(uint4*)&Bl[kp][n4] = L;
            }
        } else {
#pragma unroll
            for (int p = 0; p < 4; p++) {
                int row = arow + p * 32;
                unsigned h0 = pk_bf16x2(pb[p].x, pb[p].y);
                unsigned l0 = pk_bf16x2(pb[p].x - lo16f(h0), pb[p].y - hi16f(h0));
                unsigned h1 = pk_bf16x2(pb[p].z, pb[p].w);
                unsigned l1 = pk_bf16x2(pb[p].z - lo16f(h1), pb[p].w - hi16f(h1));
                Bh[kpA][row] = h0;  Bl[kpA][row] = l0;
                Bh[kpA + 1][row] = h1;  Bl[kpA + 1][row] = l1;
            }
        }
        __syncthreads();

        // prefetch next tile into registers (overlaps with MMA below)
        if (kt + 1 < KT) {
            int k0 = (kt + 1) * 32;
            const float* Aptr = A + (long)m0 * lda + k0;
#pragma unroll
            for (int p = 0; p < 4; p++)
                pa[p] = *(const float4*)(Aptr + (long)(arow + p * 32) * lda + acol);
            if (TRANSB == 0) {
                const float* Bptr = B + (long)k0 * ldb + n0;
#pragma unroll
                for (int p = 0; p < 2; p++) {
                    pb[2 * p]     = *(const float4*)(Bptr + (long)((qrow + p * 8) * 2)     * ldb + n4);
                    pb[2 * p + 1] = *(const float4*)(Bptr + (long)((qrow + p * 8) * 2 + 1) * ldb + n4);
                }
            } else {
                const float* Bptr = B + (long)n0 * ldb + k0;
#pragma unroll
                for (int p = 0; p < 4; p++)
                    pb[p] = *(const float4*)(Bptr + (long)(arow + p * 32) * ldb + acol);
            }
        }

        // compute: 2 k16-substeps, bf16x3 split (pure LDS feed, no cvt)
#pragma unroll
        for (int ks = 0; ks < 2; ks++) {
            int k8 = ks * 8;
            unsigned ah[4][4], al[4][4];
#pragma unroll
            for (int mt = 0; mt < 4; mt++) {
                int row = wm + mt * 16 + r0;
                ah[mt][0] = Ah[k8 + c4][row];
                ah[mt][1] = Ah[k8 + c4][row + 8];
                ah[mt][2] = Ah[k8 + 4 + c4][row];
                ah[mt][3] = Ah[k8 + 4 + c4][row + 8];
                al[mt][0] = Al[k8 + c4][row];
                al[mt][1] = Al[k8 + c4][row + 8];
                al[mt][2] = Al[k8 + 4 + c4][row];
                al[mt][3] = Al[k8 + 4 + c4][row + 8];
            }
            unsigned bh[4][2], bl[4][2];
#pragma unroll
            for (int nt = 0; nt < 4; nt++) {
                int col = wn + nt * 8 + r0;
                bh[nt][0] = Bh[k8 + c4][col];
                bh[nt][1] = Bh[k8 + 4 + c4][col];
                bl[nt][0] = Bl[k8 + c4][col];
                bl[nt][1] = Bl[k8 + 4 + c4][col];
            }
#pragma unroll
            for (int mt = 0; mt < 4; mt++)
#pragma unroll
                for (int nt = 0; nt < 4; nt++) {
                    float* c = acc[mt][nt];
                    mma_bf16(c, al[mt][0], al[mt][1], al[mt][2], al[mt][3], bh[nt][0], bh[nt][1]);
                    mma_bf16(c, ah[mt][0], ah[mt][1], ah[mt][2], ah[mt][3], bl[nt][0], bl[nt][1]);
                    mma_bf16(c, ah[mt][0], ah[mt][1], ah[mt][2], ah[mt][3], bh[nt][0], bh[nt][1]);
                }
        }
        __syncthreads();
    }

    // epilogue
#pragma unroll
    for (int mt = 0; mt < 4; mt++) {
#pragma unroll
        for (int nt = 0; nt < 4; nt++) {
            int row = m0 + wm + mt * 16 + r0;
            int col = n0 + wn + nt * 8 + c4 * 2;
            float v0 = acc[mt][nt][0] * alpha;
            float v1 = acc[mt][nt][1] * alpha;
            float v2 = acc[mt][nt][2] * alpha;
            float v3 = acc[mt][nt][3] * alpha;
            if (bptr) {
                long bi0 = (bias_mdiv ? (long)(row / bias_mdiv) * N : 0L);
                long bi2 = (bias_mdiv ? (long)((row + 8) / bias_mdiv) * N : 0L);
                v0 += bptr[bi0 + col];     v1 += bptr[bi0 + col + 1];
                v2 += bptr[bi2 + col];     v3 += bptr[bi2 + col + 1];
            }
            if (act == 1) { v0 = gelu_f(v0); v1 = gelu_f(v1); v2 = gelu_f(v2); v3 = gelu_f(v3); }
            float2 w01 = make_float2(v0, v1);
            float2 w23 = make_float2(v2, v3);
            *(float2*)(C + (long)row * ldc + col) = w01;
            *(float2*)(C + (long)(row + 8) * ldc + col) = w23;
        }
    }
}

static void launch_tgemm(const float* A, const float* B, float* C,
                         int M, int N, int Kd, int lda, int ldb, int ldc,
                         long sA1, long sB1, long sC1, int Z, int Z2,
                         long sA2, long sB2, long sC2,
                         float alpha, const float* bias, long sbias1,
                         int bias_mdiv, int act, int transB)
{
    dim3 grid(N / 128, M / 128, Z);
    if (transB)
        tgemm_kernel<1><<<grid, 256>>>(A, B, C, M, N, Kd, lda, ldb, ldc,
                                       sA1, sB1, sC1, Z2, sA2, sB2, sC2,
                                       alpha, bias, sbias1, bias_mdiv, act);
    else
        tgemm_kernel<0><<<grid, 256>>>(A, B, C, M, N, Kd, lda, ldb, ldc,
                                       sA1, sB1, sC1, Z2, sA2, sB2, sC2,
                                       alpha, bias, sbias1, bias_mdiv, act);
}

// ---------------- reductions / elementwise kernels ----------------
__device__ __forceinline__ float blockReduceSum256(float v, float* red) {
    int t = threadIdx.x;
    red[t] = v; __syncthreads();
    for (int s = 128; s > 0; s >>= 1) { if (t < s) red[t] += red[t + s]; __syncthreads(); }
    float r = red[0]; __syncthreads();
    return r;
}
__device__ __forceinline__ float blockReduceMax256(float v, float* red) {
    int t = threadIdx.x;
    red[t] = v; __syncthreads();
    for (int s = 128; s > 0; s >>= 1) { if (t < s) red[t] = fmaxf(red[t], red[t + s]); __syncthreads(); }
    float r = red[0]; __syncthreads();
    return r;
}

__global__ void softmax2048_kernel(float* __restrict__ S)
{
    long row = blockIdx.x;
    float* p = S + row * 2048;
    __shared__ float red[256];
    int t = threadIdx.x;
    float lmax = -FLT_MAX;
    for (int i = t; i < 2048; i += 256) lmax = fmaxf(lmax, p[i]);
    float mx = blockReduceMax256(lmax, red);
    float lsum = 0.f;
    float e[8];
#pragma unroll
    for (int q = 0; q < 8; q++) { e[q] = expf(p[t + 256 * q] - mx); lsum += e[q]; }
    float sum = blockReduceSum256(lsum, red);
    float inv = 1.0f / sum;
#pragma unroll
    for (int q = 0; q < 8; q++) p[t + 256 * q] = e[q] * inv;
}

__global__ void colmean_kernel(const float* __restrict__ S, float* __restrict__ w)
{
    int rb = blockIdx.y;
    int tcol = blockIdx.x * 256 + threadIdx.x;
    const float* base = S + (long)rb * Ss * Ss + tcol;
    float acc = 0.f;
    for (int s = 0; s < Ss; s++) acc += base[(long)s * Ss];
    w[rb * Ss + tcol] = acc * (1.0f / (float)Ss);
}

__global__ void pooled_gemv_kernel(const float* __restrict__ qf2,
                                   const float* __restrict__ w,
                                   float* __restrict__ pooled)
{
    int rb = blockIdx.y;
    int d = blockIdx.x * 128 + threadIdx.x;
    const float* Q = qf2 + (long)rb * Ss * Dm + d;
    const float* wv = w + rb * Ss;
    float acc = 0.f;
    for (int tt = 0; tt < Ss; tt++) acc += wv[tt] * Q[(long)tt * Dm];
    pooled[rb * Dm + d] = acc;
}

__global__ void ln12_kernel(const float* __restrict__ pooled,
                            const float* __restrict__ gw, const float* __restrict__ bw,
                            float* __restrict__ out)
{
    int rb = blockIdx.x;
    int r = rb >> 2;
    int t = threadIdx.x;
    __shared__ float red[256];
    const float* p = pooled + rb * Dm;
    float v0 = p[t], v1 = p[t + 256], v2 = p[t + 512], v3 = p[t + 768];
    float mean = blockReduceSum256(v0 + v1 + v2 + v3, red) * (1.0f / (float)Dm);
    float d0 = v0 - mean, d1 = v1 - mean, d2 = v2 - mean, d3 = v3 - mean;
    float var = blockReduceSum256(d0 * d0 + d1 * d1 + d2 * d2 + d3 * d3, red) * (1.0f / (float)Dm);
    float rs = rsqrtf(var + 1e-5f);
    out[rb * Dm + t]       = d0 * rs * gw[r * Dm + t]       + bw[r * Dm + t];
    out[rb * Dm + t + 256] = d1 * rs * gw[r * Dm + t + 256] + bw[r * Dm + t + 256];
    out[rb * Dm + t + 512] = d2 * rs * gw[r * Dm + t + 512] + bw[r * Dm + t + 512];
    out[rb * Dm + t + 768] = d3 * rs * gw[r * Dm + t + 768] + bw[r * Dm + t + 768];
}

__global__ void queries_kernel(const float* __restrict__ pooledln,
                               const float* __restrict__ pool_w,
                               const float* __restrict__ pool_b,
                               float* __restrict__ queries)
{
    int rb = blockIdx.y;
    int r = rb >> 2;
    int e = blockIdx.x * 128 + threadIdx.x;
    __shared__ float sm[Dm];
    for (int i = threadIdx.x; i < Dm; i += 128) sm[i] = pooledln[rb * Dm + i];
    __syncthreads();
    const float* W = pool_w + (long)r * Dm * Dm;
    float acc = pool_b[r * Dm + e];
    for (int d = 0; d < Dm; d++) acc += sm[d] * W[(long)d * Dm + e];
    queries[rb * Dm + e] = acc;
}

__global__ void qpart_kernel(const float* __restrict__ queries,
                             const float* __restrict__ rel_w1,
                             const float* __restrict__ rel_b1,
                             float* __restrict__ qpart)
{
    int rb = blockIdx.y;
    int j = blockIdx.x * 128 + threadIdx.x;
    __shared__ float sm[Dm];
    for (int i = threadIdx.x; i < Dm; i += 128) sm[i] = queries[rb * Dm + i];
    __syncthreads();
    float acc = rel_b1[j];
    for (int d = 0; d < Dm; d++) acc += sm[d] * rel_w1[(long)(Dm + d) * NHID + j];
    qpart[rb * NHID + j] = acc;
}

__global__ void relscore_kernel(const float* __restrict__ hidden,
                                const float* __restrict__ w2,
                                const float* __restrict__ b2,
                                float* __restrict__ rel)
{
    int row = blockIdx.x * 8 + threadIdx.y;
    const float* h = hidden + (long)row * NHID;
    float a = 0.f;
    for (int i = threadIdx.x; i < NHID; i += 32) a += h[i] * w2[i];
#pragma unroll
    for (int off = 16; off > 0; off >>= 1) a += __shfl_down_sync(0xffffffffu, a, off);
    if (threadIdx.x == 0) {
        float s = a + b2[0];
        rel[row] = 1.0f / (1.0f + expf(-s));
    }
}

__global__ void topk_kernel(const float* __restrict__ rel,
                            int* __restrict__ selidx, float* __restrict__ keyvalid,
                            int* __restrict__ anyvalid)
{
    int b = blockIdx.x;
    int t = threadIdx.x;
    __shared__ float v[1024];
    __shared__ int   id[1024];
    float val = -FLT_MAX;
    if (t < Rr * Kk) {
        int r = t >> 8, kk = t & 255;
        float rv = rel[(r * Bb + b) * Kk + kk];
        val = (rv >= 0.5f) ? rv : -FLT_MAX;
    }
    v[t] = val; id[t] = t;
    __syncthreads();
    for (int k = 2; k <= 1024; k <<= 1) {
        for (int j = k >> 1; j > 0; j >>= 1) {
            int ixj = t ^ j;
            if (ixj > t) {
                float va = v[t], vb2 = v[ixj];
                int ia = id[t], ib = id[ixj];
                bool aFirst = (va > vb2) || (va == vb2 && ia < ib);
                bool dirDesc = ((t & k) == 0);
                if (dirDesc ? !aFirst : aFirst) {
                    v[t] = vb2; v[ixj] = va; id[t] = ib; id[ixj] = ia;
                }
            }
            __syncthreads();
        }
    }
    if (t < MAXR) {
        bool valid = (v[t] > -FLT_MAX);
        selidx[b * MAXR + t] = id[t];
        keyvalid[b * MAXR + t] = valid ? 1.0f : 0.0f;
        if (t == 0) anyvalid[b] = valid ? 1 : 0;
    }
}

__global__ void gather_kernel(const float* __restrict__ retrieved,
                              const int* __restrict__ selidx,
                              float* __restrict__ seltok)
{
    int b = blockIdx.y;
    int j = blockIdx.x;
    int t = threadIdx.x;
    int c = selidx[b * MAXR + j];
    int r = c >> 8, kk = c & 255;
    const float4* src = (const float4*)(retrieved + (((long)r * Bb + b) * Kk + kk) * Dm);
    float4* dst = (float4*)(seltok + ((long)b * MAXR + j) * Dm);
    dst[t] = src[t];
}

__global__ void fsoftmax_kernel(float* __restrict__ sc, const float* __restrict__ keyvalid)
{
    long row = blockIdx.x;
    int b = (int)(row / (Hh * Ss));
    float* p = sc + row * MAXR;
    int t = threadIdx.x;
    __shared__ float red[256];
    float val = p[t];
    if (keyvalid[b * MAXR + t] == 0.0f) val = -1e9f;
    float mx = blockReduceMax256(val, red);
    float e = expf(val - mx);
    float sum = blockReduceSum256(e, red);
    p[t] = e / sum;
}

__global__ void finalize_kernel(const float* __restrict__ x, const float* __restrict__ fused,
                                const float* __restrict__ gw, const float* __restrict__ bw,
                                const int* __restrict__ anyvalid, float* __restrict__ out)
{
    long row = blockIdx.x;
    int b = (int)(row >> 11);
    int t = threadIdx.x;
    __shared__ float red[256];
    const float* xr = x + row * Dm;
    const float* fr = fused + row * Dm;
    float v0 = xr[t] + fr[t];
    float v1 = xr[t + 256] + fr[t + 256];
    float v2 = xr[t + 512] + fr[t + 512];
    float v3 = xr[t + 768] + fr[t + 768];
    float mean = blockReduceSum256(v0 + v1 + v2 + v3, red) * (1.0f / (float)Dm);
    float d0 = v0 - mean, d1 = v1 - mean, d2 = v2 - mean, d3 = v3 - mean;
    float var = blockReduceSum256(d0 * d0 + d1 * d1 + d2 * d2 + d3 * d3, red) * (1.0f / (float)Dm);
    float rs = rsqrtf(var + 1e-5f);
    int av = anyvalid[b];
    float* o = out + row * Dm;
    o[t]       = av ? (d0 * rs * gw[t]       + bw[t])       : xr[t];
    o[t + 256] = av ? (d1 * rs * gw[t + 256] + bw[t + 256]) : xr[t + 256];
    o[t + 512] = av ? (d2 * rs * gw[t + 512] + bw[t + 512]) : xr[t + 512];
    o[t + 768] = av ? (d3 * rs * gw[t + 768] + bw[t + 768]) : xr[t + 768];
}

// ---------------- host orchestration ----------------
template <typename T>
static float* sym(T& s) { void* p = 0; cudaGetSymbolAddress(&p, s); return (float*)p; }
template <typename T>
static int* symi(T& s) { void* p = 0; cudaGetSymbolAddress(&p, s); return (int*)p; }

extern "C" void kernel_launch(void* const* d_in, const int* in_sizes, int n_in,
                              void* d_out, int out_size)
{
    const float* x       = (const float*)d_in[0];
    const float* retr    = (const float*)d_in[1];
    const float* qg_w1   = (const float*)d_in[2];
    const float* qg_b1   = (const float*)d_in[3];
    const float* qg_w2   = (const float*)d_in[4];
    const float* qg_b2   = (const float*)d_in[5];
    const float* pln_g   = (const float*)d_in[6];
    const float* pln_b   = (const float*)d_in[7];
    const float* pool_w  = (const float*)d_in[8];
    const float* pool_b  = (const float*)d_in[9];
    const float* rel_w1  = (const float*)d_in[10];
    const float* rel_b1  = (const float*)d_in[11];
    const float* rel_w2  = (const float*)d_in[12];
    const float* rel_b2  = (const float*)d_in[13];
    const float* in_w    = (const float*)d_in[14];
    const float* in_b    = (const float*)d_in[15];
    const float* out_w   = (const float*)d_in[16];
    const float* out_b   = (const float*)d_in[17];
    const float* fln_g   = (const float*)d_in[18];
    const float* fln_b   = (const float*)d_in[19];
    float* out = (float*)d_out;

    float* qf1    = sym(g_qf1);
    float* qf2    = sym(g_qf2);
    float* scores = sym(g_scores);
    float* wmean  = sym(g_w);
    float* pooled = sym(g_pooled);
    float* pooledln = sym(g_pooledln);
    float* queries = sym(g_queries);
    float* qpart  = sym(g_qpart);
    float* hidden = sym(g_hidden);
    float* rel    = sym(g_rel);
    int*   selidx = symi(g_selidx);
    float* keyvalid = sym(g_keyvalid);
    int*   anyvalid = symi(g_anyvalid);
    float* seltok = sym(g_seltok);
    float* qb     = sym(g_q);
    float* kb     = sym(g_k);
    float* vb     = sym(g_v);
    float* fsc    = sym(g_fsc);
    float* attnout = sym(g_attnout);
    float* fused  = sym(g_fused);

    const long DD = (long)Dm * Dm;

    // qf1 = gelu(x @ qg_w1[r] + qg_b1[r])
    launch_tgemm(x, qg_w1, qf1, BS, Dm, Dm, Dm, Dm, Dm,
                 0, DD, (long)BS * Dm, Rr, 1, 0, 0, 0,
                 1.0f, qg_b1, Dm, 0, 1, 0);
    // qf2 = qf1 @ qg_w2[r] + qg_b2[r]
    launch_tgemm(qf1, qg_w2, qf2, BS, Dm, Dm, Dm, Dm, Dm,
                 (long)BS * Dm, DD, (long)BS * Dm, Rr, 1, 0, 0, 0,
                 1.0f, qg_b2, Dm, 0, 0, 0);
    // scores = qf2 @ qf2^T / 32
    launch_tgemm(qf2, qf2, scores, Ss, Ss, Dm, Dm, Dm, Ss,
                 (long)Ss * Dm, (long)Ss * Dm, (long)Ss * Ss, RBn, 1, 0, 0, 0,
                 0.03125f, 0, 0, 0, 0, 1);
    softmax2048_kernel<<<RBn * Ss, 256>>>(scores);
    { dim3 g(Ss / 256, RBn); colmean_kernel<<<g, 256>>>(scores, wmean); }
    { dim3 g(Dm / 128, RBn); pooled_gemv_kernel<<<g, 128>>>(qf2, wmean, pooled); }
    ln12_kernel<<<RBn, 256>>>(pooled, pln_g, pln_b, pooledln);
    { dim3 g(Dm / 128, RBn); queries_kernel<<<g, 128>>>(pooledln, pool_w, pool_b, queries); }
    { dim3 g(NHID / 128, RBn); qpart_kernel<<<g, 128>>>(queries, rel_w1, rel_b1, qpart); }
    // hidden = gelu(retrieved @ rel_w1[:D] + qpart[rb])
    launch_tgemm(retr, rel_w1, hidden, RBn * Kk, NHID, Dm, Dm, NHID, NHID,
                 0, 0, 0, 1, 1, 0, 0, 0,
                 1.0f, qpart, 0, Kk, 1, 0);
    { dim3 blk(32, 8); relscore_kernel<<<RBn * Kk / 8, blk>>>(hidden, rel_w2, rel_b2, rel); }
    topk_kernel<<<Bb, 1024>>>(rel, selidx, keyvalid, anyvalid);
    { dim3 g(MAXR, Bb); gather_kernel<<<g, 256>>>(retr, selidx, seltok); }
    // q/k/v projections
    launch_tgemm(x, in_w, qb, BS, Dm, Dm, Dm, Dm, Dm,
                 0, 0, 0, 1, 1, 0, 0, 0, 1.0f, in_b, 0, 0, 0, 0);
    launch_tgemm(seltok, in_w + DD, kb, Bb * MAXR, Dm, Dm, Dm, Dm, Dm,
                 0, 0, 0, 1, 1, 0, 0, 0, 1.0f, in_b + Dm, 0, 0, 0, 0);
    launch_tgemm(seltok, in_w + 2 * DD, vb, Bb * MAXR, Dm, Dm, Dm, Dm, Dm,
                 0, 0, 0, 1, 1, 0, 0, 0, 1.0f, in_b + 2 * Dm, 0, 0, 0, 0);
    // fusion scores
    launch_tgemm(qb, kb, fsc, Ss, MAXR, HDm, Dm, Dm, MAXR,
                 (long)Ss * Dm, (long)MAXR * Dm, (long)Hh * Ss * MAXR,
                 Bb * Hh, Hh, HDm, HDm, (long)Ss * MAXR,
                 0.08838834764831845f, 0, 0, 0, 0, 1);
    fsoftmax_kernel<<<Bb * Hh * Ss, 256>>>(fsc, keyvalid);
    // attnout = P @ V
    launch_tgemm(fsc, vb, attnout, Ss, HDm, MAXR, MAXR, Dm, Dm,
                 (long)Hh * Ss * MAXR, (long)MAXR * Dm, (long)Ss * Dm,
                 Bb * Hh, Hh, (long)Ss * MAXR, HDm, HDm,
                 1.0f, 0, 0, 0, 0, 0);
    // out projection
    launch_tgemm(attnout, out_w, fused, BS, Dm, Dm, Dm, Dm, Dm,
                 0, 0, 0, 1, 1, 0, 0, 0, 1.0f, out_b, 0, 0, 0, 0);
    finalize_kernel<<<BS, 256>>>(x, fused, fln_g, fln_b, anyvalid, out);
}

// round 10
// speedup vs baseline: 2.7563x; 1.2231x over previous
#include <cuda_runtime.h>
#include <math.h>
#include <float.h>
#include <stdint.h>

// ---------------- problem constants ----------------
#define Dm   1024
#define Bb   4
#define Ss   2048
#define Rr   3
#define Kk   256
#define MAXR 256
#define Hh   8
#define HDm  128
#define BS   (Bb*Ss)     // 8192
#define RBn  (Rr*Bb)     // 12
#define NHID 512         // DIM/2

// ---------------- scratch (device globals; no allocation) ----------------
__device__ float g_qf1[Rr*Bb*Ss*Dm];
__device__ float g_qf2[Rr*Bb*Ss*Dm];
__device__ float g_scores[RBn*Ss*Ss];
__device__ float g_w[RBn*Ss];
__device__ float g_pooled[RBn*Dm];
__device__ float g_pooledln[RBn*Dm];
__device__ float g_queries[RBn*Dm];
__device__ float g_qpart[RBn*NHID];
__device__ float g_hidden[RBn*Kk*NHID];
__device__ float g_rel[RBn*Kk];
__device__ int   g_selidx[Bb*MAXR];
__device__ float g_keyvalid[Bb*MAXR];
__device__ int   g_anyvalid[Bb];
__device__ float g_seltok[Bb*MAXR*Dm];
__device__ float g_q[BS*Dm];
__device__ float g_k[Bb*MAXR*Dm];
__device__ float g_v[Bb*MAXR*Dm];
__device__ float g_fsc[Bb*Hh*Ss*MAXR];
__device__ float g_attnout[BS*Dm];
__device__ float g_fused[BS*Dm];

__device__ __forceinline__ float gelu_f(float x) {
    return 0.5f * x * (1.0f + erff(x * 0.70710678118654752440f));
}

// pack two floats into bf16x2: 'a' -> lower half, 'b' -> upper half
__device__ __forceinline__ unsigned pk_bf16x2(float a, float b) {
    unsigned r;
    asm("cvt.rn.bf16x2.f32 %0, %1, %2;" : "=r"(r) : "f"(b), "f"(a));
    return r;
}
__device__ __forceinline__ float lo16f(unsigned u) { return __uint_as_float(u << 16); }
__device__ __forceinline__ float hi16f(unsigned u) { return __uint_as_float(u & 0xFFFF0000u); }

__device__ __forceinline__ void mma_bf16(float* c,
    unsigned a0, unsigned a1, unsigned a2, unsigned a3,
    unsigned b0, unsigned b1)
{
    asm volatile(
        "mma.sync.aligned.m16n8k16.row.col.f32.bf16.bf16.f32 "
        "{%0,%1,%2,%3},{%4,%5,%6,%7},{%8,%9},{%0,%1,%2,%3};\n"
        : "+f"(c[0]), "+f"(c[1]), "+f"(c[2]), "+f"(c[3])
        : "r"(a0), "r"(a1), "r"(a2), "r"(a3), "r"(b0), "r"(b1));
}

// ---------------- bf16x3 tensor-core GEMM (mma.sync path) ----------------
// C[m,n] = alpha * sum_k A[m,k] * B(k,n)  (+ bias)(+gelu)
// TRANSB=0: B row-major [K,N]; TRANSB=1: B row-major [N,K] -> A*B^T
template<int TRANSB>
__global__ void __launch_bounds__(256, 1)
tgemm_kernel(const float* __restrict__ A, const float* __restrict__ B,
             float* __restrict__ C,
             int M, int N, int Kd, int lda, int ldb, int ldc,
             long sA1, long sB1, long sC1, int Z2, long sA2, long sB2, long sC2,
             float alpha, const float* __restrict__ bias, long sbias1,
             int bias_mdiv, int act)
{
    __shared__ unsigned Ah[16][136];
    __shared__ unsigned Al[16][136];
    __shared__ unsigned Bh[16][136];
    __shared__ unsigned Bl[16][136];

    int z  = blockIdx.z;
    int z1 = z / Z2, z2 = z - z1 * Z2;
    A += z1 * sA1 + z2 * sA2;
    B += z1 * sB1 + z2 * sB2;
    C += z1 * sC1 + z2 * sC2;
    const float* bptr = bias ? bias + z1 * sbias1 : (const float*)0;

    int m0 = blockIdx.y * 128;
    int n0 = blockIdx.x * 128;
    int t = threadIdx.x, lane = t & 31, warp = t >> 5;
    int wm = (warp >> 2) * 64, wn = (warp & 3) * 32;
    int r0 = lane >> 2, c4 = lane & 3;

    float acc[4][4][4];
#pragma unroll
    for (int i = 0; i < 4; i++)
#pragma unroll
        for (int j = 0; j < 4; j++)
#pragma unroll
            for (int q = 0; q < 4; q++) acc[i][j][q] = 0.0f;

    int arow = t >> 3;
    int acol = (t & 7) * 4;
    int kpA  = (t & 7) * 2;
    int qrow = t >> 5;
    int n4   = (t & 31) * 4;

    float4 pa[4], pb[4];
    const int KT = Kd >> 5;

    {
        const float* Aptr = A + (long)m0 * lda;
#pragma unroll
        for (int p = 0; p < 4; p++)
            pa[p] = *(const float4*)(Aptr + (long)(arow + p * 32) * lda + acol);
        if (TRANSB == 0) {
            const float* Bptr = B + n0;
#pragma unroll
            for (int p = 0; p < 2; p++) {
                pb[2 * p]     = *(const float4*)(Bptr + (long)((qrow + p * 8) * 2)     * ldb + n4);
                pb[2 * p + 1] = *(const float4*)(Bptr + (long)((qrow + p * 8) * 2 + 1) * ldb + n4);
            }
        } else {
            const float* Bptr = B + (long)n0 * ldb;
#pragma unroll
            for (int p = 0; p < 4; p++)
                pb[p] = *(const float4*)(Bptr + (long)(arow + p * 32) * ldb + acol);
        }
    }

    for (int kt = 0; kt < KT; kt++) {
#pragma unroll
        for (int p = 0; p < 4; p++) {
            int row = arow + p * 32;
            unsigned h0 = pk_bf16x2(pa[p].x, pa[p].y);
            unsigned l0 = pk_bf16x2(pa[p].x - lo16f(h0), pa[p].y - hi16f(h0));
            unsigned h1 = pk_bf16x2(pa[p].z, pa[p].w);
            unsigned l1 = pk_bf16x2(pa[p].z - lo16f(h1), pa[p].w - hi16f(h1));
            Ah[kpA][row] = h0;  Al[kpA][row] = l0;
            Ah[kpA + 1][row] = h1;  Al[kpA + 1][row] = l1;
        }
        if (TRANSB == 0) {
#pragma unroll
            for (int p = 0; p < 2; p++) {
                int kp = qrow + p * 8;
                float4 ra = pb[2 * p], rb = pb[2 * p + 1];
                uint4 H, L;
                H.x = pk_bf16x2(ra.x, rb.x); L.x = pk_bf16x2(ra.x - lo16f(H.x), rb.x - hi16f(H.x));
                H.y = pk_bf16x2(ra.y, rb.y); L.y = pk_bf16x2(ra.y - lo16f(H.y), rb.y - hi16f(H.y));
                H.z = pk_bf16x2(ra.z, rb.z); L.z = pk_bf16x2(ra.z - lo16f(H.z), rb.z - hi16f(H.z));
                H.w = pk_bf16x2(ra.w, rb.w); L.w = pk_bf16x2(ra.w - lo16f(H.w), rb.w - hi16f(H.w));
                *(uint4*)&Bh[kp][n4] = H;
                *(uint4*)&Bl[kp][n4] = L;
            }
        } else {
#pragma unroll
            for (int p = 0; p < 4; p++) {
                int row = arow + p * 32;
                unsigned h0 = pk_bf16x2(pb[p].x, pb[p].y);
                unsigned l0 = pk_bf16x2(pb[p].x - lo16f(h0), pb[p].y - hi16f(h0));
                unsigned h1 = pk_bf16x2(pb[p].z, pb[p].w);
                unsigned l1 = pk_bf16x2(pb[p].z - lo16f(h1), pb[p].w - hi16f(h1));
                Bh[kpA][row] = h0;  Bl[kpA][row] = l0;
                Bh[kpA + 1][row] = h1;  Bl[kpA + 1][row] = l1;
            }
        }
        __syncthreads();

        if (kt + 1 < KT) {
            int k0 = (kt + 1) * 32;
            const float* Aptr = A + (long)m0 * lda + k0;
#pragma unroll
            for (int p = 0; p < 4; p++)
                pa[p] = *(const float4*)(Aptr + (long)(arow + p * 32) * lda + acol);
            if (TRANSB == 0) {
                const float* Bptr = B + (long)k0 * ldb + n0;
#pragma unroll
                for (int p = 0; p < 2; p++) {
                    pb[2 * p]     = *(const float4*)(Bptr + (long)((qrow + p * 8) * 2)     * ldb + n4);
                    pb[2 * p + 1] = *(const float4*)(Bptr + (long)((qrow + p * 8) * 2 + 1) * ldb + n4);
                }
            } else {
                const float* Bptr = B + (long)n0 * ldb + k0;
#pragma unroll
                for (int p = 0; p < 4; p++)
                    pb[p] = *(const float4*)(Bptr + (long)(arow + p * 32) * ldb + acol);
            }
        }

#pragma unroll
        for (int ks = 0; ks < 2; ks++) {
            int k8 = ks * 8;
            unsigned ah[4][4], al[4][4];
#pragma unroll
            for (int mt = 0; mt < 4; mt++) {
                int row = wm + mt * 16 + r0;
                ah[mt][0] = Ah[k8 + c4][row];
                ah[mt][1] = Ah[k8 + c4][row + 8];
                ah[mt][2] = Ah[k8 + 4 + c4][row];
                ah[mt][3] = Ah[k8 + 4 + c4][row + 8];
                al[mt][0] = Al[k8 + c4][row];
                al[mt][1] = Al[k8 + c4][row + 8];
                al[mt][2] = Al[k8 + 4 + c4][row];
                al[mt][3] = Al[k8 + 4 + c4][row + 8];
            }
            unsigned bh[4][2], bl[4][2];
#pragma unroll
            for (int nt = 0; nt < 4; nt++) {
                int col = wn + nt * 8 + r0;
                bh[nt][0] = Bh[k8 + c4][col];
                bh[nt][1] = Bh[k8 + 4 + c4][col];
                bl[nt][0] = Bl[k8 + c4][col];
                bl[nt][1] = Bl[k8 + 4 + c4][col];
            }
#pragma unroll
            for (int mt = 0; mt < 4; mt++)
#pragma unroll
                for (int nt = 0; nt < 4; nt++) {
                    float* c = acc[mt][nt];
                    mma_bf16(c, al[mt][0], al[mt][1], al[mt][2], al[mt][3], bh[nt][0], bh[nt][1]);
                    mma_bf16(c, ah[mt][0], ah[mt][1], ah[mt][2], ah[mt][3], bl[nt][0], bl[nt][1]);
                    mma_bf16(c, ah[mt][0], ah[mt][1], ah[mt][2], ah[mt][3], bh[nt][0], bh[nt][1]);
                }
        }
        __syncthreads();
    }

#pragma unroll
    for (int mt = 0; mt < 4; mt++) {
#pragma unroll
        for (int nt = 0; nt < 4; nt++) {
            int row = m0 + wm + mt * 16 + r0;
            int col = n0 + wn + nt * 8 + c4 * 2;
            float v0 = acc[mt][nt][0] * alpha;
            float v1 = acc[mt][nt][1] * alpha;
            float v2 = acc[mt][nt][2] * alpha;
            float v3 = acc[mt][nt][3] * alpha;
            if (bptr) {
                long bi0 = (bias_mdiv ? (long)(row / bias_mdiv) * N : 0L);
                long bi2 = (bias_mdiv ? (long)((row + 8) / bias_mdiv) * N : 0L);
                v0 += bptr[bi0 + col];     v1 += bptr[bi0 + col + 1];
                v2 += bptr[bi2 + col];     v3 += bptr[bi2 + col + 1];
            }
            if (act == 1) { v0 = gelu_f(v0); v1 = gelu_f(v1); v2 = gelu_f(v2); v3 = gelu_f(v3); }
            *(float2*)(C + (long)row * ldc + col) = make_float2(v0, v1);
            *(float2*)(C + (long)(row + 8) * ldc + col) = make_float2(v2, v3);
        }
    }
}

static void launch_tgemm(const float* A, const float* B, float* C,
                         int M, int N, int Kd, int lda, int ldb, int ldc,
                         long sA1, long sB1, long sC1, int Z, int Z2,
                         long sA2, long sB2, long sC2,
                         float alpha, const float* bias, long sbias1,
                         int bias_mdiv, int act, int transB)
{
    dim3 grid(N / 128, M / 128, Z);
    if (transB)
        tgemm_kernel<1><<<grid, 256>>>(A, B, C, M, N, Kd, lda, ldb, ldc,
                                       sA1, sB1, sC1, Z2, sA2, sB2, sC2,
                                       alpha, bias, sbias1, bias_mdiv, act);
    else
        tgemm_kernel<0><<<grid, 256>>>(A, B, C, M, N, Kd, lda, ldb, ldc,
                                       sA1, sB1, sC1, Z2, sA2, sB2, sC2,
                                       alpha, bias, sbias1, bias_mdiv, act);
}

// ---------------- symmetric scores GEMM: S = alpha * A A^T (A: [2048,1024]) ----
// grid.x enumerates upper-triangle 128x128 block pairs (bx >= by); off-diagonal
// blocks mirror-write the transposed block.
__global__ void __launch_bounds__(256, 1)
sym_gemm_kernel(const float* __restrict__ Ain, float* __restrict__ Cout, float alpha)
{
    __shared__ unsigned Ah[16][136];
    __shared__ unsigned Al[16][136];
    __shared__ unsigned Bh[16][136];
    __shared__ unsigned Bl[16][136];

    const float* A = Ain + (long)blockIdx.z * Ss * Dm;
    float* C = Cout + (long)blockIdx.z * Ss * Ss;

    // map linear index -> (bx >= by), 16x16 grid of blocks
    int by = 0, rem = blockIdx.x;
    while (rem >= 16 - by) { rem -= 16 - by; by++; }
    int bx = by + rem;

    int m0 = by * 128;
    int n0 = bx * 128;
    int t = threadIdx.x, lane = t & 31, warp = t >> 5;
    int wm = (warp >> 2) * 64, wn = (warp & 3) * 32;
    int r0 = lane >> 2, c4 = lane & 3;

    float acc[4][4][4];
#pragma unroll
    for (int i = 0; i < 4; i++)
#pragma unroll
        for (int j = 0; j < 4; j++)
#pragma unroll
            for (int q = 0; q < 4; q++) acc[i][j][q] = 0.0f;

    int arow = t >> 3;
    int acol = (t & 7) * 4;
    int kpA  = (t & 7) * 2;

    float4 pa[4], pb[4];
    const int KT = Dm >> 5;   // 32

    {
        const float* Aptr = A + (long)m0 * Dm;
        const float* Bptr = A + (long)n0 * Dm;
#pragma unroll
        for (int p = 0; p < 4; p++) {
            pa[p] = *(const float4*)(Aptr + (long)(arow + p * 32) * Dm + acol);
            pb[p] = *(const float4*)(Bptr + (long)(arow + p * 32) * Dm + acol);
        }
    }

    for (int kt = 0; kt < KT; kt++) {
#pragma unroll
        for (int p = 0; p < 4; p++) {
            int row = arow + p * 32;
            unsigned h0 = pk_bf16x2(pa[p].x, pa[p].y);
            unsigned l0 = pk_bf16x2(pa[p].x - lo16f(h0), pa[p].y - hi16f(h0));
            unsigned h1 = pk_bf16x2(pa[p].z, pa[p].w);
            unsigned l1 = pk_bf16x2(pa[p].z - lo16f(h1), pa[p].w - hi16f(h1));
            Ah[kpA][row] = h0;  Al[kpA][row] = l0;
            Ah[kpA + 1][row] = h1;  Al[kpA + 1][row] = l1;
            h0 = pk_bf16x2(pb[p].x, pb[p].y);
            l0 = pk_bf16x2(pb[p].x - lo16f(h0), pb[p].y - hi16f(h0));
            h1 = pk_bf16x2(pb[p].z, pb[p].w);
            l1 = pk_bf16x2(pb[p].z - lo16f(h1), pb[p].w - hi16f(h1));
            Bh[kpA][row] = h0;  Bl[kpA][row] = l0;
            Bh[kpA + 1][row] = h1;  Bl[kpA + 1][row] = l1;
        }
        __syncthreads();

        if (kt + 1 < KT) {
            int k0 = (kt + 1) * 32;
            const float* Aptr = A + (long)m0 * Dm + k0;
            const float* Bptr = A + (long)n0 * Dm + k0;
#pragma unroll
            for (int p = 0; p < 4; p++) {
                pa[p] = *(const float4*)(Aptr + (long)(arow + p * 32) * Dm + acol);
                pb[p] = *(const float4*)(Bptr + (long)(arow + p * 32) * Dm + acol);
            }
        }

#pragma unroll
        for (int ks = 0; ks < 2; ks++) {
            int k8 = ks * 8;
            unsigned ah[4][4], al[4][4];
#pragma unroll
            for (int mt = 0; mt < 4; mt++) {
                int row = wm + mt * 16 + r0;
                ah[mt][0] = Ah[k8 + c4][row];
                ah[mt][1] = Ah[k8 + c4][row + 8];
                ah[mt][2] = Ah[k8 + 4 + c4][row];
                ah[mt][3] = Ah[k8 + 4 + c4][row + 8];
                al[mt][0] = Al[k8 + c4][row];
                al[mt][1] = Al[k8 + c4][row + 8];
                al[mt][2] = Al[k8 + 4 + c4][row];
                al[mt][3] = Al[k8 + 4 + c4][row + 8];
            }
            unsigned bh[4][2], bl[4][2];
#pragma unroll
            for (int nt = 0; nt < 4; nt++) {
                int col = wn + nt * 8 + r0;
                bh[nt][0] = Bh[k8 + c4][col];
                bh[nt][1] = Bh[k8 + 4 + c4][col];
                bl[nt][0] = Bl[k8 + c4][col];
                bl[nt][1] = Bl[k8 + 4 + c4][col];
            }
#pragma unroll
            for (int mt = 0; mt < 4; mt++)
#pragma unroll
                for (int nt = 0; nt < 4; nt++) {
                    float* c = acc[mt][nt];
                    mma_bf16(c, al[mt][0], al[mt][1], al[mt][2], al[mt][3], bh[nt][0], bh[nt][1]);
                    mma_bf16(c, ah[mt][0], ah[mt][1], ah[mt][2], ah[mt][3], bl[nt][0], bl[nt][1]);
                    mma_bf16(c, ah[mt][0], ah[mt][1], ah[mt][2], ah[mt][3], bh[nt][0], bh[nt][1]);
                }
        }
        __syncthreads();
    }

    bool mirror = (bx != by);
#pragma unroll
    for (int mt = 0; mt < 4; mt++) {
#pragma unroll
        for (int nt = 0; nt < 4; nt++) {
            int row = m0 + wm + mt * 16 + r0;
            int col = n0 + wn + nt * 8 + c4 * 2;
            float v0 = acc[mt][nt][0] * alpha;
            float v1 = acc[mt][nt][1] * alpha;
            float v2 = acc[mt][nt][2] * alpha;
            float v3 = acc[mt][nt][3] * alpha;
            *(float2*)(C + (long)row * Ss + col) = make_float2(v0, v1);
            *(float2*)(C + (long)(row + 8) * Ss + col) = make_float2(v2, v3);
            if (mirror) {
                C[(long)col * Ss + row]           = v0;
                C[(long)(col + 1) * Ss + row]     = v1;
                C[(long)col * Ss + row + 8]       = v2;
                C[(long)(col + 1) * Ss + row + 8] = v3;
            }
        }
    }
}

// ---------------- shuffle-based block reductions (256 threads) ----------------
__device__ __forceinline__ float warpSum(float v) {
#pragma unroll
    for (int o = 16; o > 0; o >>= 1) v += __shfl_xor_sync(0xffffffffu, v, o);
    return v;
}
__device__ __forceinline__ float warpMax(float v) {
#pragma unroll
    for (int o = 16; o > 0; o >>= 1) v = fmaxf(v, __shfl_xor_sync(0xffffffffu, v, o));
    return v;
}
__device__ __forceinline__ float blockSum256(float v, float* sm8) {
    int w = threadIdx.x >> 5, l = threadIdx.x & 31;
    v = warpSum(v);
    if (l == 0) sm8[w] = v;
    __syncthreads();
    float x = (l < 8) ? sm8[l] : 0.0f;
    x = warpSum(x);
    __syncthreads();
    if (threadIdx.x == 0) sm8[0] = x;
    __syncthreads();
    float r = sm8[0];
    __syncthreads();
    return r;
}
__device__ __forceinline__ float blockMax256(float v, float* sm8) {
    int w = threadIdx.x >> 5, l = threadIdx.x & 31;
    v = warpMax(v);
    if (l == 0) sm8[w] = v;
    __syncthreads();
    float x = (l < 8) ? sm8[l] : -FLT_MAX;
    x = warpMax(x);
    __syncthreads();
    if (threadIdx.x == 0) sm8[0] = x;
    __syncthreads();
    float r = sm8[0];
    __syncthreads();
    return r;
}

__global__ void softmax2048_kernel(float* __restrict__ S)
{
    long row = blockIdx.x;
    float* p = S + row * 2048;
    __shared__ float red[8];
    int t = threadIdx.x;
    float e[8];
    float lmax = -FLT_MAX;
#pragma unroll
    for (int q = 0; q < 8; q++) { e[q] = p[t + 256 * q]; lmax = fmaxf(lmax, e[q]); }
    float mx = blockMax256(lmax, red);
    float lsum = 0.f;
#pragma unroll
    for (int q = 0; q < 8; q++) { e[q] = expf(e[q] - mx); lsum += e[q]; }
    float sum = blockSum256(lsum, red);
    float inv = 1.0f / sum;
#pragma unroll
    for (int q = 0; q < 8; q++) p[t + 256 * q] = e[q] * inv;
}

__global__ void colmean_kernel(const float* __restrict__ S, float* __restrict__ w)
{
    int rb = blockIdx.y;
    int tcol = blockIdx.x * 256 + threadIdx.x;
    const float* base = S + (long)rb * Ss * Ss + tcol;
    float acc = 0.f;
    for (int s = 0; s < Ss; s++) acc += base[(long)s * Ss];
    w[rb * Ss + tcol] = acc * (1.0f / (float)Ss);
}

__global__ void pooled_gemv_kernel(const float* __restrict__ qf2,
                                   const float* __restrict__ w,
                                   float* __restrict__ pooled)
{
    int rb = blockIdx.y;
    int d = blockIdx.x * 128 + threadIdx.x;
    const float* Q = qf2 + (long)rb * Ss * Dm + d;
    const float* wv = w + rb * Ss;
    float acc = 0.f;
    for (int tt = 0; tt < Ss; tt++) acc += wv[tt] * Q[(long)tt * Dm];
    pooled[rb * Dm + d] = acc;
}

__global__ void ln12_kernel(const float* __restrict__ pooled,
                            const float* __restrict__ gw, const float* __restrict__ bw,
                            float* __restrict__ out)
{
    int rb = blockIdx.x;
    int r = rb >> 2;
    int t = threadIdx.x;
    __shared__ float red[8];
    const float* p = pooled + rb * Dm;
    float v0 = p[t], v1 = p[t + 256], v2 = p[t + 512], v3 = p[t + 768];
    float mean = blockSum256(v0 + v1 + v2 + v3, red) * (1.0f / (float)Dm);
    float d0 = v0 - mean, d1 = v1 - mean, d2 = v2 - mean, d3 = v3 - mean;
    float var = blockSum256(d0 * d0 + d1 * d1 + d2 * d2 + d3 * d3, red) * (1.0f / (float)Dm);
    float rs = rsqrtf(var + 1e-5f);
    out[rb * Dm + t]       = d0 * rs * gw[r * Dm + t]       + bw[r * Dm + t];
    out[rb * Dm + t + 256] = d1 * rs * gw[r * Dm + t + 256] + bw[r * Dm + t + 256];
    out[rb * Dm + t + 512] = d2 * rs * gw[r * Dm + t + 512] + bw[r * Dm + t + 512];
    out[rb * Dm + t + 768] = d3 * rs * gw[r * Dm + t + 768] + bw[r * Dm + t + 768];
}

__global__ void queries_kernel(const float* __restrict__ pooledln,
                               const float* __restrict__ pool_w,
                               const float* __restrict__ pool_b,
                               float* __restrict__ queries)
{
    int rb = blockIdx.y;
    int r = rb >> 2;
    int e = blockIdx.x * 128 + threadIdx.x;
    __shared__ float sm[Dm];
    for (int i = threadIdx.x; i < Dm; i += 128) sm[i] = pooledln[rb * Dm + i];
    __syncthreads();
    const float* W = pool_w + (long)r * Dm * Dm;
    float acc = pool_b[r * Dm + e];
    for (int d = 0; d < Dm; d++) acc += sm[d] * W[(long)d * Dm + e];
    queries[rb * Dm + e] = acc;
}

__global__ void qpart_kernel(const float* __restrict__ queries,
                             const float* __restrict__ rel_w1,
                             const float* __restrict__ rel_b1,
                             float* __restrict__ qpart)
{
    int rb = blockIdx.y;
    int j = blockIdx.x * 128 + threadIdx.x;
    __shared__ float sm[Dm];
    for (int i = threadIdx.x; i < Dm; i += 128) sm[i] = queries[rb * Dm + i];
    __syncthreads();
    float acc = rel_b1[j];
    for (int d = 0; d < Dm; d++) acc += sm[d] * rel_w1[(long)(Dm + d) * NHID + j];
    qpart[rb * NHID + j] = acc;
}

__global__ void relscore_kernel(const float* __restrict__ hidden,
                                const float* __restrict__ w2,
                                const float* __restrict__ b2,
                                float* __restrict__ rel)
{
    int row = blockIdx.x * 8 + threadIdx.y;
    const float* h = hidden + (long)row * NHID;
    float a = 0.f;
    for (int i = threadIdx.x; i < NHID; i += 32) a += h[i] * w2[i];
#pragma unroll
    for (int off = 16; off > 0; off >>= 1) a += __shfl_down_sync(0xffffffffu, a, off);
    if (threadIdx.x == 0) {
        float s = a + b2[0];
        rel[row] = 1.0f / (1.0f + expf(-s));
    }
}

__global__ void topk_kernel(const float* __restrict__ rel,
                            int* __restrict__ selidx, float* __restrict__ keyvalid,
                            int* __restrict__ anyvalid)
{
    int b = blockIdx.x;
    int t = threadIdx.x;
    __shared__ float v[1024];
    __shared__ int   id[1024];
    float val = -FLT_MAX;
    if (t < Rr * Kk) {
        int r = t >> 8, kk = t & 255;
        float rv = rel[(r * Bb + b) * Kk + kk];
        val = (rv >= 0.5f) ? rv : -FLT_MAX;
    }
    v[t] = val; id[t] = t;
    __syncthreads();
    for (int k = 2; k <= 1024; k <<= 1) {
        for (int j = k >> 1; j > 0; j >>= 1) {
            int ixj = t ^ j;
            if (ixj > t) {
                float va = v[t], vb2 = v[ixj];
                int ia = id[t], ib = id[ixj];
                bool aFirst = (va > vb2) || (va == vb2 && ia < ib);
                bool dirDesc = ((t & k) == 0);
                if (dirDesc ? !aFirst : aFirst) {
                    v[t] = vb2; v[ixj] = va; id[t] = ib; id[ixj] = ia;
                }
            }
            __syncthreads();
        }
    }
    if (t < MAXR) {
        bool valid = (v[t] > -FLT_MAX);
        selidx[b * MAXR + t] = id[t];
        keyvalid[b * MAXR + t] = valid ? 1.0f : 0.0f;
        if (t == 0) anyvalid[b] = valid ? 1 : 0;
    }
}

__global__ void gather_kernel(const float* __restrict__ retrieved,
                              const int* __restrict__ selidx,
                              float* __restrict__ seltok)
{
    int b = blockIdx.y;
    int j = blockIdx.x;
    int t = threadIdx.x;
    int c = selidx[b * MAXR + j];
    int r = c >> 8, kk = c & 255;
    const float4* src = (const float4*)(retrieved + (((long)r * Bb + b) * Kk + kk) * Dm);
    float4* dst = (float4*)(seltok + ((long)b * MAXR + j) * Dm);
    dst[t] = src[t];
}

__global__ void fsoftmax_kernel(float* __restrict__ sc, const float* __restrict__ keyvalid)
{
    long row = blockIdx.x;
    int b = (int)(row / (Hh * Ss));
    float* p = sc + row * MAXR;
    int t = threadIdx.x;
    __shared__ float red[8];
    float val = p[t];
    if (keyvalid[b * MAXR + t] == 0.0f) val = -1e9f;
    float mx = blockMax256(val, red);
    float e = expf(val - mx);
    float sum = blockSum256(e, red);
    p[t] = e / sum;
}

__global__ void finalize_kernel(const float* __restrict__ x, const float* __restrict__ fused,
                                const float* __restrict__ gw, const float* __restrict__ bw,
                                const int* __restrict__ anyvalid, float* __restrict__ out)
{
    long row = blockIdx.x;
    int b = (int)(row >> 11);
    int t = threadIdx.x;
    __shared__ float red[8];
    const float* xr = x + row * Dm;
    const float* fr = fused + row * Dm;
    float v0 = xr[t] + fr[t];
    float v1 = xr[t + 256] + fr[t + 256];
    float v2 = xr[t + 512] + fr[t + 512];
    float v3 = xr[t + 768] + fr[t + 768];
    float mean = blockSum256(v0 + v1 + v2 + v3, red) * (1.0f / (float)Dm);
    float d0 = v0 - mean, d1 = v1 - mean, d2 = v2 - mean, d3 = v3 - mean;
    float var = blockSum256(d0 * d0 + d1 * d1 + d2 * d2 + d3 * d3, red) * (1.0f / (float)Dm);
    float rs = rsqrtf(var + 1e-5f);
    int av = anyvalid[b];
    float* o = out + row * Dm;
    o[t]       = av ? (d0 * rs * gw[t]       + bw[t])       : xr[t];
    o[t + 256] = av ? (d1 * rs * gw[t + 256] + bw[t + 256]) : xr[t + 256];
    o[t + 512] = av ? (d2 * rs * gw[t + 512] + bw[t + 512]) : xr[t + 512];
    o[t + 768] = av ? (d3 * rs * gw[t + 768] + bw[t + 768]) : xr[t + 768];
}

// ---------------- host orchestration ----------------
template <typename T>
static float* sym(T& s) { void* p = 0; cudaGetSymbolAddress(&p, s); return (float*)p; }
template <typename T>
static int* symi(T& s) { void* p = 0; cudaGetSymbolAddress(&p, s); return (int*)p; }

extern "C" void kernel_launch(void* const* d_in, const int* in_sizes, int n_in,
                              void* d_out, int out_size)
{
    const float* x       = (const float*)d_in[0];
    const float* retr    = (const float*)d_in[1];
    const float* qg_w1   = (const float*)d_in[2];
    const float* qg_b1   = (const float*)d_in[3];
    const float* qg_w2   = (const float*)d_in[4];
    const float* qg_b2   = (const float*)d_in[5];
    const float* pln_g   = (const float*)d_in[6];
    const float* pln_b   = (const float*)d_in[7];
    const float* pool_w  = (const float*)d_in[8];
    const float* pool_b  = (const float*)d_in[9];
    const float* rel_w1  = (const float*)d_in[10];
    const float* rel_b1  = (const float*)d_in[11];
    const float* rel_w2  = (const float*)d_in[12];
    const float* rel_b2  = (const float*)d_in[13];
    const float* in_w    = (const float*)d_in[14];
    const float* in_b    = (const float*)d_in[15];
    const float* out_w   = (const float*)d_in[16];
    const float* out_b   = (const float*)d_in[17];
    const float* fln_g   = (const float*)d_in[18];
    const float* fln_b   = (const float*)d_in[19];
    float* out = (float*)d_out;

    float* qf1    = sym(g_qf1);
    float* qf2    = sym(g_qf2);
    float* scores = sym(g_scores);
    float* wmean  = sym(g_w);
    float* pooled = sym(g_pooled);
    float* pooledln = sym(g_pooledln);
    float* queries = sym(g_queries);
    float* qpart  = sym(g_qpart);
    float* hidden = sym(g_hidden);
    float* rel    = sym(g_rel);
    int*   selidx = symi(g_selidx);
    float* keyvalid = sym(g_keyvalid);
    int*   anyvalid = symi(g_anyvalid);
    float* seltok = sym(g_seltok);
    float* qb     = sym(g_q);
    float* kb     = sym(g_k);
    float* vb     = sym(g_v);
    float* fsc    = sym(g_fsc);
    float* attnout = sym(g_attnout);
    float* fused  = sym(g_fused);

    const long DD = (long)Dm * Dm;

    // qf1 = gelu(x @ qg_w1[r] + qg_b1[r])
    launch_tgemm(x, qg_w1, qf1, BS, Dm, Dm, Dm, Dm, Dm,
                 0, DD, (long)BS * Dm, Rr, 1, 0, 0, 0,
                 1.0f, qg_b1, Dm, 0, 1, 0);
    // qf2 = qf1 @ qg_w2[r] + qg_b2[r]
    launch_tgemm(qf1, qg_w2, qf2, BS, Dm, Dm, Dm, Dm, Dm,
                 (long)BS * Dm, DD, (long)BS * Dm, Rr, 1, 0, 0, 0,
                 1.0f, qg_b2, Dm, 0, 0, 0);
    // scores = qf2 @ qf2^T / 32  (symmetric: triangle blocks + mirror)
    {
        dim3 g(136, 1, RBn);
        sym_gemm_kernel<<<g, 256>>>(qf2, scores, 0.03125f);
    }
    softmax2048_kernel<<<RBn * Ss, 256>>>(scores);
    { dim3 g(Ss / 256, RBn); colmean_kernel<<<g, 256>>>(scores, wmean); }
    { dim3 g(Dm / 128, RBn); pooled_gemv_kernel<<<g, 128>>>(qf2, wmean, pooled); }
    ln12_kernel<<<RBn, 256>>>(pooled, pln_g, pln_b, pooledln);
    { dim3 g(Dm / 128, RBn); queries_kernel<<<g, 128>>>(pooledln, pool_w, pool_b, queries); }
    { dim3 g(NHID / 128, RBn); qpart_kernel<<<g, 128>>>(queries, rel_w1, rel_b1, qpart); }
    // hidden = gelu(retrieved @ rel_w1[:D] + qpart[rb])
    launch_tgemm(retr, rel_w1, hidden, RBn * Kk, NHID, Dm, Dm, NHID, NHID,
                 0, 0, 0, 1, 1, 0, 0, 0,
                 1.0f, qpart, 0, Kk, 1, 0);
    { dim3 blk(32, 8); relscore_kernel<<<RBn * Kk / 8, blk>>>(hidden, rel_w2, rel_b2, rel); }
    topk_kernel<<<Bb, 1024>>>(rel, selidx, keyvalid, anyvalid);
    { dim3 g(MAXR, Bb); gather_kernel<<<g, 256>>>(retr, selidx, seltok); }
    // q/k/v projections
    launch_tgemm(x, in_w, qb, BS, Dm, Dm, Dm, Dm, Dm,
                 0, 0, 0, 1, 1, 0, 0, 0, 1.0f, in_b, 0, 0, 0, 0);
    launch_tgemm(seltok, in_w + DD, kb, Bb * MAXR, Dm, Dm, Dm, Dm, Dm,
                 0, 0, 0, 1, 1, 0, 0, 0, 1.0f, in_b + Dm, 0, 0, 0, 0);
    launch_tgemm(seltok, in_w + 2 * DD, vb, Bb * MAXR, Dm, Dm, Dm, Dm, Dm,
                 0, 0, 0, 1, 1, 0, 0, 0, 1.0f, in_b + 2 * Dm, 0, 0, 0, 0);
    // fusion scores
    launch_tgemm(qb, kb, fsc, Ss, MAXR, HDm, Dm, Dm, MAXR,
                 (long)Ss * Dm, (long)MAXR * Dm, (long)Hh * Ss * MAXR,
                 Bb * Hh, Hh, HDm, HDm, (long)Ss * MAXR,
                 0.08838834764831845f, 0, 0, 0, 0, 1);
    fsoftmax_kernel<<<Bb * Hh * Ss, 256>>>(fsc, keyvalid);
    // attnout = P @ V
    launch_tgemm(fsc, vb, attnout, Ss, HDm, MAXR, MAXR, Dm, Dm,
                 (long)Hh * Ss * MAXR, (long)MAXR * Dm, (long)Ss * Dm,
                 Bb * Hh, Hh, (long)Ss * MAXR, HDm, HDm,
                 1.0f, 0, 0, 0, 0, 0);
    // out projection
    launch_tgemm(attnout, out_w, fused, BS, Dm, Dm, Dm, Dm, Dm,
                 0, 0, 0, 1, 1, 0, 0, 0, 1.0f, out_b, 0, 0, 0, 0);
    finalize_kernel<<<BS, 256>>>(x, fused, fln_g, fln_b, anyvalid, out);
}

// round 11
// speedup vs baseline: 2.9397x; 1.0665x over previous
#include <cuda_runtime.h>
#include <math.h>
#include <float.h>
#include <stdint.h>

// ---------------- problem constants ----------------
#define Dm   1024
#define Bb   4
#define Ss   2048
#define Rr   3
#define Kk   256
#define MAXR 256
#define Hh   8
#define HDm  128
#define BS   (Bb*Ss)     // 8192
#define RBn  (Rr*Bb)     // 12
#define NHID 512         // DIM/2

// ---------------- scratch (device globals; no allocation) ----------------
__device__ float g_qf1[Rr*Bb*Ss*Dm];
__device__ float g_qf2[Rr*Bb*Ss*Dm];
__device__ float g_scores[RBn*Ss*Ss];
__device__ float g_w[RBn*Ss];
__device__ float g_pooled[RBn*Dm];
__device__ float g_pooledln[RBn*Dm];
__device__ float g_queries[RBn*Dm];
__device__ float g_qpart[RBn*NHID];
__device__ float g_hidden[RBn*Kk*NHID];
__device__ float g_rel[RBn*Kk];
__device__ int   g_selidx[Bb*MAXR];
__device__ float g_keyvalid[Bb*MAXR];
__device__ int   g_anyvalid[Bb];
__device__ float g_seltok[Bb*MAXR*Dm];
__device__ float g_q[BS*Dm];
__device__ float g_k[Bb*MAXR*Dm];
__device__ float g_v[Bb*MAXR*Dm];
__device__ float g_fsc[Bb*Hh*Ss*MAXR];
__device__ float g_attnout[BS*Dm];
__device__ float g_fused[BS*Dm];

__device__ __forceinline__ float gelu_f(float x) {
    return 0.5f * x * (1.0f + erff(x * 0.70710678118654752440f));
}

// pack two floats into bf16x2: 'a' -> lower half, 'b' -> upper half
__device__ __forceinline__ unsigned pk_bf16x2(float a, float b) {
    unsigned r;
    asm("cvt.rn.bf16x2.f32 %0, %1, %2;" : "=r"(r) : "f"(b), "f"(a));
    return r;
}
// pack two floats into f16x2: 'a' -> lower half, 'b' -> upper half
__device__ __forceinline__ unsigned pk_f16x2(float a, float b) {
    unsigned r;
    asm("cvt.rn.f16x2.f32 %0, %1, %2;" : "=r"(r) : "f"(b), "f"(a));
    return r;
}
__device__ __forceinline__ float lo16f(unsigned u) { return __uint_as_float(u << 16); }
__device__ __forceinline__ float hi16f(unsigned u) { return __uint_as_float(u & 0xFFFF0000u); }

__device__ __forceinline__ void mma_bf16(float* c,
    unsigned a0, unsigned a1, unsigned a2, unsigned a3,
    unsigned b0, unsigned b1)
{
    asm volatile(
        "mma.sync.aligned.m16n8k16.row.col.f32.bf16.bf16.f32 "
        "{%0,%1,%2,%3},{%4,%5,%6,%7},{%8,%9},{%0,%1,%2,%3};\n"
        : "+f"(c[0]), "+f"(c[1]), "+f"(c[2]), "+f"(c[3])
        : "r"(a0), "r"(a1), "r"(a2), "r"(a3), "r"(b0), "r"(b1));
}
__device__ __forceinline__ void mma_f16(float* c,
    unsigned a0, unsigned a1, unsigned a2, unsigned a3,
    unsigned b0, unsigned b1)
{
    asm volatile(
        "mma.sync.aligned.m16n8k16.row.col.f32.f16.f16.f32 "
        "{%0,%1,%2,%3},{%4,%5,%6,%7},{%8,%9},{%0,%1,%2,%3};\n"
        : "+f"(c[0]), "+f"(c[1]), "+f"(c[2]), "+f"(c[3])
        : "r"(a0), "r"(a1), "r"(a2), "r"(a3), "r"(b0), "r"(b1));
}

// ---------------- tensor-core GEMM (mma.sync path) ----------------
// C[m,n] = alpha * sum_k A[m,k] * B(k,n)  (+ bias)(+gelu)
// TRANSB=0: B row-major [K,N]; TRANSB=1: B row-major [N,K] -> A*B^T
// PREC=0: bf16x3 split (accurate); PREC=1: single-pass fp16
template<int TRANSB, int PREC>
__global__ void __launch_bounds__(256, 1)
tgemm_kernel(const float* __restrict__ A, const float* __restrict__ B,
             float* __restrict__ C,
             int M, int N, int Kd, int lda, int ldb, int ldc,
             long sA1, long sB1, long sC1, int Z2, long sA2, long sB2, long sC2,
             float alpha, const float* __restrict__ bias, long sbias1,
             int bias_mdiv, int act)
{
    __shared__ unsigned Ah[16][136];
    __shared__ unsigned Al[(PREC == 0) ? 16 : 1][136];
    __shared__ unsigned Bh[16][136];
    __shared__ unsigned Bl[(PREC == 0) ? 16 : 1][136];

    int z  = blockIdx.z;
    int z1 = z / Z2, z2 = z - z1 * Z2;
    A += z1 * sA1 + z2 * sA2;
    B += z1 * sB1 + z2 * sB2;
    C += z1 * sC1 + z2 * sC2;
    const float* bptr = bias ? bias + z1 * sbias1 : (const float*)0;

    int m0 = blockIdx.y * 128;
    int n0 = blockIdx.x * 128;
    int t = threadIdx.x, lane = t & 31, warp = t >> 5;
    int wm = (warp >> 2) * 64, wn = (warp & 3) * 32;
    int r0 = lane >> 2, c4 = lane & 3;

    float acc[4][4][4];
#pragma unroll
    for (int i = 0; i < 4; i++)
#pragma unroll
        for (int j = 0; j < 4; j++)
#pragma unroll
            for (int q = 0; q < 4; q++) acc[i][j][q] = 0.0f;

    int arow = t >> 3;
    int acol = (t & 7) * 4;
    int kpA  = (t & 7) * 2;
    int qrow = t >> 5;
    int n4   = (t & 31) * 4;

    float4 pa[4], pb[4];
    const int KT = Kd >> 5;

    {
        const float* Aptr = A + (long)m0 * lda;
#pragma unroll
        for (int p = 0; p < 4; p++)
            pa[p] = *(const float4*)(Aptr + (long)(arow + p * 32) * lda + acol);
        if (TRANSB == 0) {
            const float* Bptr = B + n0;
#pragma unroll
            for (int p = 0; p < 2; p++) {
                pb[2 * p]     = *(const float4*)(Bptr + (long)((qrow + p * 8) * 2)     * ldb + n4);
                pb[2 * p + 1] = *(const float4*)(Bptr + (long)((qrow + p * 8) * 2 + 1) * ldb + n4);
            }
        } else {
            const float* Bptr = B + (long)n0 * ldb;
#pragma unroll
            for (int p = 0; p < 4; p++)
                pb[p] = *(const float4*)(Bptr + (long)(arow + p * 32) * ldb + acol);
        }
    }

    for (int kt = 0; kt < KT; kt++) {
#pragma unroll
        for (int p = 0; p < 4; p++) {
            int row = arow + p * 32;
            if (PREC == 0) {
                unsigned h0 = pk_bf16x2(pa[p].x, pa[p].y);
                unsigned l0 = pk_bf16x2(pa[p].x - lo16f(h0), pa[p].y - hi16f(h0));
                unsigned h1 = pk_bf16x2(pa[p].z, pa[p].w);
                unsigned l1 = pk_bf16x2(pa[p].z - lo16f(h1), pa[p].w - hi16f(h1));
                Ah[kpA][row] = h0;  Al[kpA][row] = l0;
                Ah[kpA + 1][row] = h1;  Al[kpA + 1][row] = l1;
            } else {
                Ah[kpA][row]     = pk_f16x2(pa[p].x, pa[p].y);
                Ah[kpA + 1][row] = pk_f16x2(pa[p].z, pa[p].w);
            }
        }
        if (TRANSB == 0) {
#pragma unroll
            for (int p = 0; p < 2; p++) {
                int kp = qrow + p * 8;
                float4 ra = pb[2 * p], rb = pb[2 * p + 1];
                if (PREC == 0) {
                    uint4 H, L;
                    H.x = pk_bf16x2(ra.x, rb.x); L.x = pk_bf16x2(ra.x - lo16f(H.x), rb.x - hi16f(H.x));
                    H.y = pk_bf16x2(ra.y, rb.y); L.y = pk_bf16x2(ra.y - lo16f(H.y), rb.y - hi16f(H.y));
                    H.z = pk_bf16x2(ra.z, rb.z); L.z = pk_bf16x2(ra.z - lo16f(H.z), rb.z - hi16f(H.z));
                    H.w = pk_bf16x2(ra.w, rb.w); L.w = pk_bf16x2(ra.w - lo16f(H.w), rb.w - hi16f(H.w));
                    *(uint4*)&Bh[kp][n4] = H;
                    *(uint4*)&Bl[kp][n4] = L;
                } else {
                    uint4 H;
                    H.x = pk_f16x2(ra.x, rb.x);
                    H.y = pk_f16x2(ra.y, rb.y);
                    H.z = pk_f16x2(ra.z, rb.z);
                    H.w = pk_f16x2(ra.w, rb.w);
                    *(uint4*)&Bh[kp][n4] = H;
                }
            }
        } else {
#pragma unroll
            for (int p = 0; p < 4; p++) {
                int row = arow + p * 32;
                if (PREC == 0) {
                    unsigned h0 = pk_bf16x2(pb[p].x, pb[p].y);
                    unsigned l0 = pk_bf16x2(pb[p].x - lo16f(h0), pb[p].y - hi16f(h0));
                    unsigned h1 = pk_bf16x2(pb[p].z, pb[p].w);
                    unsigned l1 = pk_bf16x2(pb[p].z - lo16f(h1), pb[p].w - hi16f(h1));
                    Bh[kpA][row] = h0;  Bl[kpA][row] = l0;
                    Bh[kpA + 1][row] = h1;  Bl[kpA + 1][row] = l1;
                } else {
                    Bh[kpA][row]     = pk_f16x2(pb[p].x, pb[p].y);
                    Bh[kpA + 1][row] = pk_f16x2(pb[p].z, pb[p].w);
                }
            }
        }
        __syncthreads();

        if (kt + 1 < KT) {
            int k0 = (kt + 1) * 32;
            const float* Aptr = A + (long)m0 * lda + k0;
#pragma unroll
            for (int p = 0; p < 4; p++)
                pa[p] = *(const float4*)(Aptr + (long)(arow + p * 32) * lda + acol);
            if (TRANSB == 0) {
                const float* Bptr = B + (long)k0 * ldb + n0;
#pragma unroll
                for (int p = 0; p < 2; p++) {
                    pb[2 * p]     = *(const float4*)(Bptr + (long)((qrow + p * 8) * 2)     * ldb + n4);
                    pb[2 * p + 1] = *(const float4*)(Bptr + (long)((qrow + p * 8) * 2 + 1) * ldb + n4);
                }
            } else {
                const float* Bptr = B + (long)n0 * ldb + k0;
#pragma unroll
                for (int p = 0; p < 4; p++)
                    pb[p] = *(const float4*)(Bptr + (long)(arow + p * 32) * ldb + acol);
            }
        }

#pragma unroll
        for (int ks = 0; ks < 2; ks++) {
            int k8 = ks * 8;
            unsigned ah[4][4];
#pragma unroll
            for (int mt = 0; mt < 4; mt++) {
                int row = wm + mt * 16 + r0;
                ah[mt][0] = Ah[k8 + c4][row];
                ah[mt][1] = Ah[k8 + c4][row + 8];
                ah[mt][2] = Ah[k8 + 4 + c4][row];
                ah[mt][3] = Ah[k8 + 4 + c4][row + 8];
            }
            unsigned bh[4][2];
#pragma unroll
            for (int nt = 0; nt < 4; nt++) {
                int col = wn + nt * 8 + r0;
                bh[nt][0] = Bh[k8 + c4][col];
                bh[nt][1] = Bh[k8 + 4 + c4][col];
            }
            if (PREC == 0) {
                unsigned al[4][4], bl[4][2];
#pragma unroll
                for (int mt = 0; mt < 4; mt++) {
                    int row = wm + mt * 16 + r0;
                    al[mt][0] = Al[k8 + c4][row];
                    al[mt][1] = Al[k8 + c4][row + 8];
                    al[mt][2] = Al[k8 + 4 + c4][row];
                    al[mt][3] = Al[k8 + 4 + c4][row + 8];
                }
#pragma unroll
                for (int nt = 0; nt < 4; nt++) {
                    int col = wn + nt * 8 + r0;
                    bl[nt][0] = Bl[k8 + c4][col];
                    bl[nt][1] = Bl[k8 + 4 + c4][col];
                }
#pragma unroll
                for (int mt = 0; mt < 4; mt++)
#pragma unroll
                    for (int nt = 0; nt < 4; nt++) {
                        float* c = acc[mt][nt];
                        mma_bf16(c, al[mt][0], al[mt][1], al[mt][2], al[mt][3], bh[nt][0], bh[nt][1]);
                        mma_bf16(c, ah[mt][0], ah[mt][1], ah[mt][2], ah[mt][3], bl[nt][0], bl[nt][1]);
                        mma_bf16(c, ah[mt][0], ah[mt][1], ah[mt][2], ah[mt][3], bh[nt][0], bh[nt][1]);
                    }
            } else {
#pragma unroll
                for (int mt = 0; mt < 4; mt++)
#pragma unroll
                    for (int nt = 0; nt < 4; nt++)
                        mma_f16(acc[mt][nt], ah[mt][0], ah[mt][1], ah[mt][2], ah[mt][3],
                                bh[nt][0], bh[nt][1]);
            }
        }
        __syncthreads();
    }

#pragma unroll
    for (int mt = 0; mt < 4; mt++) {
#pragma unroll
        for (int nt = 0; nt < 4; nt++) {
            int row = m0 + wm + mt * 16 + r0;
            int col = n0 + wn + nt * 8 + c4 * 2;
            float v0 = acc[mt][nt][0] * alpha;
            float v1 = acc[mt][nt][1] * alpha;
            float v2 = acc[mt][nt][2] * alpha;
            float v3 = acc[mt][nt][3] * alpha;
            if (bptr) {
                long bi0 = (bias_mdiv ? (long)(row / bias_mdiv) * N : 0L);
                long bi2 = (bias_mdiv ? (long)((row + 8) / bias_mdiv) * N : 0L);
                v0 += bptr[bi0 + col];     v1 += bptr[bi0 + col + 1];
                v2 += bptr[bi2 + col];     v3 += bptr[bi2 + col + 1];
            }
            if (act == 1) { v0 = gelu_f(v0); v1 = gelu_f(v1); v2 = gelu_f(v2); v3 = gelu_f(v3); }
            *(float2*)(C + (long)row * ldc + col) = make_float2(v0, v1);
            *(float2*)(C + (long)(row + 8) * ldc + col) = make_float2(v2, v3);
        }
    }
}

static void launch_tgemm(const float* A, const float* B, float* C,
                         int M, int N, int Kd, int lda, int ldb, int ldc,
                         long sA1, long sB1, long sC1, int Z, int Z2,
                         long sA2, long sB2, long sC2,
                         float alpha, const float* bias, long sbias1,
                         int bias_mdiv, int act, int transB, int prec)
{
    dim3 grid(N / 128, M / 128, Z);
    if (transB) {
        if (prec)
            tgemm_kernel<1, 1><<<grid, 256>>>(A, B, C, M, N, Kd, lda, ldb, ldc,
                                              sA1, sB1, sC1, Z2, sA2, sB2, sC2,
                                              alpha, bias, sbias1, bias_mdiv, act);
        else
            tgemm_kernel<1, 0><<<grid, 256>>>(A, B, C, M, N, Kd, lda, ldb, ldc,
                                              sA1, sB1, sC1, Z2, sA2, sB2, sC2,
                                              alpha, bias, sbias1, bias_mdiv, act);
    } else {
        if (prec)
            tgemm_kernel<0, 1><<<grid, 256>>>(A, B, C, M, N, Kd, lda, ldb, ldc,
                                              sA1, sB1, sC1, Z2, sA2, sB2, sC2,
                                              alpha, bias, sbias1, bias_mdiv, act);
        else
            tgemm_kernel<0, 0><<<grid, 256>>>(A, B, C, M, N, Kd, lda, ldb, ldc,
                                              sA1, sB1, sC1, Z2, sA2, sB2, sC2,
                                              alpha, bias, sbias1, bias_mdiv, act);
    }
}

// ---------------- symmetric scores GEMM: S = alpha * A A^T (A: [2048,1024]) ----
__global__ void __launch_bounds__(256, 1)
sym_gemm_kernel(const float* __restrict__ Ain, float* __restrict__ Cout, float alpha)
{
    __shared__ unsigned Ah[16][136];
    __shared__ unsigned Al[16][136];
    __shared__ unsigned Bh[16][136];
    __shared__ unsigned Bl[16][136];

    const float* A = Ain + (long)blockIdx.z * Ss * Dm;
    float* C = Cout + (long)blockIdx.z * Ss * Ss;

    int by = 0, rem = blockIdx.x;
    while (rem >= 16 - by) { rem -= 16 - by; by++; }
    int bx = by + rem;

    int m0 = by * 128;
    int n0 = bx * 128;
    int t = threadIdx.x, lane = t & 31, warp = t >> 5;
    int wm = (warp >> 2) * 64, wn = (warp & 3) * 32;
    int r0 = lane >> 2, c4 = lane & 3;

    float acc[4][4][4];
#pragma unroll
    for (int i = 0; i < 4; i++)
#pragma unroll
        for (int j = 0; j < 4; j++)
#pragma unroll
            for (int q = 0; q < 4; q++) acc[i][j][q] = 0.0f;

    int arow = t >> 3;
    int acol = (t & 7) * 4;
    int kpA  = (t & 7) * 2;

    float4 pa[4], pb[4];
    const int KT = Dm >> 5;   // 32

    {
        const float* Aptr = A + (long)m0 * Dm;
        const float* Bptr = A + (long)n0 * Dm;
#pragma unroll
        for (int p = 0; p < 4; p++) {
            pa[p] = *(const float4*)(Aptr + (long)(arow + p * 32) * Dm + acol);
            pb[p] = *(const float4*)(Bptr + (long)(arow + p * 32) * Dm + acol);
        }
    }

    for (int kt = 0; kt < KT; kt++) {
#pragma unroll
        for (int p = 0; p < 4; p++) {
            int row = arow + p * 32;
            unsigned h0 = pk_bf16x2(pa[p].x, pa[p].y);
            unsigned l0 = pk_bf16x2(pa[p].x - lo16f(h0), pa[p].y - hi16f(h0));
            unsigned h1 = pk_bf16x2(pa[p].z, pa[p].w);
            unsigned l1 = pk_bf16x2(pa[p].z - lo16f(h1), pa[p].w - hi16f(h1));
            Ah[kpA][row] = h0;  Al[kpA][row] = l0;
            Ah[kpA + 1][row] = h1;  Al[kpA + 1][row] = l1;
            h0 = pk_bf16x2(pb[p].x, pb[p].y);
            l0 = pk_bf16x2(pb[p].x - lo16f(h0), pb[p].y - hi16f(h0));
            h1 = pk_bf16x2(pb[p].z, pb[p].w);
            l1 = pk_bf16x2(pb[p].z - lo16f(h1), pb[p].w - hi16f(h1));
            Bh[kpA][row] = h0;  Bl[kpA][row] = l0;
            Bh[kpA + 1][row] = h1;  Bl[kpA + 1][row] = l1;
        }
        __syncthreads();

        if (kt + 1 < KT) {
            int k0 = (kt + 1) * 32;
            const float* Aptr = A + (long)m0 * Dm + k0;
            const float* Bptr = A + (long)n0 * Dm + k0;
#pragma unroll
            for (int p = 0; p < 4; p++) {
                pa[p] = *(const float4*)(Aptr + (long)(arow + p * 32) * Dm + acol);
                pb[p] = *(const float4*)(Bptr + (long)(arow + p * 32) * Dm + acol);
            }
        }

#pragma unroll
        for (int ks = 0; ks < 2; ks++) {
            int k8 = ks * 8;
            unsigned ah[4][4], al[4][4];
#pragma unroll
            for (int mt = 0; mt < 4; mt++) {
                int row = wm + mt * 16 + r0;
                ah[mt][0] = Ah[k8 + c4][row];
                ah[mt][1] = Ah[k8 + c4][row + 8];
                ah[mt][2] = Ah[k8 + 4 + c4][row];
                ah[mt][3] = Ah[k8 + 4 + c4][row + 8];
                al[mt][0] = Al[k8 + c4][row];
                al[mt][1] = Al[k8 + c4][row + 8];
                al[mt][2] = Al[k8 + 4 + c4][row];
                al[mt][3] = Al[k8 + 4 + c4][row + 8];
            }
            unsigned bh[4][2], bl[4][2];
#pragma unroll
            for (int nt = 0; nt < 4; nt++) {
                int col = wn + nt * 8 + r0;
                bh[nt][0] = Bh[k8 + c4][col];
                bh[nt][1] = Bh[k8 + 4 + c4][col];
                bl[nt][0] = Bl[k8 + c4][col];
                bl[nt][1] = Bl[k8 + 4 + c4][col];
            }
#pragma unroll
            for (int mt = 0; mt < 4; mt++)
#pragma unroll
                for (int nt = 0; nt < 4; nt++) {
                    float* c = acc[mt][nt];
                    mma_bf16(c, al[mt][0], al[mt][1], al[mt][2], al[mt][3], bh[nt][0], bh[nt][1]);
                    mma_bf16(c, ah[mt][0], ah[mt][1], ah[mt][2], ah[mt][3], bl[nt][0], bl[nt][1]);
                    mma_bf16(c, ah[mt][0], ah[mt][1], ah[mt][2], ah[mt][3], bh[nt][0], bh[nt][1]);
                }
        }
        __syncthreads();
    }

    bool mirror = (bx != by);
#pragma unroll
    for (int mt = 0; mt < 4; mt++) {
#pragma unroll
        for (int nt = 0; nt < 4; nt++) {
            int row = m0 + wm + mt * 16 + r0;
            int col = n0 + wn + nt * 8 + c4 * 2;
            float v0 = acc[mt][nt][0] * alpha;
            float v1 = acc[mt][nt][1] * alpha;
            float v2 = acc[mt][nt][2] * alpha;
            float v3 = acc[mt][nt][3] * alpha;
            *(float2*)(C + (long)row * Ss + col) = make_float2(v0, v1);
            *(float2*)(C + (long)(row + 8) * Ss + col) = make_float2(v2, v3);
            if (mirror) {
                C[(long)col * Ss + row]           = v0;
                C[(long)(col + 1) * Ss + row]     = v1;
                C[(long)col * Ss + row + 8]       = v2;
                C[(long)(col + 1) * Ss + row + 8] = v3;
            }
        }
    }
}

// ---------------- shuffle-based block reductions (256 threads) ----------------
__device__ __forceinline__ float warpSum(float v) {
#pragma unroll
    for (int o = 16; o > 0; o >>= 1) v += __shfl_xor_sync(0xffffffffu, v, o);
    return v;
}
__device__ __forceinline__ float warpMax(float v) {
#pragma unroll
    for (int o = 16; o > 0; o >>= 1) v = fmaxf(v, __shfl_xor_sync(0xffffffffu, v, o));
    return v;
}
__device__ __forceinline__ float blockSum256(float v, float* sm8) {
    int w = threadIdx.x >> 5, l = threadIdx.x & 31;
    v = warpSum(v);
    if (l == 0) sm8[w] = v;
    __syncthreads();
    float x = (l < 8) ? sm8[l] : 0.0f;
    x = warpSum(x);
    __syncthreads();
    if (threadIdx.x == 0) sm8[0] = x;
    __syncthreads();
    float r = sm8[0];
    __syncthreads();
    return r;
}
__device__ __forceinline__ float blockMax256(float v, float* sm8) {
    int w = threadIdx.x >> 5, l = threadIdx.x & 31;
    v = warpMax(v);
    if (l == 0) sm8[w] = v;
    __syncthreads();
    float x = (l < 8) ? sm8[l] : -FLT_MAX;
    x = warpMax(x);
    __syncthreads();
    if (threadIdx.x == 0) sm8[0] = x;
    __syncthreads();
    float r = sm8[0];
    __syncthreads();
    return r;
}

__global__ void softmax2048_kernel(float* __restrict__ S)
{
    long row = blockIdx.x;
    float* p = S + row * 2048;
    __shared__ float red[8];
    int t = threadIdx.x;
    float e[8];
    float lmax = -FLT_MAX;
#pragma unroll
    for (int q = 0; q < 8; q++) { e[q] = p[t + 256 * q]; lmax = fmaxf(lmax, e[q]); }
    float mx = blockMax256(lmax, red);
    float lsum = 0.f;
#pragma unroll
    for (int q = 0; q < 8; q++) { e[q] = expf(e[q] - mx); lsum += e[q]; }
    float sum = blockSum256(lsum, red);
    float inv = 1.0f / sum;
#pragma unroll
    for (int q = 0; q < 8; q++) p[t + 256 * q] = e[q] * inv;
}

__global__ void colmean_kernel(const float* __restrict__ S, float* __restrict__ w)
{
    int rb = blockIdx.y;
    int tcol = blockIdx.x * 256 + threadIdx.x;
    const float* base = S + (long)rb * Ss * Ss + tcol;
    float acc = 0.f;
    for (int s = 0; s < Ss; s++) acc += base[(long)s * Ss];
    w[rb * Ss + tcol] = acc * (1.0f / (float)Ss);
}

__global__ void pooled_gemv_kernel(const float* __restrict__ qf2,
                                   const float* __restrict__ w,
                                   float* __restrict__ pooled)
{
    int rb = blockIdx.y;
    int d = blockIdx.x * 128 + threadIdx.x;
    const float* Q = qf2 + (long)rb * Ss * Dm + d;
    const float* wv = w + rb * Ss;
    float acc = 0.f;
    for (int tt = 0; tt < Ss; tt++) acc += wv[tt] * Q[(long)tt * Dm];
    pooled[rb * Dm + d] = acc;
}

__global__ void ln12_kernel(const float* __restrict__ pooled,
                            const float* __restrict__ gw, const float* __restrict__ bw,
                            float* __restrict__ out)
{
    int rb = blockIdx.x;
    int r = rb >> 2;
    int t = threadIdx.x;
    __shared__ float red[8];
    const float* p = pooled + rb * Dm;
    float v0 = p[t], v1 = p[t + 256], v2 = p[t + 512], v3 = p[t + 768];
    float mean = blockSum256(v0 + v1 + v2 + v3, red) * (1.0f / (float)Dm);
    float d0 = v0 - mean, d1 = v1 - mean, d2 = v2 - mean, d3 = v3 - mean;
    float var = blockSum256(d0 * d0 + d1 * d1 + d2 * d2 + d3 * d3, red) * (1.0f / (float)Dm);
    float rs = rsqrtf(var + 1e-5f);
    out[rb * Dm + t]       = d0 * rs * gw[r * Dm + t]       + bw[r * Dm + t];
    out[rb * Dm + t + 256] = d1 * rs * gw[r * Dm + t + 256] + bw[r * Dm + t + 256];
    out[rb * Dm + t + 512] = d2 * rs * gw[r * Dm + t + 512] + bw[r * Dm + t + 512];
    out[rb * Dm + t + 768] = d3 * rs * gw[r * Dm + t + 768] + bw[r * Dm + t + 768];
}

__global__ void queries_kernel(const float* __restrict__ pooledln,
                               const float* __restrict__ pool_w,
                               const float* __restrict__ pool_b,
                               float* __restrict__ queries)
{
    int rb = blockIdx.y;
    int r = rb >> 2;
    int e = blockIdx.x * 128 + threadIdx.x;
    __shared__ float sm[Dm];
    for (int i = threadIdx.x; i < Dm; i += 128) sm[i] = pooledln[rb * Dm + i];
    __syncthreads();
    const float* W = pool_w + (long)r * Dm * Dm;
    float acc = pool_b[r * Dm + e];
    for (int d = 0; d < Dm; d++) acc += sm[d] * W[(long)d * Dm + e];
    queries[rb * Dm + e] = acc;
}

__global__ void qpart_kernel(const float* __restrict__ queries,
                             const float* __restrict__ rel_w1,
                             const float* __restrict__ rel_b1,
                             float* __restrict__ qpart)
{
    int rb = blockIdx.y;
    int j = blockIdx.x * 128 + threadIdx.x;
    __shared__ float sm[Dm];
    for (int i = threadIdx.x; i < Dm; i += 128) sm[i] = queries[rb * Dm + i];
    __syncthreads();
    float acc = rel_b1[j];
    for (int d = 0; d < Dm; d++) acc += sm[d] * rel_w1[(long)(Dm + d) * NHID + j];
    qpart[rb * NHID + j] = acc;
}

__global__ void relscore_kernel(const float* __restrict__ hidden,
                                const float* __restrict__ w2,
                                const float* __restrict__ b2,
                                float* __restrict__ rel)
{
    int row = blockIdx.x * 8 + threadIdx.y;
    const float* h = hidden + (long)row * NHID;
    float a = 0.f;
    for (int i = threadIdx.x; i < NHID; i += 32) a += h[i] * w2[i];
#pragma unroll
    for (int off = 16; off > 0; off >>= 1) a += __shfl_down_sync(0xffffffffu, a, off);
    if (threadIdx.x == 0) {
        float s = a + b2[0];
        rel[row] = 1.0f / (1.0f + expf(-s));
    }
}

__global__ void topk_kernel(const float* __restrict__ rel,
                            int* __restrict__ selidx, float* __restrict__ keyvalid,
                            int* __restrict__ anyvalid)
{
    int b = blockIdx.x;
    int t = threadIdx.x;
    __shared__ float v[1024];
    __shared__ int   id[1024];
    float val = -FLT_MAX;
    if (t < Rr * Kk) {
        int r = t >> 8, kk = t & 255;
        float rv = rel[(r * Bb + b) * Kk + kk];
        val = (rv >= 0.5f) ? rv : -FLT_MAX;
    }
    v[t] = val; id[t] = t;
    __syncthreads();
    for (int k = 2; k <= 1024; k <<= 1) {
        for (int j = k >> 1; j > 0; j >>= 1) {
            int ixj = t ^ j;
            if (ixj > t) {
                float va = v[t], vb2 = v[ixj];
                int ia = id[t], ib = id[ixj];
                bool aFirst = (va > vb2) || (va == vb2 && ia < ib);
                bool dirDesc = ((t & k) == 0);
                if (dirDesc ? !aFirst : aFirst) {
                    v[t] = vb2; v[ixj] = va; id[t] = ib; id[ixj] = ia;
                }
            }
            __syncthreads();
        }
    }
    if (t < MAXR) {
        bool valid = (v[t] > -FLT_MAX);
        selidx[b * MAXR + t] = id[t];
        keyvalid[b * MAXR + t] = valid ? 1.0f : 0.0f;
        if (t == 0) anyvalid[b] = valid ? 1 : 0;
    }
}

__global__ void gather_kernel(const float* __restrict__ retrieved,
                              const int* __restrict__ selidx,
                              float* __restrict__ seltok)
{
    int b = blockIdx.y;
    int j = blockIdx.x;
    int t = threadIdx.x;
    int c = selidx[b * MAXR + j];
    int r = c >> 8, kk = c & 255;
    const float4* src = (const float4*)(retrieved + (((long)r * Bb + b) * Kk + kk) * Dm);
    float4* dst = (float4*)(seltok + ((long)b * MAXR + j) * Dm);
    dst[t] = src[t];
}

__global__ void fsoftmax_kernel(float* __restrict__ sc, const float* __restrict__ keyvalid)
{
    long row = blockIdx.x;
    int b = (int)(row / (Hh * Ss));
    float* p = sc + row * MAXR;
    int t = threadIdx.x;
    __shared__ float red[8];
    float val = p[t];
    if (keyvalid[b * MAXR + t] == 0.0f) val = -1e9f;
    float mx = blockMax256(val, red);
    float e = expf(val - mx);
    float sum = blockSum256(e, red);
    p[t] = e / sum;
}

__global__ void finalize_kernel(const float* __restrict__ x, const float* __restrict__ fused,
                                const float* __restrict__ gw, const float* __restrict__ bw,
                                const int* __restrict__ anyvalid, float* __restrict__ out)
{
    long row = blockIdx.x;
    int b = (int)(row >> 11);
    int t = threadIdx.x;
    __shared__ float red[8];
    const float* xr = x + row * Dm;
    const float* fr = fused + row * Dm;
    float v0 = xr[t] + fr[t];
    float v1 = xr[t + 256] + fr[t + 256];
    float v2 = xr[t + 512] + fr[t + 512];
    float v3 = xr[t + 768] + fr[t + 768];
    float mean = blockSum256(v0 + v1 + v2 + v3, red) * (1.0f / (float)Dm);
    float d0 = v0 - mean, d1 = v1 - mean, d2 = v2 - mean, d3 = v3 - mean;
    float var = blockSum256(d0 * d0 + d1 * d1 + d2 * d2 + d3 * d3, red) * (1.0f / (float)Dm);
    float rs = rsqrtf(var + 1e-5f);
    int av = anyvalid[b];
    float* o = out + row * Dm;
    o[t]       = av ? (d0 * rs * gw[t]       + bw[t])       : xr[t];
    o[t + 256] = av ? (d1 * rs * gw[t + 256] + bw[t + 256]) : xr[t + 256];
    o[t + 512] = av ? (d2 * rs * gw[t + 512] + bw[t + 512]) : xr[t + 512];
    o[t + 768] = av ? (d3 * rs * gw[t + 768] + bw[t + 768]) : xr[t + 768];
}

// ---------------- host orchestration ----------------
template <typename T>
static float* sym(T& s) { void* p = 0; cudaGetSymbolAddress(&p, s); return (float*)p; }
template <typename T>
static int* symi(T& s) { void* p = 0; cudaGetSymbolAddress(&p, s); return (int*)p; }

extern "C" void kernel_launch(void* const* d_in, const int* in_sizes, int n_in,
                              void* d_out, int out_size)
{
    const float* x       = (const float*)d_in[0];
    const float* retr    = (const float*)d_in[1];
    const float* qg_w1   = (const float*)d_in[2];
    const float* qg_b1   = (const float*)d_in[3];
    const float* qg_w2   = (const float*)d_in[4];
    const float* qg_b2   = (const float*)d_in[5];
    const float* pln_g   = (const float*)d_in[6];
    const float* pln_b   = (const float*)d_in[7];
    const float* pool_w  = (const float*)d_in[8];
    const float* pool_b  = (const float*)d_in[9];
    const float* rel_w1  = (const float*)d_in[10];
    const float* rel_b1  = (const float*)d_in[11];
    const float* rel_w2  = (const float*)d_in[12];
    const float* rel_b2  = (const float*)d_in[13];
    const float* in_w    = (const float*)d_in[14];
    const float* in_b    = (const float*)d_in[15];
    const float* out_w   = (const float*)d_in[16];
    const float* out_b   = (const float*)d_in[17];
    const float* fln_g   = (const float*)d_in[18];
    const float* fln_b   = (const float*)d_in[19];
    float* out = (float*)d_out;

    float* qf1    = sym(g_qf1);
    float* qf2    = sym(g_qf2);
    float* scores = sym(g_scores);
    float* wmean  = sym(g_w);
    float* pooled = sym(g_pooled);
    float* pooledln = sym(g_pooledln);
    float* queries = sym(g_queries);
    float* qpart  = sym(g_qpart);
    float* hidden = sym(g_hidden);
    float* rel    = sym(g_rel);
    int*   selidx = symi(g_selidx);
    float* keyvalid = sym(g_keyvalid);
    int*   anyvalid = symi(g_anyvalid);
    float* seltok = sym(g_seltok);
    float* qb     = sym(g_q);
    float* kb     = sym(g_k);
    float* vb     = sym(g_v);
    float* fsc    = sym(g_fsc);
    float* attnout = sym(g_attnout);
    float* fused  = sym(g_fused);

    const long DD = (long)Dm * Dm;

    // ---- query-gen / relevance path: bf16x3 (threshold-sensitive) ----
    launch_tgemm(x, qg_w1, qf1, BS, Dm, Dm, Dm, Dm, Dm,
                 0, DD, (long)BS * Dm, Rr, 1, 0, 0, 0,
                 1.0f, qg_b1, Dm, 0, 1, 0, 0);
    launch_tgemm(qf1, qg_w2, qf2, BS, Dm, Dm, Dm, Dm, Dm,
                 (long)BS * Dm, DD, (long)BS * Dm, Rr, 1, 0, 0, 0,
                 1.0f, qg_b2, Dm, 0, 0, 0, 0);
    {
        dim3 g(136, 1, RBn);
        sym_gemm_kernel<<<g, 256>>>(qf2, scores, 0.03125f);
    }
    softmax2048_kernel<<<RBn * Ss, 256>>>(scores);
    { dim3 g(Ss / 256, RBn); colmean_kernel<<<g, 256>>>(scores, wmean); }
    { dim3 g(Dm / 128, RBn); pooled_gemv_kernel<<<g, 128>>>(qf2, wmean, pooled); }
    ln12_kernel<<<RBn, 256>>>(pooled, pln_g, pln_b, pooledln);
    { dim3 g(Dm / 128, RBn); queries_kernel<<<g, 128>>>(pooledln, pool_w, pool_b, queries); }
    { dim3 g(NHID / 128, RBn); qpart_kernel<<<g, 128>>>(queries, rel_w1, rel_b1, qpart); }
    launch_tgemm(retr, rel_w1, hidden, RBn * Kk, NHID, Dm, Dm, NHID, NHID,
                 0, 0, 0, 1, 1, 0, 0, 0,
                 1.0f, qpart, 0, Kk, 1, 0, 0);
    { dim3 blk(32, 8); relscore_kernel<<<RBn * Kk / 8, blk>>>(hidden, rel_w2, rel_b2, rel); }
    topk_kernel<<<Bb, 1024>>>(rel, selidx, keyvalid, anyvalid);
    { dim3 g(MAXR, Bb); gather_kernel<<<g, 256>>>(retr, selidx, seltok); }

    // ---- fusion path: single-pass fp16 (smooth to output) ----
    launch_tgemm(x, in_w, qb, BS, Dm, Dm, Dm, Dm, Dm,
                 0, 0, 0, 1, 1, 0, 0, 0, 1.0f, in_b, 0, 0, 0, 0, 1);
    launch_tgemm(seltok, in_w + DD, kb, Bb * MAXR, Dm, Dm, Dm, Dm, Dm,
                 0, 0, 0, 1, 1, 0, 0, 0, 1.0f, in_b + Dm, 0, 0, 0, 0, 1);
    launch_tgemm(seltok, in_w + 2 * DD, vb, Bb * MAXR, Dm, Dm, Dm, Dm, Dm,
                 0, 0, 0, 1, 1, 0, 0, 0, 1.0f, in_b + 2 * Dm, 0, 0, 0, 0, 1);
    launch_tgemm(qb, kb, fsc, Ss, MAXR, HDm, Dm, Dm, MAXR,
                 (long)Ss * Dm, (long)MAXR * Dm, (long)Hh * Ss * MAXR,
                 Bb * Hh, Hh, HDm, HDm, (long)Ss * MAXR,
                 0.08838834764831845f, 0, 0, 0, 0, 1, 1);
    fsoftmax_kernel<<<Bb * Hh * Ss, 256>>>(fsc, keyvalid);
    launch_tgemm(fsc, vb, attnout, Ss, HDm, MAXR, MAXR, Dm, Dm,
                 (long)Hh * Ss * MAXR, (long)MAXR * Dm, (long)Ss * Dm,
                 Bb * Hh, Hh, (long)Ss * MAXR, HDm, HDm,
                 1.0f, 0, 0, 0, 0, 0, 1);
    launch_tgemm(attnout, out_w, fused, BS, Dm, Dm, Dm, Dm, Dm,
                 0, 0, 0, 1, 1, 0, 0, 0, 1.0f, out_b, 0, 0, 0, 0, 1);
    finalize_kernel<<<BS, 256>>>(x, fused, fln_g, fln_b, anyvalid, out);
}

// round 13
// speedup vs baseline: 2.9864x; 1.0159x over previous
#include <cuda_runtime.h>
#include <math.h>
#include <float.h>
#include <stdint.h>

// ---------------- problem constants ----------------
#define Dm   1024
#define Bb   4
#define Ss   2048
#define Rr   3
#define Kk   256
#define MAXR 256
#define Hh   8
#define HDm  128
#define BS   (Bb*Ss)     // 8192
#define RBn  (Rr*Bb)     // 12
#define NHID 512         // DIM/2

// ---------------- scratch (device globals; no allocation) ----------------
__device__ float g_qf1[Rr*Bb*Ss*Dm];
__device__ float g_qf2[Rr*Bb*Ss*Dm];
__device__ float g_scores[RBn*Ss*Ss];
__device__ float g_w[RBn*Ss];
__device__ float g_pooled[RBn*Dm];
__device__ float g_pooledln[RBn*Dm];
__device__ float g_queries[RBn*Dm];
__device__ float g_qpart[RBn*NHID];
__device__ float g_hidden[RBn*Kk*NHID];
__device__ float g_rel[RBn*Kk];
__device__ int   g_selidx[Bb*MAXR];
__device__ float g_keyvalid[Bb*MAXR];
__device__ int   g_anyvalid[Bb];
__device__ float g_seltok[Bb*MAXR*Dm];
__device__ float g_q[BS*Dm];
__device__ float g_k[Bb*MAXR*Dm];
__device__ float g_v[Bb*MAXR*Dm];
__device__ float g_fsc[Bb*Hh*Ss*MAXR];
__device__ float g_attnout[BS*Dm];
__device__ float g_fused[BS*Dm];

__device__ __forceinline__ float gelu_f(float x) {
    return 0.5f * x * (1.0f + erff(x * 0.70710678118654752440f));
}

__device__ __forceinline__ unsigned pk_bf16x2(float a, float b) {
    unsigned r;
    asm("cvt.rn.bf16x2.f32 %0, %1, %2;" : "=r"(r) : "f"(b), "f"(a));
    return r;
}
__device__ __forceinline__ unsigned pk_f16x2(float a, float b) {
    unsigned r;
    asm("cvt.rn.f16x2.f32 %0, %1, %2;" : "=r"(r) : "f"(b), "f"(a));
    return r;
}
__device__ __forceinline__ float lo16f(unsigned u) { return __uint_as_float(u << 16); }
__device__ __forceinline__ float hi16f(unsigned u) { return __uint_as_float(u & 0xFFFF0000u); }

__device__ __forceinline__ void mma_bf16(float* c,
    unsigned a0, unsigned a1, unsigned a2, unsigned a3,
    unsigned b0, unsigned b1)
{
    asm volatile(
        "mma.sync.aligned.m16n8k16.row.col.f32.bf16.bf16.f32 "
        "{%0,%1,%2,%3},{%4,%5,%6,%7},{%8,%9},{%0,%1,%2,%3};\n"
        : "+f"(c[0]), "+f"(c[1]), "+f"(c[2]), "+f"(c[3])
        : "r"(a0), "r"(a1), "r"(a2), "r"(a3), "r"(b0), "r"(b1));
}
__device__ __forceinline__ void mma_f16(float* c,
    unsigned a0, unsigned a1, unsigned a2, unsigned a3,
    unsigned b0, unsigned b1)
{
    asm volatile(
        "mma.sync.aligned.m16n8k16.row.col.f32.f16.f16.f32 "
        "{%0,%1,%2,%3},{%4,%5,%6,%7},{%8,%9},{%0,%1,%2,%3};\n"
        : "+f"(c[0]), "+f"(c[1]), "+f"(c[2]), "+f"(c[3])
        : "r"(a0), "r"(a1), "r"(a2), "r"(a3), "r"(b0), "r"(b1));
}

#define PLW 2176   // 16*136 words per plane

// ---------------- tensor-core GEMM, double-buffered smem pipeline ----------
// C[m,n] = alpha * sum_k A[m,k] * B(k,n)  (+ bias)(+gelu)
// TRANSB=0: B row-major [K,N]; TRANSB=1: B row-major [N,K] -> A*B^T
// PREC=0: bf16x3 split; PREC=1: single-pass fp16
// SMAX=1 (requires TRANSB=0, PREC=1, Kd==256): fuse masked softmax over A rows
template<int TRANSB, int PREC, int SMAX>
__global__ void __launch_bounds__(256, 1)
tgemm_kernel(const float* __restrict__ A, const float* __restrict__ B,
             float* __restrict__ C,
             int M, int N, int Kd, int lda, int ldb, int ldc,
             long sA1, long sB1, long sC1, int Z2, long sA2, long sB2, long sC2,
             float alpha, const float* __restrict__ bias, long sbias1,
             int bias_mdiv, int act, const float* __restrict__ kvmask)
{
    extern __shared__ __align__(16) unsigned dsm[];
    const int NPL  = (PREC == 0) ? 4 : 2;
    const int BUFW = NPL * PLW;

    __shared__ float s_kv[256];
    __shared__ float s_mx[128];
    __shared__ float s_iv[128];

    int z  = blockIdx.z;
    int z1 = z / Z2, z2 = z - z1 * Z2;
    A += z1 * sA1 + z2 * sA2;
    B += z1 * sB1 + z2 * sB2;
    C += z1 * sC1 + z2 * sC2;
    const float* bptr = bias ? bias + z1 * sbias1 : (const float*)0;

    int m0 = blockIdx.y * 128;
    int n0 = blockIdx.x * 128;
    int t = threadIdx.x, lane = t & 31, warp = t >> 5;
    int wm = (warp >> 2) * 64, wn = (warp & 3) * 32;
    int r0 = lane >> 2, c4 = lane & 3;

    float acc[4][4][4];
#pragma unroll
    for (int i = 0; i < 4; i++)
#pragma unroll
        for (int j = 0; j < 4; j++)
#pragma unroll
            for (int q = 0; q < 4; q++) acc[i][j][q] = 0.0f;

    int arow = t >> 3;
    int acol = (t & 7) * 4;
    int kpA  = (t & 7) * 2;
    int qrow = t >> 5;
    int n4   = (t & 31) * 4;

    // ---- fused masked-softmax stats over A rows (attnout only) ----
    if (SMAX) {
        s_kv[t & 255] = kvmask[(long)z1 * MAXR + (t & 255)];
        __syncthreads();
        int row = t >> 1, half = t & 1;
        const float* Ar = A + (long)(m0 + row) * lda + half * 128;
        float mxl = -FLT_MAX;
#pragma unroll 8
        for (int i = 0; i < 32; i++) {
            float4 v = *(const float4*)(Ar + i * 4);
            int cb = half * 128 + i * 4;
            if (s_kv[cb + 0] != 0.f) mxl = fmaxf(mxl, v.x);
            if (s_kv[cb + 1] != 0.f) mxl = fmaxf(mxl, v.y);
            if (s_kv[cb + 2] != 0.f) mxl = fmaxf(mxl, v.z);
            if (s_kv[cb + 3] != 0.f) mxl = fmaxf(mxl, v.w);
        }
        mxl = fmaxf(mxl, __shfl_xor_sync(0xffffffffu, mxl, 1));
        float sl = 0.f;
#pragma unroll 8
        for (int i = 0; i < 32; i++) {
            float4 v = *(const float4*)(Ar + i * 4);
            int cb = half * 128 + i * 4;
            if (s_kv[cb + 0] != 0.f) sl += expf(v.x - mxl);
            if (s_kv[cb + 1] != 0.f) sl += expf(v.y - mxl);
            if (s_kv[cb + 2] != 0.f) sl += expf(v.z - mxl);
            if (s_kv[cb + 3] != 0.f) sl += expf(v.w - mxl);
        }
        sl += __shfl_xor_sync(0xffffffffu, sl, 1);
        if (half == 0) { s_mx[row] = mxl; s_iv[row] = (sl > 0.f) ? 1.0f / sl : 0.f; }
        __syncthreads();
    }

    float4 pa[4], pb[4];
    const int KT = Kd >> 5;

    // prologue: LDG tile 0 into registers
    {
        const float* Aptr = A + (long)m0 * lda;
#pragma unroll
        for (int p = 0; p < 4; p++)
            pa[p] = *(const float4*)(Aptr + (long)(arow + p * 32) * lda + acol);
        if (TRANSB == 0) {
            const float* Bptr = B + n0;
#pragma unroll
            for (int p = 0; p < 2; p++) {
                pb[2 * p]     = *(const float4*)(Bptr + (long)((qrow + p * 8) * 2)     * ldb + n4);
                pb[2 * p + 1] = *(const float4*)(Bptr + (long)((qrow + p * 8) * 2 + 1) * ldb + n4);
            }
        } else {
            const float* Bptr = B + (long)n0 * ldb;
#pragma unroll
            for (int p = 0; p < 4; p++)
                pb[p] = *(const float4*)(Bptr + (long)(arow + p * 32) * ldb + acol);
        }
    }

    for (int kt = 0; kt < KT; kt++) {
        int sbuf = kt & 1;
        unsigned* AhP = dsm + sbuf * BUFW;
        unsigned* AlP = AhP + PLW;
        unsigned* BhP = AhP + ((PREC == 0) ? 2 : 1) * PLW;
        unsigned* BlP = BhP + PLW;
        int k0s = kt * 32;

        // ---- stage tile kt (regs -> smem buffer sbuf) ----
#pragma unroll
        for (int p = 0; p < 4; p++) {
            int row = arow + p * 32;
            float4 va = pa[p];
            if (SMAX) {
                float mxv = s_mx[row], ivv = s_iv[row];
                int c = k0s + acol;
                va.x = (s_kv[c + 0] != 0.f) ? expf(va.x - mxv) * ivv : 0.f;
                va.y = (s_kv[c + 1] != 0.f) ? expf(va.y - mxv) * ivv : 0.f;
                va.z = (s_kv[c + 2] != 0.f) ? expf(va.z - mxv) * ivv : 0.f;
                va.w = (s_kv[c + 3] != 0.f) ? expf(va.w - mxv) * ivv : 0.f;
            }
            if (PREC == 0) {
                unsigned h0 = pk_bf16x2(va.x, va.y);
                unsigned l0 = pk_bf16x2(va.x - lo16f(h0), va.y - hi16f(h0));
                unsigned h1 = pk_bf16x2(va.z, va.w);
                unsigned l1 = pk_bf16x2(va.z - lo16f(h1), va.w - hi16f(h1));
                AhP[kpA * 136 + row] = h0;       AlP[kpA * 136 + row] = l0;
                AhP[(kpA + 1) * 136 + row] = h1; AlP[(kpA + 1) * 136 + row] = l1;
            } else {
                AhP[kpA * 136 + row]       = pk_f16x2(va.x, va.y);
                AhP[(kpA + 1) * 136 + row] = pk_f16x2(va.z, va.w);
            }
        }
        if (TRANSB == 0) {
#pragma unroll
            for (int p = 0; p < 2; p++) {
                int kp = qrow + p * 8;
                float4 ra = pb[2 * p], rb = pb[2 * p + 1];
                if (PREC == 0) {
                    uint4 H, L;
                    H.x = pk_bf16x2(ra.x, rb.x); L.x = pk_bf16x2(ra.x - lo16f(H.x), rb.x - hi16f(H.x));
                    H.y = pk_bf16x2(ra.y, rb.y); L.y = pk_bf16x2(ra.y - lo16f(H.y), rb.y - hi16f(H.y));
                    H.z = pk_bf16x2(ra.z, rb.z); L.z = pk_bf16x2(ra.z - lo16f(H.z), rb.z - hi16f(H.z));
                    H.w = pk_bf16x2(ra.w, rb.w); L.w = pk_bf16x2(ra.w - lo16f(H.w), rb.w - hi16f(H.w));
                    *(uint4*)&BhP[kp * 136 + n4] = H;
                    *(uint4*)&BlP[kp * 136 + n4] = L;
                } else {
                    uint4 H;
                    H.x = pk_f16x2(ra.x, rb.x);
                    H.y = pk_f16x2(ra.y, rb.y);
                    H.z = pk_f16x2(ra.z, rb.z);
                    H.w = pk_f16x2(ra.w, rb.w);
                    *(uint4*)&BhP[kp * 136 + n4] = H;
                }
            }
        } else {
#pragma unroll
            for (int p = 0; p < 4; p++) {
                int row = arow + p * 32;
                if (PREC == 0) {
                    unsigned h0 = pk_bf16x2(pb[p].x, pb[p].y);
                    unsigned l0 = pk_bf16x2(pb[p].x - lo16f(h0), pb[p].y - hi16f(h0));
                    unsigned h1 = pk_bf16x2(pb[p].z, pb[p].w);
                    unsigned l1 = pk_bf16x2(pb[p].z - lo16f(h1), pb[p].w - hi16f(h1));
                    BhP[kpA * 136 + row] = h0;       BlP[kpA * 136 + row] = l0;
                    BhP[(kpA + 1) * 136 + row] = h1; BlP[(kpA + 1) * 136 + row] = l1;
                } else {
                    BhP[kpA * 136 + row]       = pk_f16x2(pb[p].x, pb[p].y);
                    BhP[(kpA + 1) * 136 + row] = pk_f16x2(pb[p].z, pb[p].w);
                }
            }
        }
        __syncthreads();

        // ---- prefetch tile kt+1 into registers (overlaps compute) ----
        if (kt + 1 < KT) {
            int k0 = (kt + 1) * 32;
            const float* Aptr = A + (long)m0 * lda + k0;
#pragma unroll
            for (int p = 0; p < 4; p++)
                pa[p] = *(const float4*)(Aptr + (long)(arow + p * 32) * lda + acol);
            if (TRANSB == 0) {
                const float* Bptr = B + (long)k0 * ldb + n0;
#pragma unroll
                for (int p = 0; p < 2; p++) {
                    pb[2 * p]     = *(const float4*)(Bptr + (long)((qrow + p * 8) * 2)     * ldb + n4);
                    pb[2 * p + 1] = *(const float4*)(Bptr + (long)((qrow + p * 8) * 2 + 1) * ldb + n4);
                }
            } else {
                const float* Bptr = B + (long)n0 * ldb + k0;
#pragma unroll
                for (int p = 0; p < 4; p++)
                    pb[p] = *(const float4*)(Bptr + (long)(arow + p * 32) * ldb + acol);
            }
        }

        // ---- compute tile kt from buffer sbuf ----
#pragma unroll
        for (int ks = 0; ks < 2; ks++) {
            int k8 = ks * 8;
            unsigned ah[4][4];
#pragma unroll
            for (int mt = 0; mt < 4; mt++) {
                int row = wm + mt * 16 + r0;
                ah[mt][0] = AhP[(k8 + c4) * 136 + row];
                ah[mt][1] = AhP[(k8 + c4) * 136 + row + 8];
                ah[mt][2] = AhP[(k8 + 4 + c4) * 136 + row];
                ah[mt][3] = AhP[(k8 + 4 + c4) * 136 + row + 8];
            }
            unsigned bh[4][2];
#pragma unroll
            for (int nt = 0; nt < 4; nt++) {
                int col = wn + nt * 8 + r0;
                bh[nt][0] = BhP[(k8 + c4) * 136 + col];
                bh[nt][1] = BhP[(k8 + 4 + c4) * 136 + col];
            }
            if (PREC == 0) {
                unsigned al[4][4], bl[4][2];
#pragma unroll
                for (int mt = 0; mt < 4; mt++) {
                    int row = wm + mt * 16 + r0;
                    al[mt][0] = AlP[(k8 + c4) * 136 + row];
                    al[mt][1] = AlP[(k8 + c4) * 136 + row + 8];
                    al[mt][2] = AlP[(k8 + 4 + c4) * 136 + row];
                    al[mt][3] = AlP[(k8 + 4 + c4) * 136 + row + 8];
                }
#pragma unroll
                for (int nt = 0; nt < 4; nt++) {
                    int col = wn + nt * 8 + r0;
                    bl[nt][0] = BlP[(k8 + c4) * 136 + col];
                    bl[nt][1] = BlP[(k8 + 4 + c4) * 136 + col];
                }
#pragma unroll
                for (int mt = 0; mt < 4; mt++)
#pragma unroll
                    for (int nt = 0; nt < 4; nt++) {
                        float* c = acc[mt][nt];
                        mma_bf16(c, al[mt][0], al[mt][1], al[mt][2], al[mt][3], bh[nt][0], bh[nt][1]);
                        mma_bf16(c, ah[mt][0], ah[mt][1], ah[mt][2], ah[mt][3], bl[nt][0], bl[nt][1]);
                        mma_bf16(c, ah[mt][0], ah[mt][1], ah[mt][2], ah[mt][3], bh[nt][0], bh[nt][1]);
                    }
            } else {
#pragma unroll
                for (int mt = 0; mt < 4; mt++)
#pragma unroll
                    for (int nt = 0; nt < 4; nt++)
                        mma_f16(acc[mt][nt], ah[mt][0], ah[mt][1], ah[mt][2], ah[mt][3],
                                bh[nt][0], bh[nt][1]);
            }
        }
    }

#pragma unroll
    for (int mt = 0; mt < 4; mt++) {
#pragma unroll
        for (int nt = 0; nt < 4; nt++) {
            int row = m0 + wm + mt * 16 + r0;
            int col = n0 + wn + nt * 8 + c4 * 2;
            float v0 = acc[mt][nt][0] * alpha;
            float v1 = acc[mt][nt][1] * alpha;
            float v2 = acc[mt][nt][2] * alpha;
            float v3 = acc[mt][nt][3] * alpha;
            if (bptr) {
                long bi0 = (bias_mdiv ? (long)(row / bias_mdiv) * N : 0L);
                long bi2 = (bias_mdiv ? (long)((row + 8) / bias_mdiv) * N : 0L);
                v0 += bptr[bi0 + col];     v1 += bptr[bi0 + col + 1];
                v2 += bptr[bi2 + col];     v3 += bptr[bi2 + col + 1];
            }
            if (act == 1) { v0 = gelu_f(v0); v1 = gelu_f(v1); v2 = gelu_f(v2); v3 = gelu_f(v3); }
            *(float2*)(C + (long)row * ldc + col) = make_float2(v0, v1);
            *(float2*)(C + (long)(row + 8) * ldc + col) = make_float2(v2, v3);
        }
    }
}

static void launch_tgemm(const float* A, const float* B, float* C,
                         int M, int N, int Kd, int lda, int ldb, int ldc,
                         long sA1, long sB1, long sC1, int Z, int Z2,
                         long sA2, long sB2, long sC2,
                         float alpha, const float* bias, long sbias1,
                         int bias_mdiv, int act, int transB, int prec,
                         const float* kvmask = 0, int smax = 0)
{
    dim3 grid(N / 128, M / 128, Z);
    size_t shm0 = 2 * 4 * PLW * 4;   // 69632
    size_t shm1 = 2 * 2 * PLW * 4;   // 34816
    if (smax) {
        cudaFuncSetAttribute(tgemm_kernel<0, 1, 1>, cudaFuncAttributeMaxDynamicSharedMemorySize, (int)shm1);
        tgemm_kernel<0, 1, 1><<<grid, 256, shm1>>>(A, B, C, M, N, Kd, lda, ldb, ldc,
                                                   sA1, sB1, sC1, Z2, sA2, sB2, sC2,
                                                   alpha, bias, sbias1, bias_mdiv, act, kvmask);
    } else if (transB) {
        if (prec) {
            cudaFuncSetAttribute(tgemm_kernel<1, 1, 0>, cudaFuncAttributeMaxDynamicSharedMemorySize, (int)shm1);
            tgemm_kernel<1, 1, 0><<<grid, 256, shm1>>>(A, B, C, M, N, Kd, lda, ldb, ldc,
                                                       sA1, sB1, sC1, Z2, sA2, sB2, sC2,
                                                       alpha, bias, sbias1, bias_mdiv, act, 0);
        } else {
            cudaFuncSetAttribute(tgemm_kernel<1, 0, 0>, cudaFuncAttributeMaxDynamicSharedMemorySize, (int)shm0);
            tgemm_kernel<1, 0, 0><<<grid, 256, shm0>>>(A, B, C, M, N, Kd, lda, ldb, ldc,
                                                       sA1, sB1, sC1, Z2, sA2, sB2, sC2,
                                                       alpha, bias, sbias1, bias_mdiv, act, 0);
        }
    } else {
        if (prec) {
            cudaFuncSetAttribute(tgemm_kernel<0, 1, 0>, cudaFuncAttributeMaxDynamicSharedMemorySize, (int)shm1);
            tgemm_kernel<0, 1, 0><<<grid, 256, shm1>>>(A, B, C, M, N, Kd, lda, ldb, ldc,
                                                       sA1, sB1, sC1, Z2, sA2, sB2, sC2,
                                                       alpha, bias, sbias1, bias_mdiv, act, 0);
        } else {
            cudaFuncSetAttribute(tgemm_kernel<0, 0, 0>, cudaFuncAttributeMaxDynamicSharedMemorySize, (int)shm0);
            tgemm_kernel<0, 0, 0><<<grid, 256, shm0>>>(A, B, C, M, N, Kd, lda, ldb, ldc,
                                                       sA1, sB1, sC1, Z2, sA2, sB2, sC2,
                                                       alpha, bias, sbias1, bias_mdiv, act, 0);
        }
    }
}

// ---------------- symmetric scores GEMM: S = alpha * A A^T, double-buffered --
__global__ void __launch_bounds__(256, 1)
sym_gemm_kernel(const float* __restrict__ Ain, float* __restrict__ Cout, float alpha)
{
    extern __shared__ __align__(16) unsigned dsm[];
    const int BUFW = 4 * PLW;

    const float* A = Ain + (long)blockIdx.z * Ss * Dm;
    float* C = Cout + (long)blockIdx.z * Ss * Ss;

    int by = 0, rem = blockIdx.x;
    while (rem >= 16 - by) { rem -= 16 - by; by++; }
    int bx = by + rem;

    int m0 = by * 128;
    int n0 = bx * 128;
    int t = threadIdx.x, lane = t & 31, warp = t >> 5;
    int wm = (warp >> 2) * 64, wn = (warp & 3) * 32;
    int r0 = lane >> 2, c4 = lane & 3;

    float acc[4][4][4];
#pragma unroll
    for (int i = 0; i < 4; i++)
#pragma unroll
        for (int j = 0; j < 4; j++)
#pragma unroll
            for (int q = 0; q < 4; q++) acc[i][j][q] = 0.0f;

    int arow = t >> 3;
    int acol = (t & 7) * 4;
    int kpA  = (t & 7) * 2;

    float4 pa[4], pb[4];
    const int KT = Dm >> 5;   // 32

    {
        const float* Aptr = A + (long)m0 * Dm;
        const float* Bptr = A + (long)n0 * Dm;
#pragma unroll
        for (int p = 0; p < 4; p++) {
            pa[p] = *(const float4*)(Aptr + (long)(arow + p * 32) * Dm + acol);
            pb[p] = *(const float4*)(Bptr + (long)(arow + p * 32) * Dm + acol);
        }
    }

    for (int kt = 0; kt < KT; kt++) {
        int sbuf = kt & 1;
        unsigned* AhP = dsm + sbuf * BUFW;
        unsigned* AlP = AhP + PLW;
        unsigned* BhP = AhP + 2 * PLW;
        unsigned* BlP = BhP + PLW;

#pragma unroll
        for (int p = 0; p < 4; p++) {
            int row = arow + p * 32;
            unsigned h0 = pk_bf16x2(pa[p].x, pa[p].y);
            unsigned l0 = pk_bf16x2(pa[p].x - lo16f(h0), pa[p].y - hi16f(h0));
            unsigned h1 = pk_bf16x2(pa[p].z, pa[p].w);
            unsigned l1 = pk_bf16x2(pa[p].z - lo16f(h1), pa[p].w - hi16f(h1));
            AhP[kpA * 136 + row] = h0;       AlP[kpA * 136 + row] = l0;
            AhP[(kpA + 1) * 136 + row] = h1; AlP[(kpA + 1) * 136 + row] = l1;
            h0 = pk_bf16x2(pb[p].x, pb[p].y);
            l0 = pk_bf16x2(pb[p].x - lo16f(h0), pb[p].y - hi16f(h0));
            h1 = pk_bf16x2(pb[p].z, pb[p].w);
            l1 = pk_bf16x2(pb[p].z - lo16f(h1), pb[p].w - hi16f(h1));
            BhP[kpA * 136 + row] = h0;       BlP[kpA * 136 + row] = l0;
            BhP[(kpA + 1) * 136 + row] = h1; BlP[(kpA + 1) * 136 + row] = l1;
        }
        __syncthreads();

        if (kt + 1 < KT) {
            int k0 = (kt + 1) * 32;
            const float* Aptr = A + (long)m0 * Dm + k0;
            const float* Bptr = A + (long)n0 * Dm + k0;
#pragma unroll
            for (int p = 0; p < 4; p++) {
                pa[p] = *(const float4*)(Aptr + (long)(arow + p * 32) * Dm + acol);
                pb[p] = *(const float4*)(Bptr + (long)(arow + p * 32) * Dm + acol);
            }
        }

#pragma unroll
        for (int ks = 0; ks < 2; ks++) {
            int k8 = ks * 8;
            unsigned ah[4][4], al[4][4];
#pragma unroll
            for (int mt = 0; mt < 4; mt++) {
                int row = wm + mt * 16 + r0;
                ah[mt][0] = AhP[(k8 + c4) * 136 + row];
                ah[mt][1] = AhP[(k8 + c4) * 136 + row + 8];
                ah[mt][2] = AhP[(k8 + 4 + c4) * 136 + row];
                ah[mt][3] = AhP[(k8 + 4 + c4) * 136 + row + 8];
                al[mt][0] = AlP[(k8 + c4) * 136 + row];
                al[mt][1] = AlP[(k8 + c4) * 136 + row + 8];
                al[mt][2] = AlP[(k8 + 4 + c4) * 136 + row];
                al[mt][3] = AlP[(k8 + 4 + c4) * 136 + row + 8];
            }
            unsigned bh[4][2], bl[4][2];
#pragma unroll
            for (int nt = 0; nt < 4; nt++) {
                int col = wn + nt * 8 + r0;
                bh[nt][0] = BhP[(k8 + c4) * 136 + col];
                bh[nt][1] = BhP[(k8 + 4 + c4) * 136 + col];
                bl[nt][0] = BlP[(k8 + c4) * 136 + col];
                bl[nt][1] = BlP[(k8 + 4 + c4) * 136 + col];
            }
#pragma unroll
            for (int mt = 0; mt < 4; mt++)
#pragma unroll
                for (int nt = 0; nt < 4; nt++) {
                    float* c = acc[mt][nt];
                    mma_bf16(c, al[mt][0], al[mt][1], al[mt][2], al[mt][3], bh[nt][0], bh[nt][1]);
                    mma_bf16(c, ah[mt][0], ah[mt][1], ah[mt][2], ah[mt][3], bl[nt][0], bl[nt][1]);
                    mma_bf16(c, ah[mt][0], ah[mt][1], ah[mt][2], ah[mt][3], bh[nt][0], bh[nt][1]);
                }
        }
    }

    bool mirror = (bx != by);
#pragma unroll
    for (int mt = 0; mt < 4; mt++) {
#pragma unroll
        for (int nt = 0; nt < 4; nt++) {
            int row = m0 + wm + mt * 16 + r0;
            int col = n0 + wn + nt * 8 + c4 * 2;
            float v0 = acc[mt][nt][0] * alpha;
            float v1 = acc[mt][nt][1] * alpha;
            float v2 = acc[mt][nt][2] * alpha;
            float v3 = acc[mt][nt][3] * alpha;
            *(float2*)(C + (long)row * Ss + col) = make_float2(v0, v1);
            *(float2*)(C + (long)(row + 8) * Ss + col) = make_float2(v2, v3);
            if (mirror) {
                C[(long)col * Ss + row]           = v0;
                C[(long)(col + 1) * Ss + row]     = v1;
                C[(long)col * Ss + row + 8]       = v2;
                C[(long)(col + 1) * Ss + row + 8] = v3;
            }
        }
    }
}

// ---------------- shuffle-based block reductions (256 threads) ----------------
__device__ __forceinline__ float warpSum(float v) {
#pragma unroll
    for (int o = 16; o > 0; o >>= 1) v += __shfl_xor_sync(0xffffffffu, v, o);
    return v;
}
__device__ __forceinline__ float warpMax(float v) {
#pragma unroll
    for (int o = 16; o > 0; o >>= 1) v = fmaxf(v, __shfl_xor_sync(0xffffffffu, v, o));
    return v;
}
__device__ __forceinline__ float blockSum256(float v, float* sm8) {
    int w = threadIdx.x >> 5, l = threadIdx.x & 31;
    v = warpSum(v);
    if (l == 0) sm8[w] = v;
    __syncthreads();
    float x = (l < 8) ? sm8[l] : 0.0f;
    x = warpSum(x);
    __syncthreads();
    if (threadIdx.x == 0) sm8[0] = x;
    __syncthreads();
    float r = sm8[0];
    __syncthreads();
    return r;
}
__device__ __forceinline__ float blockMax256(float v, float* sm8) {
    int w = threadIdx.x >> 5, l = threadIdx.x & 31;
    v = warpMax(v);
    if (l == 0) sm8[w] = v;
    __syncthreads();
    float x = (l < 8) ? sm8[l] : -FLT_MAX;
    x = warpMax(x);
    __syncthreads();
    if (threadIdx.x == 0) sm8[0] = x;
    __syncthreads();
    float r = sm8[0];
    __syncthreads();
    return r;
}

__global__ void softmax2048_kernel(float* __restrict__ S)
{
    long row = blockIdx.x;
    float* p = S + row * 2048;
    __shared__ float red[8];
    int t = threadIdx.x;
    float e[8];
    float lmax = -FLT_MAX;
#pragma unroll
    for (int q = 0; q < 8; q++) { e[q] = p[t + 256 * q]; lmax = fmaxf(lmax, e[q]); }
    float mx = blockMax256(lmax, red);
    float lsum = 0.f;
#pragma unroll
    for (int q = 0; q < 8; q++) { e[q] = expf(e[q] - mx); lsum += e[q]; }
    float sum = blockSum256(lsum, red);
    float inv = 1.0f / sum;
#pragma unroll
    for (int q = 0; q < 8; q++) p[t + 256 * q] = e[q] * inv;
}

__global__ void colmean_kernel(const float* __restrict__ S, float* __restrict__ w)
{
    int rb = blockIdx.y;
    int tcol = blockIdx.x * 256 + threadIdx.x;
    const float* base = S + (long)rb * Ss * Ss + tcol;
    float acc = 0.f;
    for (int s = 0; s < Ss; s++) acc += base[(long)s * Ss];
    w[rb * Ss + tcol] = acc * (1.0f / (float)Ss);
}

__global__ void pooled_gemv_kernel(const float* __restrict__ qf2,
                                   const float* __restrict__ w,
                                   float* __restrict__ pooled)
{
    int rb = blockIdx.y;
    int d = blockIdx.x * 128 + threadIdx.x;
    const float* Q = qf2 + (long)rb * Ss * Dm + d;
    const float* wv = w + rb * Ss;
    float acc = 0.f;
    for (int tt = 0; tt < Ss; tt++) acc += wv[tt] * Q[(long)tt * Dm];
    pooled[rb * Dm + d] = acc;
}

__global__ void ln12_kernel(const float* __restrict__ pooled,
                            const float* __restrict__ gw, const float* __restrict__ bw,
                            float* __restrict__ out)
{
    int rb = blockIdx.x;
    int r = rb >> 2;
    int t = threadIdx.x;
    __shared__ float red[8];
    const float* p = pooled + rb * Dm;
    float v0 = p[t], v1 = p[t + 256], v2 = p[t + 512], v3 = p[t + 768];
    float mean = blockSum256(v0 + v1 + v2 + v3, red) * (1.0f / (float)Dm);
    float d0 = v0 - mean, d1 = v1 - mean, d2 = v2 - mean, d3 = v3 - mean;
    float var = blockSum256(d0 * d0 + d1 * d1 + d2 * d2 + d3 * d3, red) * (1.0f / (float)Dm);
    float rs = rsqrtf(var + 1e-5f);
    out[rb * Dm + t]       = d0 * rs * gw[r * Dm + t]       + bw[r * Dm + t];
    out[rb * Dm + t + 256] = d1 * rs * gw[r * Dm + t + 256] + bw[r * Dm + t + 256];
    out[rb * Dm + t + 512] = d2 * rs * gw[r * Dm + t + 512] + bw[r * Dm + t + 512];
    out[rb * Dm + t + 768] = d3 * rs * gw[r * Dm + t + 768] + bw[r * Dm + t + 768];
}

__global__ void queries_kernel(const float* __restrict__ pooledln,
                               const float* __restrict__ pool_w,
                               const float* __restrict__ pool_b,
                               float* __restrict__ queries)
{
    int rb = blockIdx.y;
    int r = rb >> 2;
    int e = blockIdx.x * 128 + threadIdx.x;
    __shared__ float sm[Dm];
    for (int i = threadIdx.x; i < Dm; i += 128) sm[i] = pooledln[rb * Dm + i];
    __syncthreads();
    const float* W = pool_w + (long)r * Dm * Dm;
    float acc = pool_b[r * Dm + e];
    for (int d = 0; d < Dm; d++) acc += sm[d] * W[(long)d * Dm + e];
    queries[rb * Dm + e] = acc;
}

__global__ void qpart_kernel(const float* __restrict__ queries,
                             const float* __restrict__ rel_w1,
                             const float* __restrict__ rel_b1,
                             float* __restrict__ qpart)
{
    int rb = blockIdx.y;
    int j = blockIdx.x * 128 + threadIdx.x;
    __shared__ float sm[Dm];
    for (int i = threadIdx.x; i < Dm; i += 128) sm[i] = queries[rb * Dm + i];
    __syncthreads();
    float acc = rel_b1[j];
    for (int d = 0; d < Dm; d++) acc += sm[d] * rel_w1[(long)(Dm + d) * NHID + j];
    qpart[rb * NHID + j] = acc;
}

__global__ void relscore_kernel(const float* __restrict__ hidden,
                                const float* __restrict__ w2,
                                const float* __restrict__ b2,
                                float* __restrict__ rel)
{
    int row = blockIdx.x * 8 + threadIdx.y;
    const float* h = hidden + (long)row * NHID;
    float a = 0.f;
    for (int i = threadIdx.x; i < NHID; i += 32) a += h[i] * w2[i];
#pragma unroll
    for (int off = 16; off > 0; off >>= 1) a += __shfl_down_sync(0xffffffffu, a, off);
    if (threadIdx.x == 0) {
        float s = a + b2[0];
        rel[row] = 1.0f / (1.0f + expf(-s));
    }
}

__global__ void topk_kernel(const float* __restrict__ rel,
                            int* __restrict__ selidx, float* __restrict__ keyvalid,
                            int* __restrict__ anyvalid)
{
    int b = blockIdx.x;
    int t = threadIdx.x;
    __shared__ float v[1024];
    __shared__ int   id[1024];
    float val = -FLT_MAX;
    if (t < Rr * Kk) {
        int r = t >> 8, kk = t & 255;
        float rv = rel[(r * Bb + b) * Kk + kk];
        val = (rv >= 0.5f) ? rv : -FLT_MAX;
    }
    v[t] = val; id[t] = t;
    __syncthreads();
    for (int k = 2; k <= 1024; k <<= 1) {
        for (int j = k >> 1; j > 0; j >>= 1) {
            int ixj = t ^ j;
            if (ixj > t) {
                float va = v[t], vb2 = v[ixj];
                int ia = id[t], ib = id[ixj];
                bool aFirst = (va > vb2) || (va == vb2 && ia < ib);
                bool dirDesc = ((t & k) == 0);
                if (dirDesc ? !aFirst : aFirst) {
                    v[t] = vb2; v[ixj] = va; id[t] = ib; id[ixj] = ia;
                }
            }
            __syncthreads();
        }
    }
    if (t < MAXR) {
        bool valid = (v[t] > -FLT_MAX);
        selidx[b * MAXR + t] = id[t];
        keyvalid[b * MAXR + t] = valid ? 1.0f : 0.0f;
        if (t == 0) anyvalid[b] = valid ? 1 : 0;
    }
}

__global__ void gather_kernel(const float* __restrict__ retrieved,
                              const int* __restrict__ selidx,
                              float* __restrict__ seltok)
{
    int b = blockIdx.y;
    int j = blockIdx.x;
    int t = threadIdx.x;
    int c = selidx[b * MAXR + j];
    int r = c >> 8, kk = c & 255;
    const float4* src = (const float4*)(retrieved + (((long)r * Bb + b) * Kk + kk) * Dm);
    float4* dst = (float4*)(seltok + ((long)b * MAXR + j) * Dm);
    dst[t] = src[t];
}

__global__ void finalize_kernel(const float* __restrict__ x, const float* __restrict__ fused,
                                const float* __restrict__ gw, const float* __restrict__ bw,
                                const int* __restrict__ anyvalid, float* __restrict__ out)
{
    long row = blockIdx.x;
    int b = (int)(row >> 11);
    int t = threadIdx.x;
    __shared__ float red[8];
    const float* xr = x + row * Dm;
    const float* fr = fused + row * Dm;
    float v0 = xr[t] + fr[t];
    float v1 = xr[t + 256] + fr[t + 256];
    float v2 = xr[t + 512] + fr[t + 512];
    float v3 = xr[t + 768] + fr[t + 768];
    float mean = blockSum256(v0 + v1 + v2 + v3, red) * (1.0f / (float)Dm);
    float d0 = v0 - mean, d1 = v1 - mean, d2 = v2 - mean, d3 = v3 - mean;
    float var = blockSum256(d0 * d0 + d1 * d1 + d2 * d2 + d3 * d3, red) * (1.0f / (float)Dm);
    float rs = rsqrtf(var + 1e-5f);
    int av = anyvalid[b];
    float* o = out + row * Dm;
    o[t]       = av ? (d0 * rs * gw[t]       + bw[t])       : xr[t];
    o[t + 256] = av ? (d1 * rs * gw[t + 256] + bw[t + 256]) : xr[t + 256];
    o[t + 512] = av ? (d2 * rs * gw[t + 512] + bw[t + 512]) : xr[t + 512];
    o[t + 768] = av ? (d3 * rs * gw[t + 768] + bw[t + 768]) : xr[t + 768];
}

// ---------------- host orchestration ----------------
template <typename T>
static float* sym(T& s) { void* p = 0; cudaGetSymbolAddress(&p, s); return (float*)p; }
template <typename T>
static int* symi(T& s) { void* p = 0; cudaGetSymbolAddress(&p, s); return (int*)p; }

extern "C" void kernel_launch(void* const* d_in, const int* in_sizes, int n_in,
                              void* d_out, int out_size)
{
    const float* x       = (const float*)d_in[0];
    const float* retr    = (const float*)d_in[1];
    const float* qg_w1   = (const float*)d_in[2];
    const float* qg_b1   = (const float*)d_in[3];
    const float* qg_w2   = (const float*)d_in[4];
    const float* qg_b2   = (const float*)d_in[5];
    const float* pln_g   = (const float*)d_in[6];
    const float* pln_b   = (const float*)d_in[7];
    const float* pool_w  = (const float*)d_in[8];
    const float* pool_b  = (const float*)d_in[9];
    const float* rel_w1  = (const float*)d_in[10];
    const float* rel_b1  = (const float*)d_in[11];
    const float* rel_w2  = (const float*)d_in[12];
    const float* rel_b2  = (const float*)d_in[13];
    const float* in_w    = (const float*)d_in[14];
    const float* in_b    = (const float*)d_in[15];
    const float* out_w   = (const float*)d_in[16];
    const float* out_b   = (const float*)d_in[17];
    const float* fln_g   = (const float*)d_in[18];
    const float* fln_b   = (const float*)d_in[19];
    float* out = (float*)d_out;

    float* qf1    = sym(g_qf1);
    float* qf2    = sym(g_qf2);
    float* scores = sym(g_scores);
    float* wmean  = sym(g_w);
    float* pooled = sym(g_pooled);
    float* pooledln = sym(g_pooledln);
    float* queries = sym(g_queries);
    float* qpart  = sym(g_qpart);
    float* hidden = sym(g_hidden);
    float* rel    = sym(g_rel);
    int*   selidx = symi(g_selidx);
    float* keyvalid = sym(g_keyvalid);
    int*   anyvalid = symi(g_anyvalid);
    float* seltok = sym(g_seltok);
    float* qb     = sym(g_q);
    float* kb     = sym(g_k);
    float* vb     = sym(g_v);
    float* fsc    = sym(g_fsc);
    float* attnout = sym(g_attnout);
    float* fused  = sym(g_fused);

    const long DD = (long)Dm * Dm;

    // ---- query-gen / relevance path: bf16x3 (threshold-sensitive) ----
    launch_tgemm(x, qg_w1, qf1, BS, Dm, Dm, Dm, Dm, Dm,
                 0, DD, (long)BS * Dm, Rr, 1, 0, 0, 0,
                 1.0f, qg_b1, Dm, 0, 1, 0, 0);
    launch_tgemm(qf1, qg_w2, qf2, BS, Dm, Dm, Dm, Dm, Dm,
                 (long)BS * Dm, DD, (long)BS * Dm, Rr, 1, 0, 0, 0,
                 1.0f, qg_b2, Dm, 0, 0, 0, 0);
    {
        dim3 g(136, 1, RBn);
        size_t shm0 = 2 * 4 * PLW * 4;
        cudaFuncSetAttribute(sym_gemm_kernel, cudaFuncAttributeMaxDynamicSharedMemorySize, (int)shm0);
        sym_gemm_kernel<<<g, 256, shm0>>>(qf2, scores, 0.03125f);
    }
    softmax2048_kernel<<<RBn * Ss, 256>>>(scores);
    { dim3 g(Ss / 256, RBn); colmean_kernel<<<g, 256>>>(scores, wmean); }
    { dim3 g(Dm / 128, RBn); pooled_gemv_kernel<<<g, 128>>>(qf2, wmean, pooled); }
    ln12_kernel<<<RBn, 256>>>(pooled, pln_g, pln_b, pooledln);
    { dim3 g(Dm / 128, RBn); queries_kernel<<<g, 128>>>(pooledln, pool_w, pool_b, queries); }
    { dim3 g(NHID / 128, RBn); qpart_kernel<<<g, 128>>>(queries, rel_w1, rel_b1, qpart); }
    launch_tgemm(retr, rel_w1, hidden, RBn * Kk, NHID, Dm, Dm, NHID, NHID,
                 0, 0, 0, 1, 1, 0, 0, 0,
                 1.0f, qpart, 0, Kk, 1, 0, 0);
    { dim3 blk(32, 8); relscore_kernel<<<RBn * Kk / 8, blk>>>(hidden, rel_w2, rel_b2, rel); }
    topk_kernel<<<Bb, 1024>>>(rel, selidx, keyvalid, anyvalid);
    { dim3 g(MAXR, Bb); gather_kernel<<<g, 256>>>(retr, selidx, seltok); }

    // ---- fusion path: single-pass fp16 ----
    launch_tgemm(x, in_w, qb, BS, Dm, Dm, Dm, Dm, Dm,
                 0, 0, 0, 1, 1, 0, 0, 0, 1.0f, in_b, 0, 0, 0, 0, 1);
    launch_tgemm(seltok, in_w + DD, kb, Bb * MAXR, Dm, Dm, Dm, Dm, Dm,
                 0, 0, 0, 1, 1, 0, 0, 0, 1.0f, in_b + Dm, 0, 0, 0, 0, 1);
    launch_tgemm(seltok, in_w + 2 * DD, vb, Bb * MAXR, Dm, Dm, Dm, Dm, Dm,
                 0, 0, 0, 1, 1, 0, 0, 0, 1.0f, in_b + 2 * Dm, 0, 0, 0, 0, 1);
    launch_tgemm(qb, kb, fsc, Ss, MAXR, HDm, Dm, Dm, MAXR,
                 (long)Ss * Dm, (long)MAXR * Dm, (long)Hh * Ss * MAXR,
                 Bb * Hh, Hh, HDm, HDm, (long)Ss * MAXR,
                 0.08838834764831845f, 0, 0, 0, 0, 1, 1);
    // attnout = softmax(fsc, masked) @ V   (softmax fused into A-staging)
    launch_tgemm(fsc, vb, attnout, Ss, HDm, MAXR, MAXR, Dm, Dm,
                 (long)Hh * Ss * MAXR, (long)MAXR * Dm, (long)Ss * Dm,
                 Bb * Hh, Hh, (long)Ss * MAXR, HDm, HDm,
                 1.0f, 0, 0, 0, 0, 0, 1, keyvalid, 1);
    launch_tgemm(attnout, out_w, fused, BS, Dm, Dm, Dm, Dm, Dm,
                 0, 0, 0, 1, 1, 0, 0, 0, 1.0f, out_b, 0, 0, 0, 0, 1);
    finalize_kernel<<<BS, 256>>>(x, fused, fln_g, fln_b, anyvalid, out);
}